// round 1
// baseline (speedup 1.0000x reference)
#include <cuda_runtime.h>
#include <cuda_bf16.h>
#include <math.h>

// ---------------------------------------------------------------------------
// SpatialTransformer block, fp32 CUDA-core implementation (round 0)
// x: (1, 320, 64, 64)  context: (1, 77, 768)
// L = 4096 tokens, C = 320, HEADS = 8, DH = 40, FF_INNER = 1280, G = 32
// ---------------------------------------------------------------------------

#define L_TOK   4096
#define C_DIM   320
#define HEADS   8
#define DH      40
#define CTX_DIM 768
#define LCTX    77
#define FFI     1280
#define NGROUPS 32
#define CH_PER_G 10

// scratch (static device allocations are allowed; cudaMalloc is not)
__device__ float g_xn[L_TOK * C_DIM];
__device__ float g_t [L_TOK * C_DIM];
__device__ float g_hn[L_TOK * C_DIM];
__device__ float g_q [L_TOK * C_DIM];
__device__ float g_k [L_TOK * C_DIM];
__device__ float g_v [L_TOK * C_DIM];
__device__ float g_a [L_TOK * C_DIM];
__device__ float g_p [L_TOK * 2 * FFI];
__device__ float g_gg[L_TOK * FFI];
__device__ float g_mean[NGROUPS];
__device__ float g_rstd[NGROUPS];

// ---------------- GroupNorm ----------------
__global__ void gn_stats_kernel(const float* __restrict__ x)
{
    int g = blockIdx.x;
    int tid = threadIdx.x;
    const int NEL = CH_PER_G * L_TOK;  // 40960
    float s = 0.f, ss = 0.f;
    const float* base = x + g * CH_PER_G * L_TOK;
    for (int i = tid; i < NEL; i += blockDim.x) {
        float v = base[i];
        s += v; ss += v * v;
    }
    __shared__ float rs[256], rss[256];
    rs[tid] = s; rss[tid] = ss;
    __syncthreads();
    for (int o = 128; o > 0; o >>= 1) {
        if (tid < o) { rs[tid] += rs[tid + o]; rss[tid] += rss[tid + o]; }
        __syncthreads();
    }
    if (tid == 0) {
        float m = rs[0] / (float)NEL;
        float var = rss[0] / (float)NEL - m * m;
        g_mean[g] = m;
        g_rstd[g] = rsqrtf(var + 1e-6f);
    }
}

// normalize + scale/shift + transpose (C,HW) -> (HW,C)
__global__ void gn_apply_kernel(const float* __restrict__ x,
                                const float* __restrict__ gw,
                                const float* __restrict__ gb)
{
    int idx = blockIdx.x * blockDim.x + threadIdx.x;  // over C*HW, c-major
    if (idx >= C_DIM * L_TOK) return;
    int c = idx / L_TOK;
    int hw = idx % L_TOK;
    int g = c / CH_PER_G;
    float v = (x[idx] - g_mean[g]) * g_rstd[g] * gw[c] + gb[c];
    g_xn[hw * C_DIM + c] = v;
}

// ---------------- LayerNorm (warp per token) ----------------
__global__ void ln_kernel(const float* __restrict__ in,
                          const float* __restrict__ w,
                          const float* __restrict__ b,
                          float* __restrict__ out)
{
    int token = blockIdx.x * (blockDim.x / 32) + (threadIdx.x >> 5);
    int lane = threadIdx.x & 31;
    if (token >= L_TOK) return;
    const float* row = in + token * C_DIM;
    float s = 0.f, ss = 0.f;
    for (int j = lane; j < C_DIM; j += 32) {
        float v = row[j];
        s += v; ss += v * v;
    }
    #pragma unroll
    for (int o = 16; o > 0; o >>= 1) {
        s  += __shfl_xor_sync(0xffffffffu, s, o);
        ss += __shfl_xor_sync(0xffffffffu, ss, o);
    }
    float m = s / (float)C_DIM;
    float var = ss / (float)C_DIM - m * m;
    float r = rsqrtf(var + 1e-5f);
    float* orow = out + token * C_DIM;
    for (int j = lane; j < C_DIM; j += 32)
        orow[j] = (row[j] - m) * r * w[j] + b[j];
}

// ---------------- generic tiled SGEMM ----------------
// C[m,n] = sum_k A[m,k]*B[k,n] (+bias[n]) (+res)   B row-major (K,N)
// transOut: store/res index = n*M + m  (for channel-major output)
__global__ void gemm64_kernel(const float* __restrict__ A,
                              const float* __restrict__ B,
                              const float* __restrict__ bias,
                              const float* __restrict__ res,
                              float* __restrict__ C,
                              int M, int N, int K, int transOut)
{
    __shared__ float As[16][68];
    __shared__ float Bs[16][64];
    int bm = blockIdx.y * 64;
    int bn = blockIdx.x * 64;
    int tid = threadIdx.x;
    int tx = tid & 15;          // col group
    int ty = tid >> 4;          // row group
    float acc[4][4] = {};
    for (int k0 = 0; k0 < K; k0 += 16) {
        #pragma unroll
        for (int i = 0; i < 4; i++) {
            int t = tid + i * 256;
            int m = t >> 4, kk = t & 15;
            int gm = bm + m;
            float v = (gm < M) ? A[gm * K + k0 + kk] : 0.f;
            As[kk][m] = v;
        }
        #pragma unroll
        for (int i = 0; i < 4; i++) {
            int t = tid + i * 256;
            int kk = t >> 6, n = t & 63;
            Bs[kk][n] = B[(k0 + kk) * N + bn + n];
        }
        __syncthreads();
        #pragma unroll
        for (int kk = 0; kk < 16; kk++) {
            float4 a4 = *(const float4*)&As[kk][ty * 4];
            float4 b4 = *(const float4*)&Bs[kk][tx * 4];
            float av[4] = {a4.x, a4.y, a4.z, a4.w};
            float bv[4] = {b4.x, b4.y, b4.z, b4.w};
            #pragma unroll
            for (int i = 0; i < 4; i++)
                #pragma unroll
                for (int j = 0; j < 4; j++)
                    acc[i][j] += av[i] * bv[j];
        }
        __syncthreads();
    }
    #pragma unroll
    for (int i = 0; i < 4; i++) {
        int m = bm + ty * 4 + i;
        if (m >= M) continue;
        #pragma unroll
        for (int j = 0; j < 4; j++) {
            int n = bn + tx * 4 + j;
            float v = acc[i][j];
            if (bias) v += bias[n];
            int idx = transOut ? (n * M + m) : (m * N + n);
            if (res) v += res[idx];
            C[idx] = v;
        }
    }
}

// ---------------- flash attention (one query per thread) ----------------
// Q/K/V layout: channel c = j*HEADS + h  (reference's reshape(L, dh, heads))
// O layout:     channel c = h*DH + j
__global__ void flash_attn_kernel(const float* __restrict__ Q,
                                  const float* __restrict__ Kt,
                                  const float* __restrict__ V,
                                  float* __restrict__ O,
                                  int Lk)
{
    const float scale = 0.15811388300841898f;  // 1/sqrt(40)
    int h = blockIdx.y;
    int l = blockIdx.x * 128 + threadIdx.x;

    float qreg[DH];
    #pragma unroll
    for (int j = 0; j < DH; j++)
        qreg[j] = Q[l * C_DIM + j * HEADS + h] * scale;

    float o[DH];
    #pragma unroll
    for (int j = 0; j < DH; j++) o[j] = 0.f;
    float mprev = -1e30f, lsum = 0.f;

    __shared__ float sK[32][DH];
    __shared__ float sV[32][DH];

    for (int k0 = 0; k0 < Lk; k0 += 32) {
        __syncthreads();
        for (int i = threadIdx.x; i < 32 * DH; i += 128) {
            int kk = i / DH, j = i % DH;
            int key = k0 + kk;
            float kv = 0.f, vv = 0.f;
            if (key < Lk) {
                kv = Kt[key * C_DIM + j * HEADS + h];
                vv = V [key * C_DIM + j * HEADS + h];
            }
            sK[kk][j] = kv;
            sV[kk][j] = vv;
        }
        __syncthreads();

        float sc[32];
        #pragma unroll
        for (int kk = 0; kk < 32; kk++) {
            float s = 0.f;
            #pragma unroll
            for (int j4 = 0; j4 < DH; j4 += 4) {
                float4 k4 = *(const float4*)&sK[kk][j4];
                s += qreg[j4 + 0] * k4.x;
                s += qreg[j4 + 1] * k4.y;
                s += qreg[j4 + 2] * k4.z;
                s += qreg[j4 + 3] * k4.w;
            }
            sc[kk] = (k0 + kk < Lk) ? s : -1e30f;
        }
        float tmax = mprev;
        #pragma unroll
        for (int kk = 0; kk < 32; kk++) tmax = fmaxf(tmax, sc[kk]);
        float corr = __expf(mprev - tmax);
        lsum *= corr;
        #pragma unroll
        for (int j = 0; j < DH; j++) o[j] *= corr;

        #pragma unroll
        for (int kk = 0; kk < 32; kk++) {
            float p = __expf(sc[kk] - tmax);
            lsum += p;
            #pragma unroll
            for (int j4 = 0; j4 < DH; j4 += 4) {
                float4 v4 = *(const float4*)&sV[kk][j4];
                o[j4 + 0] += p * v4.x;
                o[j4 + 1] += p * v4.y;
                o[j4 + 2] += p * v4.z;
                o[j4 + 3] += p * v4.w;
            }
        }
        mprev = tmax;
    }
    float inv = 1.f / lsum;
    #pragma unroll
    for (int j = 0; j < DH; j++)
        O[l * C_DIM + h * DH + j] = o[j] * inv;
}

// ---------------- GEGLU (exact gelu on gate) ----------------
__global__ void geglu_kernel(const float* __restrict__ p, float* __restrict__ g)
{
    int idx = blockIdx.x * blockDim.x + threadIdx.x;
    if (idx >= L_TOK * FFI) return;
    int l = idx / FFI, i = idx - l * FFI;
    float a = p[l * 2 * FFI + i];
    float x = p[l * 2 * FFI + FFI + i];
    float ge = 0.5f * x * (1.f + erff(x * 0.70710678118654752f));
    g[idx] = a * ge;
}

// ---------------------------------------------------------------------------
extern "C" void kernel_launch(void* const* d_in, const int* in_sizes, int n_in,
                              void* d_out, int out_size)
{
    const float* x       = (const float*)d_in[0];
    const float* context = (const float*)d_in[1];
    const float* gn_w    = (const float*)d_in[2];
    const float* gn_b    = (const float*)d_in[3];
    const float* w_in    = (const float*)d_in[4];
    const float* b_in    = (const float*)d_in[5];
    const float* ln1_w   = (const float*)d_in[6];
    const float* ln1_b   = (const float*)d_in[7];
    const float* wq1     = (const float*)d_in[8];
    const float* wk1     = (const float*)d_in[9];
    const float* wv1     = (const float*)d_in[10];
    const float* wo1     = (const float*)d_in[11];
    const float* bo1     = (const float*)d_in[12];
    const float* ln2_w   = (const float*)d_in[13];
    const float* ln2_b   = (const float*)d_in[14];
    const float* wq2     = (const float*)d_in[15];
    const float* wk2     = (const float*)d_in[16];
    const float* wv2     = (const float*)d_in[17];
    const float* wo2     = (const float*)d_in[18];
    const float* bo2     = (const float*)d_in[19];
    const float* ln3_w   = (const float*)d_in[20];
    const float* ln3_b   = (const float*)d_in[21];
    const float* wff1    = (const float*)d_in[22];
    const float* bff1    = (const float*)d_in[23];
    const float* wff2    = (const float*)d_in[24];
    const float* bff2    = (const float*)d_in[25];
    const float* w_out   = (const float*)d_in[26];
    const float* b_out   = (const float*)d_in[27];
    float* out = (float*)d_out;

    static float *xn = nullptr, *t, *hn, *q, *k, *v, *a, *p, *gg;
    if (!xn) {
        cudaGetSymbolAddress((void**)&xn, g_xn);
        cudaGetSymbolAddress((void**)&t,  g_t);
        cudaGetSymbolAddress((void**)&hn, g_hn);
        cudaGetSymbolAddress((void**)&q,  g_q);
        cudaGetSymbolAddress((void**)&k,  g_k);
        cudaGetSymbolAddress((void**)&v,  g_v);
        cudaGetSymbolAddress((void**)&a,  g_a);
        cudaGetSymbolAddress((void**)&p,  g_p);
        cudaGetSymbolAddress((void**)&gg, g_gg);
    }

    dim3 gemmGrid320(C_DIM / 64, L_TOK / 64);          // (5, 64)
    dim3 gemmGridFF1(2 * FFI / 64, L_TOK / 64);        // (40, 64)
    dim3 gemmGridCtx(C_DIM / 64, (LCTX + 63) / 64);    // (5, 2)
    dim3 attnGrid(L_TOK / 128, HEADS);                 // (32, 8)

    // GroupNorm + proj_in
    gn_stats_kernel<<<NGROUPS, 256>>>(x);
    gn_apply_kernel<<<(C_DIM * L_TOK + 255) / 256, 256>>>(x, gn_w, gn_b);
    gemm64_kernel<<<gemmGrid320, 256>>>(xn, w_in, b_in, nullptr, t,
                                        L_TOK, C_DIM, C_DIM, 0);

    // ---- self-attention ----
    ln_kernel<<<L_TOK / 4, 128>>>(t, ln1_w, ln1_b, hn);
    gemm64_kernel<<<gemmGrid320, 256>>>(hn, wq1, nullptr, nullptr, q,
                                        L_TOK, C_DIM, C_DIM, 0);
    gemm64_kernel<<<gemmGrid320, 256>>>(q, wk1, nullptr, nullptr, k,
                                        L_TOK, C_DIM, C_DIM, 0);
    gemm64_kernel<<<gemmGrid320, 256>>>(q, wv1, nullptr, nullptr, v,
                                        L_TOK, C_DIM, C_DIM, 0);
    flash_attn_kernel<<<attnGrid, 128>>>(q, k, v, a, L_TOK);
    gemm64_kernel<<<gemmGrid320, 256>>>(a, wo1, bo1, t, t,
                                        L_TOK, C_DIM, C_DIM, 0);

    // ---- cross-attention ----
    ln_kernel<<<L_TOK / 4, 128>>>(t, ln2_w, ln2_b, hn);
    gemm64_kernel<<<gemmGrid320, 256>>>(hn, wq2, nullptr, nullptr, q,
                                        L_TOK, C_DIM, C_DIM, 0);
    gemm64_kernel<<<gemmGridCtx, 256>>>(context, wk2, nullptr, nullptr, k,
                                        LCTX, C_DIM, CTX_DIM, 0);
    gemm64_kernel<<<gemmGridCtx, 256>>>(context, wv2, nullptr, nullptr, v,
                                        LCTX, C_DIM, CTX_DIM, 0);
    flash_attn_kernel<<<attnGrid, 128>>>(q, k, v, a, LCTX);
    gemm64_kernel<<<gemmGrid320, 256>>>(a, wo2, bo2, t, t,
                                        L_TOK, C_DIM, C_DIM, 0);

    // ---- feed-forward (GEGLU) ----
    ln_kernel<<<L_TOK / 4, 128>>>(t, ln3_w, ln3_b, hn);
    gemm64_kernel<<<gemmGridFF1, 256>>>(hn, wff1, bff1, nullptr, p,
                                        L_TOK, 2 * FFI, C_DIM, 0);
    geglu_kernel<<<(L_TOK * FFI + 255) / 256, 256>>>(p, gg);
    gemm64_kernel<<<gemmGrid320, 256>>>(gg, wff2, bff2, t, t,
                                        L_TOK, C_DIM, FFI, 0);

    // ---- proj_out (+ x residual), channel-major store ----
    gemm64_kernel<<<gemmGrid320, 256>>>(t, w_out, b_out, x, out,
                                        L_TOK, C_DIM, C_DIM, 1);
}

// round 2
// speedup vs baseline: 1.0558x; 1.0558x over previous
#include <cuda_runtime.h>
#include <cuda_bf16.h>
#include <mma.h>
#include <math.h>

using namespace nvcuda;

// ---------------------------------------------------------------------------
// SpatialTransformer block — round 1: tf32 tensor cores (wmma) for all GEMMs
// and both attentions. fp32 elsewhere.
// x: (1, 320, 64, 64)  context: (1, 77, 768)
// L = 4096 tokens, C = 320, HEADS = 8, DH = 40, FF_INNER = 1280, G = 32
// ---------------------------------------------------------------------------

#define L_TOK   4096
#define C_DIM   320
#define HEADS   8
#define DH      40
#define CTX_DIM 768
#define LCTX    77
#define FFI     1280
#define NGROUPS 32
#define CH_PER_G 10

// scratch
__device__ float g_xn[L_TOK * C_DIM];
__device__ float g_t [L_TOK * C_DIM];
__device__ float g_hn[L_TOK * C_DIM];
__device__ float g_q [L_TOK * C_DIM];
__device__ float g_k [L_TOK * C_DIM];
__device__ float g_v [L_TOK * C_DIM];
__device__ float g_a [L_TOK * C_DIM];
__device__ float g_p [L_TOK * 2 * FFI];
__device__ float g_gg[L_TOK * FFI];
__device__ float g_mean[NGROUPS];
__device__ float g_rstd[NGROUPS];

// ---------------- GroupNorm ----------------
__global__ void gn_stats_kernel(const float* __restrict__ x)
{
    int g = blockIdx.x;
    int tid = threadIdx.x;
    const int NEL = CH_PER_G * L_TOK;
    float s = 0.f, ss = 0.f;
    const float* base = x + g * CH_PER_G * L_TOK;
    for (int i = tid; i < NEL; i += blockDim.x) {
        float v = base[i];
        s += v; ss += v * v;
    }
    __shared__ float rs[256], rss[256];
    rs[tid] = s; rss[tid] = ss;
    __syncthreads();
    for (int o = 128; o > 0; o >>= 1) {
        if (tid < o) { rs[tid] += rs[tid + o]; rss[tid] += rss[tid + o]; }
        __syncthreads();
    }
    if (tid == 0) {
        float m = rs[0] / (float)NEL;
        float var = rss[0] / (float)NEL - m * m;
        g_mean[g] = m;
        g_rstd[g] = rsqrtf(var + 1e-6f);
    }
}

__global__ void gn_apply_kernel(const float* __restrict__ x,
                                const float* __restrict__ gw,
                                const float* __restrict__ gb)
{
    int idx = blockIdx.x * blockDim.x + threadIdx.x;
    if (idx >= C_DIM * L_TOK) return;
    int c = idx / L_TOK;
    int hw = idx % L_TOK;
    int g = c / CH_PER_G;
    float v = (x[idx] - g_mean[g]) * g_rstd[g] * gw[c] + gb[c];
    g_xn[hw * C_DIM + c] = v;
}

// ---------------- LayerNorm ----------------
__global__ void ln_kernel(const float* __restrict__ in,
                          const float* __restrict__ w,
                          const float* __restrict__ b,
                          float* __restrict__ out)
{
    int token = blockIdx.x * (blockDim.x / 32) + (threadIdx.x >> 5);
    int lane = threadIdx.x & 31;
    if (token >= L_TOK) return;
    const float* row = in + token * C_DIM;
    float s = 0.f, ss = 0.f;
    for (int j = lane; j < C_DIM; j += 32) {
        float v = row[j];
        s += v; ss += v * v;
    }
    #pragma unroll
    for (int o = 16; o > 0; o >>= 1) {
        s  += __shfl_xor_sync(0xffffffffu, s, o);
        ss += __shfl_xor_sync(0xffffffffu, ss, o);
    }
    float m = s / (float)C_DIM;
    float var = ss / (float)C_DIM - m * m;
    float r = rsqrtf(var + 1e-5f);
    float* orow = out + token * C_DIM;
    for (int j = lane; j < C_DIM; j += 32)
        orow[j] = (row[j] - m) * r * w[j] + b[j];
}

// ---------------- tf32 tensor-core GEMM ----------------
// C[m,n] = sum_k A[m,k]*B[k,n] (+bias[n]) (+res)   A row-major (M,K), B row-major (K,N)
// tile 128x64x32, 8 warps (4x2), 2x2 wmma fragments per warp.
// N must be a multiple of 64, K a multiple of 32. M arbitrary (guarded).
__global__ __launch_bounds__(256) void gemm_tc_kernel(
    const float* __restrict__ A, const float* __restrict__ B,
    const float* __restrict__ bias, const float* __restrict__ res,
    float* __restrict__ C, int M, int N, int K, int transOut)
{
    struct InBuf { float As[128][36]; float Bs[32][68]; };
    __shared__ union SU { InBuf in; float Cs[128][68]; } sm;

    int bm = blockIdx.y * 128;
    int bn = blockIdx.x * 64;
    int tid = threadIdx.x;
    int w = tid >> 5;
    int wm = w >> 1;          // 0..3 -> 32-row band
    int wn = w & 1;           // 0..1 -> 32-col band

    wmma::fragment<wmma::accumulator, 16, 16, 8, float> acc[2][2];
    #pragma unroll
    for (int i = 0; i < 2; i++)
        #pragma unroll
        for (int j = 0; j < 2; j++) wmma::fill_fragment(acc[i][j], 0.f);

    for (int k0 = 0; k0 < K; k0 += 32) {
        // A tile: 128x32 = 1024 float4
        #pragma unroll
        for (int p = 0; p < 4; p++) {
            int i = tid + p * 256;
            int m = i >> 3, c4 = i & 7;
            float4 v = make_float4(0.f, 0.f, 0.f, 0.f);
            int gm = bm + m;
            if (gm < M) v = *(const float4*)&A[(size_t)gm * K + k0 + c4 * 4];
            sm.in.As[m][c4*4+0] = wmma::__float_to_tf32(v.x);
            sm.in.As[m][c4*4+1] = wmma::__float_to_tf32(v.y);
            sm.in.As[m][c4*4+2] = wmma::__float_to_tf32(v.z);
            sm.in.As[m][c4*4+3] = wmma::__float_to_tf32(v.w);
        }
        // B tile: 32x64 = 512 float4
        #pragma unroll
        for (int p = 0; p < 2; p++) {
            int i = tid + p * 256;
            int kk = i >> 4, c4 = i & 15;
            float4 v = *(const float4*)&B[(size_t)(k0 + kk) * N + bn + c4 * 4];
            sm.in.Bs[kk][c4*4+0] = wmma::__float_to_tf32(v.x);
            sm.in.Bs[kk][c4*4+1] = wmma::__float_to_tf32(v.y);
            sm.in.Bs[kk][c4*4+2] = wmma::__float_to_tf32(v.z);
            sm.in.Bs[kk][c4*4+3] = wmma::__float_to_tf32(v.w);
        }
        __syncthreads();
        #pragma unroll
        for (int ks = 0; ks < 4; ks++) {
            wmma::fragment<wmma::matrix_a, 16, 16, 8, wmma::precision::tf32, wmma::row_major> af[2];
            wmma::fragment<wmma::matrix_b, 16, 16, 8, wmma::precision::tf32, wmma::row_major> bf[2];
            wmma::load_matrix_sync(af[0], &sm.in.As[wm*32     ][ks*8], 36);
            wmma::load_matrix_sync(af[1], &sm.in.As[wm*32 + 16][ks*8], 36);
            wmma::load_matrix_sync(bf[0], &sm.in.Bs[ks*8][wn*32     ], 68);
            wmma::load_matrix_sync(bf[1], &sm.in.Bs[ks*8][wn*32 + 16], 68);
            #pragma unroll
            for (int i = 0; i < 2; i++)
                #pragma unroll
                for (int j = 0; j < 2; j++)
                    wmma::mma_sync(acc[i][j], af[i], bf[j], acc[i][j]);
        }
        __syncthreads();
    }

    // epilogue via smem staging
    #pragma unroll
    for (int i = 0; i < 2; i++)
        #pragma unroll
        for (int j = 0; j < 2; j++)
            wmma::store_matrix_sync(&sm.Cs[wm*32 + i*16][wn*32 + j*16],
                                    acc[i][j], 68, wmma::mem_row_major);
    __syncthreads();
    #pragma unroll
    for (int p = 0; p < 32; p++) {
        int i = tid + p * 256;            // 0..8191
        int m = i >> 6, n = i & 63;
        int gm = bm + m, gn = bn + n;
        if (gm >= M) continue;
        float v = sm.Cs[m][n];
        if (bias) v += bias[gn];
        size_t idx = transOut ? ((size_t)gn * M + gm) : ((size_t)gm * N + gn);
        if (res) v += res[idx];
        C[idx] = v;
    }
}

// ---------------- tf32 tensor-core flash attention ----------------
// One head, 64 queries per block, 64-key tiles. 4 warps, each owns a 16-row
// query band. Q/K/V layout: channel c = j*HEADS + h ; O layout: c = h*DH + j.
#define ATTN_SMEM_BYTES ((3072 + 3072 + 4352 + 3072 + 64 + 64) * 4)

__global__ __launch_bounds__(128) void attn_tc_kernel(
    const float* __restrict__ Q, const float* __restrict__ Kt,
    const float* __restrict__ V, float* __restrict__ O, int Lk)
{
    extern __shared__ float smf[];
    float* sK = smf;            // [64][48]
    float* sV = sK + 3072;      // [64][48]
    float* sS = sV + 3072;      // [64][68]  (also Q staging / PV staging)
    float* sO = sS + 4352;      // [64][48]
    float* sM = sO + 3072;      // [64]
    float* sL = sM + 64;        // [64]

    const float scale = 0.15811388300841898f; // 1/sqrt(40)
    int h = blockIdx.y;
    int qbase = blockIdx.x * 64;
    int tid = threadIdx.x;
    int w = tid >> 5;
    int lane = tid & 31;

    // stage scaled Q into sS as [64][48] (pad dh 40->48)
    for (int i = tid; i < 64 * 48; i += 128) {
        int r = i / 48, j = i - r * 48;
        float v = 0.f;
        if (j < DH) v = Q[(size_t)(qbase + r) * C_DIM + j * HEADS + h] * scale;
        sS[i] = wmma::__float_to_tf32(v);
    }
    for (int i = tid; i < 64 * 48; i += 128) sO[i] = 0.f;
    if (tid < 64) { sM[tid] = -1e30f; sL[tid] = 0.f; }
    __syncthreads();

    wmma::fragment<wmma::matrix_a, 16, 16, 8, wmma::precision::tf32, wmma::row_major> qa[6];
    #pragma unroll
    for (int kd = 0; kd < 6; kd++)
        wmma::load_matrix_sync(qa[kd], &sS[(w*16)*48 + kd*8], 48);
    __syncthreads();   // everyone done reading Q staging before sS is reused

    for (int k0 = 0; k0 < Lk; k0 += 64) {
        // load K/V tile (zero-pad invalid keys / dh)
        for (int i = tid; i < 64 * 48; i += 128) {
            int r = i / 48, j = i - r * 48;
            int key = k0 + r;
            float kv = 0.f, vv = 0.f;
            if (j < DH && key < Lk) {
                size_t off = (size_t)key * C_DIM + j * HEADS + h;
                kv = Kt[off];
                vv = V[off];
            }
            sK[r*48 + j] = wmma::__float_to_tf32(kv);
            sV[r*48 + j] = wmma::__float_to_tf32(vv);
        }
        __syncthreads();

        // S = Q K^T : warp band 16 rows x 64 keys
        wmma::fragment<wmma::accumulator, 16, 16, 8, float> sacc[4];
        #pragma unroll
        for (int j = 0; j < 4; j++) wmma::fill_fragment(sacc[j], 0.f);
        #pragma unroll
        for (int kd = 0; kd < 6; kd++) {
            #pragma unroll
            for (int j = 0; j < 4; j++) {
                wmma::fragment<wmma::matrix_b, 16, 16, 8, wmma::precision::tf32, wmma::col_major> kb;
                wmma::load_matrix_sync(kb, &sK[(j*16)*48 + kd*8], 48);
                wmma::mma_sync(sacc[j], qa[kd], kb, sacc[j]);
            }
        }
        #pragma unroll
        for (int j = 0; j < 4; j++)
            wmma::store_matrix_sync(&sS[(w*16)*68 + j*16], sacc[j], 68, wmma::mem_row_major);
        __syncwarp();

        // online softmax on this warp's 16 rows (2 lanes per row)
        {
            int r = w * 16 + (lane >> 1);
            int half = lane & 1;
            float* row = &sS[r * 68];
            float mx = -1e30f;
            #pragma unroll
            for (int c = 0; c < 32; c++) {
                int col = half * 32 + c;
                float s = (k0 + col < Lk) ? row[col] : -1e30f;
                mx = fmaxf(mx, s);
            }
            mx = fmaxf(mx, __shfl_xor_sync(0xffffffffu, mx, 1));
            float mold = sM[r];
            float mnew = fmaxf(mold, mx);
            float corr = __expf(mold - mnew);
            float sum = 0.f;
            #pragma unroll
            for (int c = 0; c < 32; c++) {
                int col = half * 32 + c;
                float s = (k0 + col < Lk) ? row[col] : -1e30f;
                float p = __expf(s - mnew);
                row[col] = wmma::__float_to_tf32(p);
                sum += p;
            }
            sum += __shfl_xor_sync(0xffffffffu, sum, 1);
            if (half == 0) { sM[r] = mnew; sL[r] = sL[r] * corr + sum; }
            float* orow = &sO[r * 48];
            #pragma unroll
            for (int c = 0; c < 24; c++) orow[half * 24 + c] *= corr;
        }
        __syncwarp();

        // PV : band 16 rows x 48 dh
        wmma::fragment<wmma::accumulator, 16, 16, 8, float> pv[3];
        #pragma unroll
        for (int j = 0; j < 3; j++) wmma::fill_fragment(pv[j], 0.f);
        #pragma unroll
        for (int kk = 0; kk < 8; kk++) {
            wmma::fragment<wmma::matrix_a, 16, 16, 8, wmma::precision::tf32, wmma::row_major> pa;
            wmma::load_matrix_sync(pa, &sS[(w*16)*68 + kk*8], 68);
            #pragma unroll
            for (int j = 0; j < 3; j++) {
                wmma::fragment<wmma::matrix_b, 16, 16, 8, wmma::precision::tf32, wmma::row_major> vb;
                wmma::load_matrix_sync(vb, &sV[(kk*8)*48 + j*16], 48);
                wmma::mma_sync(pv[j], pa, vb, pv[j]);
            }
        }
        #pragma unroll
        for (int j = 0; j < 3; j++)
            wmma::store_matrix_sync(&sS[(w*16)*68 + j*16], pv[j], 68, wmma::mem_row_major);
        __syncwarp();
        {
            int r = w * 16 + (lane >> 1);
            int half = lane & 1;
            #pragma unroll
            for (int c = 0; c < 24; c++) {
                int col = half * 24 + c;
                sO[r*48 + col] += sS[r*68 + col];
            }
        }
        __syncthreads();   // protect sK/sV/sS for next tile
    }

    for (int i = tid; i < 64 * DH; i += 128) {
        int r = i / DH, j = i - r * DH;
        O[(size_t)(qbase + r) * C_DIM + h * DH + j] = sO[r*48 + j] / sL[r];
    }
}

// ---------------- GEGLU ----------------
__global__ void geglu_kernel(const float* __restrict__ p, float* __restrict__ g)
{
    int idx = blockIdx.x * blockDim.x + threadIdx.x;
    if (idx >= L_TOK * FFI) return;
    int l = idx / FFI, i = idx - l * FFI;
    float a = p[l * 2 * FFI + i];
    float x = p[l * 2 * FFI + FFI + i];
    float ge = 0.5f * x * (1.f + erff(x * 0.70710678118654752f));
    g[idx] = a * ge;
}

// ---------------------------------------------------------------------------
extern "C" void kernel_launch(void* const* d_in, const int* in_sizes, int n_in,
                              void* d_out, int out_size)
{
    const float* x       = (const float*)d_in[0];
    const float* context = (const float*)d_in[1];
    const float* gn_w    = (const float*)d_in[2];
    const float* gn_b    = (const float*)d_in[3];
    const float* w_in    = (const float*)d_in[4];
    const float* b_in    = (const float*)d_in[5];
    const float* ln1_w   = (const float*)d_in[6];
    const float* ln1_b   = (const float*)d_in[7];
    const float* wq1     = (const float*)d_in[8];
    const float* wk1     = (const float*)d_in[9];
    const float* wv1     = (const float*)d_in[10];
    const float* wo1     = (const float*)d_in[11];
    const float* bo1     = (const float*)d_in[12];
    const float* ln2_w   = (const float*)d_in[13];
    const float* ln2_b   = (const float*)d_in[14];
    const float* wq2     = (const float*)d_in[15];
    const float* wk2     = (const float*)d_in[16];
    const float* wv2     = (const float*)d_in[17];
    const float* wo2     = (const float*)d_in[18];
    const float* bo2     = (const float*)d_in[19];
    const float* ln3_w   = (const float*)d_in[20];
    const float* ln3_b   = (const float*)d_in[21];
    const float* wff1    = (const float*)d_in[22];
    const float* bff1    = (const float*)d_in[23];
    const float* wff2    = (const float*)d_in[24];
    const float* bff2    = (const float*)d_in[25];
    const float* w_out   = (const float*)d_in[26];
    const float* b_out   = (const float*)d_in[27];
    float* out = (float*)d_out;

    static float *xn = nullptr, *t, *hn, *q, *k, *v, *a, *p, *gg;
    static bool attr_set = false;
    if (!xn) {
        cudaGetSymbolAddress((void**)&xn, g_xn);
        cudaGetSymbolAddress((void**)&t,  g_t);
        cudaGetSymbolAddress((void**)&hn, g_hn);
        cudaGetSymbolAddress((void**)&q,  g_q);
        cudaGetSymbolAddress((void**)&k,  g_k);
        cudaGetSymbolAddress((void**)&v,  g_v);
        cudaGetSymbolAddress((void**)&a,  g_a);
        cudaGetSymbolAddress((void**)&p,  g_p);
        cudaGetSymbolAddress((void**)&gg, g_gg);
    }
    if (!attr_set) {
        cudaFuncSetAttribute(attn_tc_kernel,
                             cudaFuncAttributeMaxDynamicSharedMemorySize,
                             ATTN_SMEM_BYTES);
        attr_set = true;
    }

    dim3 g320(C_DIM / 64, L_TOK / 128);          // (5, 32)
    dim3 gFF1(2 * FFI / 64, L_TOK / 128);        // (40, 32)
    dim3 gCtx(C_DIM / 64, 1);                    // (5, 1)  M=77
    dim3 attnGrid(L_TOK / 64, HEADS);            // (64, 8)

    // GroupNorm + proj_in
    gn_stats_kernel<<<NGROUPS, 256>>>(x);
    gn_apply_kernel<<<(C_DIM * L_TOK + 255) / 256, 256>>>(x, gn_w, gn_b);
    gemm_tc_kernel<<<g320, 256>>>(xn, w_in, b_in, nullptr, t,
                                  L_TOK, C_DIM, C_DIM, 0);

    // ---- self-attention ----
    ln_kernel<<<L_TOK / 4, 128>>>(t, ln1_w, ln1_b, hn);
    gemm_tc_kernel<<<g320, 256>>>(hn, wq1, nullptr, nullptr, q,
                                  L_TOK, C_DIM, C_DIM, 0);
    gemm_tc_kernel<<<g320, 256>>>(q, wk1, nullptr, nullptr, k,
                                  L_TOK, C_DIM, C_DIM, 0);
    gemm_tc_kernel<<<g320, 256>>>(q, wv1, nullptr, nullptr, v,
                                  L_TOK, C_DIM, C_DIM, 0);
    attn_tc_kernel<<<attnGrid, 128, ATTN_SMEM_BYTES>>>(q, k, v, a, L_TOK);
    gemm_tc_kernel<<<g320, 256>>>(a, wo1, bo1, t, t,
                                  L_TOK, C_DIM, C_DIM, 0);

    // ---- cross-attention ----
    ln_kernel<<<L_TOK / 4, 128>>>(t, ln2_w, ln2_b, hn);
    gemm_tc_kernel<<<g320, 256>>>(hn, wq2, nullptr, nullptr, q,
                                  L_TOK, C_DIM, C_DIM, 0);
    gemm_tc_kernel<<<gCtx, 256>>>(context, wk2, nullptr, nullptr, k,
                                  LCTX, C_DIM, CTX_DIM, 0);
    gemm_tc_kernel<<<gCtx, 256>>>(context, wv2, nullptr, nullptr, v,
                                  LCTX, C_DIM, CTX_DIM, 0);
    attn_tc_kernel<<<attnGrid, 128, ATTN_SMEM_BYTES>>>(q, k, v, a, LCTX);
    gemm_tc_kernel<<<g320, 256>>>(a, wo2, bo2, t, t,
                                  L_TOK, C_DIM, C_DIM, 0);

    // ---- feed-forward (GEGLU) ----
    ln_kernel<<<L_TOK / 4, 128>>>(t, ln3_w, ln3_b, hn);
    gemm_tc_kernel<<<gFF1, 256>>>(hn, wff1, bff1, nullptr, p,
                                  L_TOK, 2 * FFI, C_DIM, 0);
    geglu_kernel<<<(L_TOK * FFI + 255) / 256, 256>>>(p, gg);
    gemm_tc_kernel<<<g320, 256>>>(gg, wff2, bff2, t, t,
                                  L_TOK, C_DIM, FFI, 0);

    // ---- proj_out (+ x residual), channel-major store ----
    gemm_tc_kernel<<<g320, 256>>>(t, w_out, b_out, x, out,
                                  L_TOK, C_DIM, C_DIM, 1);
}

// round 3
// speedup vs baseline: 1.1849x; 1.1223x over previous
#include <cuda_runtime.h>
#include <cuda_bf16.h>
#include <mma.h>
#include <math.h>

using namespace nvcuda;

// ---------------------------------------------------------------------------
// SpatialTransformer — round 2: tf32 TC everywhere + head-major Q/K/V layouts
// written by GEMM epilogues so attention loads are coalesced float4.
// ---------------------------------------------------------------------------

#define L_TOK   4096
#define C_DIM   320
#define HEADS   8
#define DH      40
#define DHP     48          // dh padded to 48 (6 x 8)
#define CTX_DIM 768
#define LCTX    77
#define LCTXP   128
#define FFI     1280
#define NGROUPS 32
#define CH_PER_G 10
#define AQ      128         // queries per attention block

// scratch
__device__ float g_xn[L_TOK * C_DIM];
__device__ float g_t [L_TOK * C_DIM];
__device__ float g_hn[L_TOK * C_DIM];
__device__ float g_q [L_TOK * C_DIM];
__device__ float g_a [L_TOK * C_DIM];
__device__ float g_p [L_TOK * 2 * FFI];
__device__ float g_gg[L_TOK * FFI];
__device__ float g_qh[HEADS * L_TOK * DHP];
__device__ float g_kh[HEADS * L_TOK * DHP];
__device__ float g_vh[HEADS * L_TOK * DHP];
__device__ float g_k2h[HEADS * LCTXP * DHP];
__device__ float g_v2h[HEADS * LCTXP * DHP];
__device__ float g_mean[NGROUPS];
__device__ float g_rstd[NGROUPS];

// ---------------- zero fill ----------------
__global__ void zero_kernel(float4* p, int n4)
{
    int i = blockIdx.x * blockDim.x + threadIdx.x;
    if (i < n4) p[i] = make_float4(0.f, 0.f, 0.f, 0.f);
}

// ---------------- GroupNorm ----------------
__global__ void gn_stats_kernel(const float* __restrict__ x)
{
    int g = blockIdx.x;
    int tid = threadIdx.x;
    const int NEL = CH_PER_G * L_TOK;
    float s = 0.f, ss = 0.f;
    const float* base = x + g * CH_PER_G * L_TOK;
    for (int i = tid; i < NEL; i += blockDim.x) {
        float v = base[i];
        s += v; ss += v * v;
    }
    __shared__ float rs[256], rss[256];
    rs[tid] = s; rss[tid] = ss;
    __syncthreads();
    for (int o = 128; o > 0; o >>= 1) {
        if (tid < o) { rs[tid] += rs[tid + o]; rss[tid] += rss[tid + o]; }
        __syncthreads();
    }
    if (tid == 0) {
        float m = rs[0] / (float)NEL;
        float var = rss[0] / (float)NEL - m * m;
        g_mean[g] = m;
        g_rstd[g] = rsqrtf(var + 1e-6f);
    }
}

__global__ void gn_apply_kernel(const float* __restrict__ x,
                                const float* __restrict__ gw,
                                const float* __restrict__ gb)
{
    int idx = blockIdx.x * blockDim.x + threadIdx.x;
    if (idx >= C_DIM * L_TOK) return;
    int c = idx / L_TOK;
    int hw = idx % L_TOK;
    int g = c / CH_PER_G;
    float v = (x[idx] - g_mean[g]) * g_rstd[g] * gw[c] + gb[c];
    g_xn[hw * C_DIM + c] = v;
}

// ---------------- LayerNorm ----------------
__global__ void ln_kernel(const float* __restrict__ in,
                          const float* __restrict__ w,
                          const float* __restrict__ b,
                          float* __restrict__ out)
{
    int token = blockIdx.x * (blockDim.x / 32) + (threadIdx.x >> 5);
    int lane = threadIdx.x & 31;
    if (token >= L_TOK) return;
    const float* row = in + token * C_DIM;
    float s = 0.f, ss = 0.f;
    for (int j = lane; j < C_DIM; j += 32) {
        float v = row[j];
        s += v; ss += v * v;
    }
    #pragma unroll
    for (int o = 16; o > 0; o >>= 1) {
        s  += __shfl_xor_sync(0xffffffffu, s, o);
        ss += __shfl_xor_sync(0xffffffffu, ss, o);
    }
    float m = s / (float)C_DIM;
    float var = ss / (float)C_DIM - m * m;
    float r = rsqrtf(var + 1e-5f);
    float* orow = out + token * C_DIM;
    for (int j = lane; j < C_DIM; j += 32)
        orow[j] = (row[j] - m) * r * w[j] + b[j];
}

// ---------------- tf32 tensor-core GEMM (64x64x32, 128 thr) ----------------
// C[m,n] = sum_k A[m,k]*B[k,n] (+bias) (+res).
// Optional head-major store: attnOut[((n&7)*Lpad + m)*48 + (n>>3)] = tf32(v*scale)
__global__ __launch_bounds__(128) void gemm_tc_kernel(
    const float* __restrict__ A, const float* __restrict__ B,
    const float* __restrict__ bias, const float* __restrict__ res,
    float* __restrict__ C, float* __restrict__ attnOut,
    float attnScale, int Lpad,
    int M, int N, int K, int transOut)
{
    struct InBuf { float As[64][36]; float Bs[32][68]; };
    __shared__ union SU { InBuf in; float Cs[64][68]; } sm;

    int bm = blockIdx.y * 64;
    int bn = blockIdx.x * 64;
    int tid = threadIdx.x;
    int w = tid >> 5;
    int wm = w >> 1;
    int wn = w & 1;

    wmma::fragment<wmma::accumulator, 16, 16, 8, float> acc[2][2];
    #pragma unroll
    for (int i = 0; i < 2; i++)
        #pragma unroll
        for (int j = 0; j < 2; j++) wmma::fill_fragment(acc[i][j], 0.f);

    for (int k0 = 0; k0 < K; k0 += 32) {
        #pragma unroll
        for (int p = 0; p < 4; p++) {
            int i = tid + p * 128;
            int m = i >> 3, c4 = i & 7;
            float4 v = make_float4(0.f, 0.f, 0.f, 0.f);
            int gm = bm + m;
            if (gm < M) v = *(const float4*)&A[(size_t)gm * K + k0 + c4 * 4];
            sm.in.As[m][c4*4+0] = wmma::__float_to_tf32(v.x);
            sm.in.As[m][c4*4+1] = wmma::__float_to_tf32(v.y);
            sm.in.As[m][c4*4+2] = wmma::__float_to_tf32(v.z);
            sm.in.As[m][c4*4+3] = wmma::__float_to_tf32(v.w);
        }
        #pragma unroll
        for (int p = 0; p < 4; p++) {
            int i = tid + p * 128;
            int kk = i >> 4, c4 = i & 15;
            float4 v = *(const float4*)&B[(size_t)(k0 + kk) * N + bn + c4 * 4];
            sm.in.Bs[kk][c4*4+0] = wmma::__float_to_tf32(v.x);
            sm.in.Bs[kk][c4*4+1] = wmma::__float_to_tf32(v.y);
            sm.in.Bs[kk][c4*4+2] = wmma::__float_to_tf32(v.z);
            sm.in.Bs[kk][c4*4+3] = wmma::__float_to_tf32(v.w);
        }
        __syncthreads();
        #pragma unroll
        for (int ks = 0; ks < 4; ks++) {
            wmma::fragment<wmma::matrix_a, 16, 16, 8, wmma::precision::tf32, wmma::row_major> af[2];
            wmma::fragment<wmma::matrix_b, 16, 16, 8, wmma::precision::tf32, wmma::row_major> bf[2];
            wmma::load_matrix_sync(af[0], &sm.in.As[wm*32     ][ks*8], 36);
            wmma::load_matrix_sync(af[1], &sm.in.As[wm*32 + 16][ks*8], 36);
            wmma::load_matrix_sync(bf[0], &sm.in.Bs[ks*8][wn*32     ], 68);
            wmma::load_matrix_sync(bf[1], &sm.in.Bs[ks*8][wn*32 + 16], 68);
            #pragma unroll
            for (int i = 0; i < 2; i++)
                #pragma unroll
                for (int j = 0; j < 2; j++)
                    wmma::mma_sync(acc[i][j], af[i], bf[j], acc[i][j]);
        }
        __syncthreads();
    }

    #pragma unroll
    for (int i = 0; i < 2; i++)
        #pragma unroll
        for (int j = 0; j < 2; j++)
            wmma::store_matrix_sync(&sm.Cs[wm*32 + i*16][wn*32 + j*16],
                                    acc[i][j], 68, wmma::mem_row_major);
    __syncthreads();
    #pragma unroll
    for (int p = 0; p < 32; p++) {
        int i = tid + p * 128;
        int m = i >> 6, n = i & 63;
        int gm = bm + m, gn = bn + n;
        if (gm >= M) continue;
        float v = sm.Cs[m][n];
        if (bias) v += bias[gn];
        if (C) {
            size_t idx = transOut ? ((size_t)gn * M + gm) : ((size_t)gm * N + gn);
            if (res) v += res[idx];
            C[idx] = v;
        }
        if (attnOut) {
            int h = gn & 7, j = gn >> 3;
            attnOut[((size_t)h * Lpad + gm) * DHP + j] =
                wmma::__float_to_tf32(v * attnScale);
        }
    }
}

// ---------------- tf32 flash attention (128 queries, 8 warps) ----------------
// qh: [8][L_TOK][48] (pre-scaled, tf32), kh/vh: [8][Lpad][48] (tf32)
#define ATTN_SMEM_BYTES ((3072 + 3072 + AQ*68 + AQ*48 + 2*AQ) * 4)

__global__ __launch_bounds__(256) void attn_tc_kernel(
    const float* __restrict__ qh, const float* __restrict__ kh,
    const float* __restrict__ vh, float* __restrict__ O,
    int Lk, int Lpad)
{
    extern __shared__ float smf[];
    float* sK = smf;                 // [64][48]
    float* sV = sK + 3072;           // [64][48]
    float* sS = sV + 3072;           // [AQ][68]
    float* sO = sS + AQ * 68;        // [AQ][48]
    float* sM = sO + AQ * 48;        // [AQ]
    float* sL = sM + AQ;             // [AQ]

    int h = blockIdx.y;
    int qbase = blockIdx.x * AQ;
    int tid = threadIdx.x;
    int w = tid >> 5;
    int lane = tid & 31;

    // stage Q band [AQ][48] into sS (coalesced float4)
    {
        const float4* src = (const float4*)(qh + ((size_t)h * L_TOK + qbase) * DHP);
        float4* dst = (float4*)sS;
        #pragma unroll
        for (int p = 0; p < AQ * 12 / 256; p++)
            dst[tid + p * 256] = src[tid + p * 256];
    }
    for (int i = tid; i < AQ * 48; i += 256) sO[i] = 0.f;
    if (tid < AQ) { sM[tid] = -1e30f; sL[tid] = 0.f; }
    __syncthreads();

    wmma::fragment<wmma::matrix_a, 16, 16, 8, wmma::precision::tf32, wmma::row_major> qa[6];
    #pragma unroll
    for (int kd = 0; kd < 6; kd++)
        wmma::load_matrix_sync(qa[kd], &sS[(w * 16) * 48 + kd * 8], 48);
    __syncthreads();

    for (int k0 = 0; k0 < Lk; k0 += 64) {
        // coalesced K/V tile load: 64 rows x 12 float4 each
        {
            const float4* ksrc = (const float4*)(kh + ((size_t)h * Lpad + k0) * DHP);
            const float4* vsrc = (const float4*)(vh + ((size_t)h * Lpad + k0) * DHP);
            float4* kdst = (float4*)sK;
            float4* vdst = (float4*)sV;
            #pragma unroll
            for (int p = 0; p < 3; p++) {
                kdst[tid + p * 256] = ksrc[tid + p * 256];
                vdst[tid + p * 256] = vsrc[tid + p * 256];
            }
        }
        __syncthreads();

        // S = Q K^T : per-warp 16 rows x 64 keys
        wmma::fragment<wmma::accumulator, 16, 16, 8, float> sacc[4];
        #pragma unroll
        for (int j = 0; j < 4; j++) wmma::fill_fragment(sacc[j], 0.f);
        #pragma unroll
        for (int kd = 0; kd < 6; kd++) {
            #pragma unroll
            for (int j = 0; j < 4; j++) {
                wmma::fragment<wmma::matrix_b, 16, 16, 8, wmma::precision::tf32, wmma::col_major> kb;
                wmma::load_matrix_sync(kb, &sK[(j * 16) * 48 + kd * 8], 48);
                wmma::mma_sync(sacc[j], qa[kd], kb, sacc[j]);
            }
        }
        #pragma unroll
        for (int j = 0; j < 4; j++)
            wmma::store_matrix_sync(&sS[(w * 16) * 68 + j * 16], sacc[j], 68,
                                    wmma::mem_row_major);
        __syncwarp();

        // online softmax on this warp's 16 rows (2 lanes per row)
        {
            int r = w * 16 + (lane >> 1);
            int half = lane & 1;
            float* row = &sS[r * 68];
            float mx = -1e30f;
            #pragma unroll
            for (int c = 0; c < 32; c++) {
                int col = half * 32 + c;
                float s = (k0 + col < Lk) ? row[col] : -1e30f;
                mx = fmaxf(mx, s);
            }
            mx = fmaxf(mx, __shfl_xor_sync(0xffffffffu, mx, 1));
            float mold = sM[r];
            float mnew = fmaxf(mold, mx);
            float corr = __expf(mold - mnew);
            float sum = 0.f;
            #pragma unroll
            for (int c = 0; c < 32; c++) {
                int col = half * 32 + c;
                float s = (k0 + col < Lk) ? row[col] : -1e30f;
                float p = __expf(s - mnew);
                row[col] = wmma::__float_to_tf32(p);
                sum += p;
            }
            sum += __shfl_xor_sync(0xffffffffu, sum, 1);
            if (half == 0) { sM[r] = mnew; sL[r] = sL[r] * corr + sum; }
            float* orow = &sO[r * 48];
            #pragma unroll
            for (int c = 0; c < 24; c++) orow[half * 24 + c] *= corr;
        }
        __syncwarp();

        // PV : 16 rows x 48 dh
        wmma::fragment<wmma::accumulator, 16, 16, 8, float> pv[3];
        #pragma unroll
        for (int j = 0; j < 3; j++) wmma::fill_fragment(pv[j], 0.f);
        #pragma unroll
        for (int kk = 0; kk < 8; kk++) {
            wmma::fragment<wmma::matrix_a, 16, 16, 8, wmma::precision::tf32, wmma::row_major> pa;
            wmma::load_matrix_sync(pa, &sS[(w * 16) * 68 + kk * 8], 68);
            #pragma unroll
            for (int j = 0; j < 3; j++) {
                wmma::fragment<wmma::matrix_b, 16, 16, 8, wmma::precision::tf32, wmma::row_major> vb;
                wmma::load_matrix_sync(vb, &sV[(kk * 8) * 48 + j * 16], 48);
                wmma::mma_sync(pv[j], pa, vb, pv[j]);
            }
        }
        #pragma unroll
        for (int j = 0; j < 3; j++)
            wmma::store_matrix_sync(&sS[(w * 16) * 68 + j * 16], pv[j], 68,
                                    wmma::mem_row_major);
        __syncwarp();
        {
            int r = w * 16 + (lane >> 1);
            int half = lane & 1;
            #pragma unroll
            for (int c = 0; c < 24; c++) {
                int col = half * 24 + c;
                sO[r * 48 + col] += sS[r * 68 + col];
            }
        }
        __syncthreads();
    }

    for (int i = tid; i < AQ * DH; i += 256) {
        int r = i / DH, j = i - r * DH;
        O[(size_t)(qbase + r) * C_DIM + h * DH + j] = sO[r * 48 + j] / sL[r];
    }
}

// ---------------- GEGLU ----------------
__global__ void geglu_kernel(const float* __restrict__ p, float* __restrict__ g)
{
    int idx = blockIdx.x * blockDim.x + threadIdx.x;
    if (idx >= L_TOK * FFI) return;
    int l = idx / FFI, i = idx - l * FFI;
    float a = p[l * 2 * FFI + i];
    float x = p[l * 2 * FFI + FFI + i];
    float ge = 0.5f * x * (1.f + erff(x * 0.70710678118654752f));
    g[idx] = a * ge;
}

// ---------------------------------------------------------------------------
extern "C" void kernel_launch(void* const* d_in, const int* in_sizes, int n_in,
                              void* d_out, int out_size)
{
    const float* x       = (const float*)d_in[0];
    const float* context = (const float*)d_in[1];
    const float* gn_w    = (const float*)d_in[2];
    const float* gn_b    = (const float*)d_in[3];
    const float* w_in    = (const float*)d_in[4];
    const float* b_in    = (const float*)d_in[5];
    const float* ln1_w   = (const float*)d_in[6];
    const float* ln1_b   = (const float*)d_in[7];
    const float* wq1     = (const float*)d_in[8];
    const float* wk1     = (const float*)d_in[9];
    const float* wv1     = (const float*)d_in[10];
    const float* wo1     = (const float*)d_in[11];
    const float* bo1     = (const float*)d_in[12];
    const float* ln2_w   = (const float*)d_in[13];
    const float* ln2_b   = (const float*)d_in[14];
    const float* wq2     = (const float*)d_in[15];
    const float* wk2     = (const float*)d_in[16];
    const float* wv2     = (const float*)d_in[17];
    const float* wo2     = (const float*)d_in[18];
    const float* bo2     = (const float*)d_in[19];
    const float* ln3_w   = (const float*)d_in[20];
    const float* ln3_b   = (const float*)d_in[21];
    const float* wff1    = (const float*)d_in[22];
    const float* bff1    = (const float*)d_in[23];
    const float* wff2    = (const float*)d_in[24];
    const float* bff2    = (const float*)d_in[25];
    const float* w_out   = (const float*)d_in[26];
    const float* b_out   = (const float*)d_in[27];
    float* out = (float*)d_out;

    static float *xn = nullptr, *t, *hn, *q, *a, *p, *gg;
    static float *qh, *kh, *vh, *k2h, *v2h;
    static bool attr_set = false;
    if (!xn) {
        cudaGetSymbolAddress((void**)&xn, g_xn);
        cudaGetSymbolAddress((void**)&t,  g_t);
        cudaGetSymbolAddress((void**)&hn, g_hn);
        cudaGetSymbolAddress((void**)&q,  g_q);
        cudaGetSymbolAddress((void**)&a,  g_a);
        cudaGetSymbolAddress((void**)&p,  g_p);
        cudaGetSymbolAddress((void**)&gg, g_gg);
        cudaGetSymbolAddress((void**)&qh, g_qh);
        cudaGetSymbolAddress((void**)&kh, g_kh);
        cudaGetSymbolAddress((void**)&vh, g_vh);
        cudaGetSymbolAddress((void**)&k2h, g_k2h);
        cudaGetSymbolAddress((void**)&v2h, g_v2h);
    }
    if (!attr_set) {
        cudaFuncSetAttribute(attn_tc_kernel,
                             cudaFuncAttributeMaxDynamicSharedMemorySize,
                             ATTN_SMEM_BYTES);
        attr_set = true;
    }

    const float scale = 0.15811388300841898f;  // 1/sqrt(40)

    dim3 g320(C_DIM / 64, L_TOK / 64);           // (5, 64)
    dim3 gFF1(2 * FFI / 64, L_TOK / 64);         // (40, 64)
    dim3 gCtx(C_DIM / 64, 2);                    // (5, 2)  M=77
    dim3 attnGrid(L_TOK / AQ, HEADS);            // (32, 8)

    // zero pad regions of head-major buffers
    {
        int n4 = HEADS * L_TOK * DHP / 4;
        zero_kernel<<<(n4 + 255) / 256, 256>>>((float4*)qh, n4);
        zero_kernel<<<(n4 + 255) / 256, 256>>>((float4*)kh, n4);
        zero_kernel<<<(n4 + 255) / 256, 256>>>((float4*)vh, n4);
        int m4 = HEADS * LCTXP * DHP / 4;
        zero_kernel<<<(m4 + 255) / 256, 256>>>((float4*)k2h, m4);
        zero_kernel<<<(m4 + 255) / 256, 256>>>((float4*)v2h, m4);
    }

    // GroupNorm + proj_in
    gn_stats_kernel<<<NGROUPS, 256>>>(x);
    gn_apply_kernel<<<(C_DIM * L_TOK + 255) / 256, 256>>>(x, gn_w, gn_b);
    gemm_tc_kernel<<<g320, 128>>>(xn, w_in, b_in, nullptr, t, nullptr, 0.f, 0,
                                  L_TOK, C_DIM, C_DIM, 0);

    // ---- self-attention ----
    ln_kernel<<<L_TOK / 4, 128>>>(t, ln1_w, ln1_b, hn);
    gemm_tc_kernel<<<g320, 128>>>(hn, wq1, nullptr, nullptr, q, qh, scale, L_TOK,
                                  L_TOK, C_DIM, C_DIM, 0);
    gemm_tc_kernel<<<g320, 128>>>(q, wk1, nullptr, nullptr, nullptr, kh, 1.f, L_TOK,
                                  L_TOK, C_DIM, C_DIM, 0);
    gemm_tc_kernel<<<g320, 128>>>(q, wv1, nullptr, nullptr, nullptr, vh, 1.f, L_TOK,
                                  L_TOK, C_DIM, C_DIM, 0);
    attn_tc_kernel<<<attnGrid, 256, ATTN_SMEM_BYTES>>>(qh, kh, vh, a, L_TOK, L_TOK);
    gemm_tc_kernel<<<g320, 128>>>(a, wo1, bo1, t, t, nullptr, 0.f, 0,
                                  L_TOK, C_DIM, C_DIM, 0);

    // ---- cross-attention ----
    ln_kernel<<<L_TOK / 4, 128>>>(t, ln2_w, ln2_b, hn);
    gemm_tc_kernel<<<g320, 128>>>(hn, wq2, nullptr, nullptr, nullptr, qh, scale, L_TOK,
                                  L_TOK, C_DIM, C_DIM, 0);
    gemm_tc_kernel<<<gCtx, 128>>>(context, wk2, nullptr, nullptr, nullptr, k2h, 1.f, LCTXP,
                                  LCTX, C_DIM, CTX_DIM, 0);
    gemm_tc_kernel<<<gCtx, 128>>>(context, wv2, nullptr, nullptr, nullptr, v2h, 1.f, LCTXP,
                                  LCTX, C_DIM, CTX_DIM, 0);
    attn_tc_kernel<<<attnGrid, 256, ATTN_SMEM_BYTES>>>(qh, k2h, v2h, a, LCTX, LCTXP);
    gemm_tc_kernel<<<g320, 128>>>(a, wo2, bo2, t, t, nullptr, 0.f, 0,
                                  L_TOK, C_DIM, C_DIM, 0);

    // ---- feed-forward (GEGLU) ----
    ln_kernel<<<L_TOK / 4, 128>>>(t, ln3_w, ln3_b, hn);
    gemm_tc_kernel<<<gFF1, 128>>>(hn, wff1, bff1, nullptr, p, nullptr, 0.f, 0,
                                  L_TOK, 2 * FFI, C_DIM, 0);
    geglu_kernel<<<(L_TOK * FFI + 255) / 256, 256>>>(p, gg);
    gemm_tc_kernel<<<g320, 128>>>(gg, wff2, bff2, t, t, nullptr, 0.f, 0,
                                  L_TOK, C_DIM, FFI, 0);

    // ---- proj_out (+ x residual), channel-major store ----
    gemm_tc_kernel<<<g320, 128>>>(t, w_out, b_out, x, out, nullptr, 0.f, 0,
                                  L_TOK, C_DIM, C_DIM, 1);
}

// round 5
// speedup vs baseline: 1.9296x; 1.6285x over previous
#include <cuda_runtime.h>
#include <cuda_bf16.h>
#include <mma.h>
#include <math.h>
#include <cstdint>

using namespace nvcuda;

// ---------------------------------------------------------------------------
// SpatialTransformer — round 4: bf16 tensor cores + cp.async double buffering.
// (round-3 design; fixed missing <cstdint>)
// ---------------------------------------------------------------------------

#define L_TOK   4096
#define C_DIM   320
#define HEADS   8
#define DH      40
#define DHP     48
#define CTX_DIM 768
#define LCTX    77
#define LCTXP   128
#define FFI     1280
#define NGROUPS 32
#define CH_PER_G 10
#define AQ      128
#define AK      64

typedef __nv_bfloat16 bf16;

// fp32 scratch
__device__ float g_t [L_TOK * C_DIM];
__device__ float g_p [L_TOK * 2 * FFI];
__device__ float g_mean[NGROUPS];
__device__ float g_rstd[NGROUPS];
// bf16 activations
__device__ bf16 b_xn[L_TOK * C_DIM];
__device__ bf16 b_hn[L_TOK * C_DIM];
__device__ bf16 b_q [L_TOK * C_DIM];
__device__ bf16 b_a [L_TOK * C_DIM];
__device__ bf16 b_gg[L_TOK * FFI];
__device__ bf16 b_t [L_TOK * C_DIM];
__device__ bf16 b_qh[HEADS * L_TOK * DHP];
__device__ bf16 b_kh[HEADS * L_TOK * DHP];
__device__ bf16 b_vh[HEADS * L_TOK * DHP];
__device__ bf16 b_k2h[HEADS * LCTXP * DHP];
__device__ bf16 b_v2h[HEADS * LCTXP * DHP];
__device__ bf16 b_ctx[LCTX * CTX_DIM];
// bf16 weights
__device__ bf16 b_w_in[C_DIM * C_DIM];
__device__ bf16 b_wq1[C_DIM * C_DIM];
__device__ bf16 b_wk1[C_DIM * C_DIM];
__device__ bf16 b_wv1[C_DIM * C_DIM];
__device__ bf16 b_wo1[C_DIM * C_DIM];
__device__ bf16 b_wq2[C_DIM * C_DIM];
__device__ bf16 b_wk2[CTX_DIM * C_DIM];
__device__ bf16 b_wv2[CTX_DIM * C_DIM];
__device__ bf16 b_wo2[C_DIM * C_DIM];
__device__ bf16 b_wff1[C_DIM * 2 * FFI];
__device__ bf16 b_wff2[FFI * C_DIM];
__device__ bf16 b_wout[C_DIM * C_DIM];

// ---------------- cp.async helpers ----------------
__device__ __forceinline__ unsigned int smem_u32(const void* p)
{ return (unsigned int)__cvta_generic_to_shared(p); }

__device__ __forceinline__ void cp16(unsigned int dst, const void* src, int sz)
{ asm volatile("cp.async.cg.shared.global [%0], [%1], 16, %2;\n"
               :: "r"(dst), "l"(src), "r"(sz)); }

__device__ __forceinline__ void cp_commit()
{ asm volatile("cp.async.commit_group;\n"); }

template<int N> __device__ __forceinline__ void cp_wait()
{ asm volatile("cp.async.wait_group %0;\n" :: "n"(N)); }

// ---------------- fp32 -> bf16 conversion (4 jobs, float4-vectorized) -------
__global__ void cvt4_kernel(const float4* s0, __nv_bfloat162* d0, int n0,
                            const float4* s1, __nv_bfloat162* d1, int n1,
                            const float4* s2, __nv_bfloat162* d2, int n2,
                            const float4* s3, __nv_bfloat162* d3, int n3)
{
    int i0 = blockIdx.x * blockDim.x + threadIdx.x;
    int st = gridDim.x * blockDim.x;
    if (s0) for (int j = i0; j < n0; j += st) {
        float4 v = s0[j];
        d0[2*j]   = __floats2bfloat162_rn(v.x, v.y);
        d0[2*j+1] = __floats2bfloat162_rn(v.z, v.w);
    }
    if (s1) for (int j = i0; j < n1; j += st) {
        float4 v = s1[j];
        d1[2*j]   = __floats2bfloat162_rn(v.x, v.y);
        d1[2*j+1] = __floats2bfloat162_rn(v.z, v.w);
    }
    if (s2) for (int j = i0; j < n2; j += st) {
        float4 v = s2[j];
        d2[2*j]   = __floats2bfloat162_rn(v.x, v.y);
        d2[2*j+1] = __floats2bfloat162_rn(v.z, v.w);
    }
    if (s3) for (int j = i0; j < n3; j += st) {
        float4 v = s3[j];
        d3[2*j]   = __floats2bfloat162_rn(v.x, v.y);
        d3[2*j+1] = __floats2bfloat162_rn(v.z, v.w);
    }
}

// ---------------- zero head-major buffers ----------------
__global__ void zero_pads_kernel(uint4* a, uint4* b, uint4* c, uint4* d, uint4* e)
{
    const uint4 z = make_uint4(0, 0, 0, 0);
    int i = blockIdx.x * blockDim.x + threadIdx.x;
    int st = gridDim.x * blockDim.x;
    const int NB = HEADS * L_TOK * DHP / 8;   // 196608
    const int NS = HEADS * LCTXP * DHP / 8;   // 6144
    for (int j = i; j < NB; j += st) { a[j] = z; b[j] = z; c[j] = z; }
    for (int j = i; j < NS; j += st) { d[j] = z; e[j] = z; }
}

// ---------------- GroupNorm ----------------
__global__ void gn_stats_kernel(const float* __restrict__ x)
{
    int g = blockIdx.x;
    int tid = threadIdx.x;
    const int N4 = CH_PER_G * L_TOK / 4;
    float s = 0.f, ss = 0.f;
    const float4* base = (const float4*)(x + (size_t)g * CH_PER_G * L_TOK);
    for (int i = tid; i < N4; i += blockDim.x) {
        float4 v = base[i];
        s  += v.x + v.y + v.z + v.w;
        ss += v.x*v.x + v.y*v.y + v.z*v.z + v.w*v.w;
    }
    __shared__ float rs[256], rss[256];
    rs[tid] = s; rss[tid] = ss;
    __syncthreads();
    for (int o = 128; o > 0; o >>= 1) {
        if (tid < o) { rs[tid] += rs[tid + o]; rss[tid] += rss[tid + o]; }
        __syncthreads();
    }
    if (tid == 0) {
        const float NEL = (float)(CH_PER_G * L_TOK);
        float m = rs[0] / NEL;
        float var = rss[0] / NEL - m * m;
        g_mean[g] = m;
        g_rstd[g] = rsqrtf(var + 1e-6f);
    }
}

// normalize + affine + transpose (C,HW)->(HW,C), bf16 out, smem tiled
__global__ void gn_apply_kernel(const float* __restrict__ x,
                                const float* __restrict__ gw,
                                const float* __restrict__ gb,
                                bf16* __restrict__ out)
{
    __shared__ float tile[32][65];
    int hw0 = blockIdx.x * 64;
    int c0  = blockIdx.y * 32;
    #pragma unroll
    for (int p = 0; p < 8; p++) {
        int i = threadIdx.x + p * 256;
        int c = i >> 6, hw = i & 63;
        int gc = c0 + c;
        int g = gc / CH_PER_G;
        float v = (x[(size_t)gc * L_TOK + hw0 + hw] - g_mean[g]) * g_rstd[g]
                  * gw[gc] + gb[gc];
        tile[c][hw] = v;
    }
    __syncthreads();
    #pragma unroll
    for (int p = 0; p < 8; p++) {
        int i = threadIdx.x + p * 256;
        int hw = i >> 5, c = i & 31;
        out[(size_t)(hw0 + hw) * C_DIM + c0 + c] = __float2bfloat16(tile[c][hw]);
    }
}

// ---------------- LayerNorm (warp per token, bf16 out) ----------------
__global__ void ln_kernel(const float* __restrict__ in,
                          const float* __restrict__ w,
                          const float* __restrict__ b,
                          bf16* __restrict__ out)
{
    int token = blockIdx.x * (blockDim.x / 32) + (threadIdx.x >> 5);
    int lane = threadIdx.x & 31;
    if (token >= L_TOK) return;
    const float* row = in + (size_t)token * C_DIM;
    float s = 0.f, ss = 0.f;
    for (int j = lane; j < C_DIM; j += 32) {
        float v = row[j];
        s += v; ss += v * v;
    }
    #pragma unroll
    for (int o = 16; o > 0; o >>= 1) {
        s  += __shfl_xor_sync(0xffffffffu, s, o);
        ss += __shfl_xor_sync(0xffffffffu, ss, o);
    }
    float m = s / (float)C_DIM;
    float var = ss / (float)C_DIM - m * m;
    float r = rsqrtf(var + 1e-5f);
    bf16* orow = out + (size_t)token * C_DIM;
    for (int j = lane; j < C_DIM; j += 32)
        orow[j] = __float2bfloat16((row[j] - m) * r * w[j] + b[j]);
}

// ---------------- bf16 TC GEMM, 64x64x32, 2-stage cp.async ----------------
__global__ __launch_bounds__(128) void gemm_bf16_kernel(
    const bf16* __restrict__ A, const bf16* __restrict__ B,
    const float* __restrict__ bias, const float* __restrict__ res,
    float* __restrict__ Cf, bf16* __restrict__ Cbf,
    bf16* __restrict__ attnOut, float attnScale, int Lpad,
    int M, int N, int K, int transOut)
{
    struct InBuf { bf16 As[2][64][40]; bf16 Bs[2][32][72]; };
    __shared__ union SU { InBuf in; float Cs[64][68]; } sm;

    int bm = blockIdx.y * 64;
    int bn = blockIdx.x * 64;
    int tid = threadIdx.x;
    int w = tid >> 5, wm = w >> 1, wn = w & 1;

    wmma::fragment<wmma::accumulator, 16, 16, 16, float> acc[2][2];
    #pragma unroll
    for (int i = 0; i < 2; i++)
        #pragma unroll
        for (int j = 0; j < 2; j++) wmma::fill_fragment(acc[i][j], 0.f);

    auto issue = [&](int s, int k0) {
        #pragma unroll
        for (int p = 0; p < 2; p++) {
            int c = tid + p * 128;
            int row = c >> 2, ch = c & 3;
            int gm = bm + row;
            const bf16* src = A + (size_t)(gm < M ? gm : 0) * K + k0 + ch * 8;
            cp16(smem_u32(&sm.in.As[s][row][ch * 8]), src, (gm < M) ? 16 : 0);
        }
        #pragma unroll
        for (int p = 0; p < 2; p++) {
            int c = tid + p * 128;
            int row = c >> 3, ch = c & 7;
            const bf16* src = B + (size_t)(k0 + row) * N + bn + ch * 8;
            cp16(smem_u32(&sm.in.Bs[s][row][ch * 8]), src, 16);
        }
        cp_commit();
    };

    issue(0, 0);
    int nk = K / 32;
    for (int ki = 0; ki < nk; ki++) {
        int s = ki & 1;
        if (ki + 1 < nk) { issue(s ^ 1, (ki + 1) * 32); cp_wait<1>(); }
        else cp_wait<0>();
        __syncthreads();
        #pragma unroll
        for (int ks = 0; ks < 2; ks++) {
            wmma::fragment<wmma::matrix_a, 16, 16, 16, bf16, wmma::row_major> af[2];
            wmma::fragment<wmma::matrix_b, 16, 16, 16, bf16, wmma::row_major> bfr[2];
            wmma::load_matrix_sync(af[0], &sm.in.As[s][wm*32     ][ks*16], 40);
            wmma::load_matrix_sync(af[1], &sm.in.As[s][wm*32 + 16][ks*16], 40);
            wmma::load_matrix_sync(bfr[0], &sm.in.Bs[s][ks*16][wn*32     ], 72);
            wmma::load_matrix_sync(bfr[1], &sm.in.Bs[s][ks*16][wn*32 + 16], 72);
            #pragma unroll
            for (int i = 0; i < 2; i++)
                #pragma unroll
                for (int j = 0; j < 2; j++)
                    wmma::mma_sync(acc[i][j], af[i], bfr[j], acc[i][j]);
        }
        __syncthreads();
    }

    #pragma unroll
    for (int i = 0; i < 2; i++)
        #pragma unroll
        for (int j = 0; j < 2; j++)
            wmma::store_matrix_sync(&sm.Cs[wm*32 + i*16][wn*32 + j*16],
                                    acc[i][j], 68, wmma::mem_row_major);
    __syncthreads();
    #pragma unroll
    for (int p = 0; p < 32; p++) {
        int i = tid + p * 128;
        int m = i >> 6, n = i & 63;
        int gm = bm + m, gn = bn + n;
        if (gm >= M) continue;
        float v = sm.Cs[m][n];
        if (bias) v += bias[gn];
        if (Cf) {
            size_t idx = transOut ? ((size_t)gn * M + gm) : ((size_t)gm * N + gn);
            if (res) v += res[idx];
            Cf[idx] = v;
        }
        if (Cbf) Cbf[(size_t)gm * N + gn] = __float2bfloat16(v);
        if (attnOut) {
            int h = gn & 7, j = gn >> 3;
            attnOut[((size_t)h * Lpad + gm) * DHP + j] =
                __float2bfloat16(v * attnScale);
        }
    }
}

// ---------------- bf16 TC flash attention, cp.async double-buffered --------
#define ATTN_SMEM_BYTES (12288 + 12288 + 18432 + 34816 + 24576 + 1024)

__global__ __launch_bounds__(256) void attn_bf16_kernel(
    const bf16* __restrict__ qh, const bf16* __restrict__ kh,
    const bf16* __restrict__ vh, bf16* __restrict__ Obf,
    int Lk, int Lpad)
{
    extern __shared__ char smraw[];
    bf16* sK = (bf16*)smraw;                       // 2*64*48
    bf16* sV = sK + 2 * 64 * 48;                   // 2*64*48
    bf16* sP = sV + 2 * 64 * 48;                   // 128*72
    float* sS = (float*)(smraw + 12288 + 12288 + 18432);  // 128*68
    float* sO = sS + 128 * 68;                     // 128*48
    float* sM = sO + 128 * 48;
    float* sL = sM + 128;

    int h = blockIdx.y;
    int qbase = blockIdx.x * AQ;
    int tid = threadIdx.x;
    int w = tid >> 5;
    int lane = tid & 31;

    auto load_kv = [&](int s, int k0) {
        const bf16* kp = kh + ((size_t)h * Lpad + k0) * DHP;
        const bf16* vp = vh + ((size_t)h * Lpad + k0) * DHP;
        #pragma unroll
        for (int p = 0; p < 3; p++) {
            int c = tid + p * 256;   // 0..767 ; 384 K chunks + 384 V chunks
            if (c < 384) cp16(smem_u32(sK + s * 3072 + c * 8), kp + c * 8, 16);
            else         cp16(smem_u32(sV + s * 3072 + (c - 384) * 8),
                              vp + (c - 384) * 8, 16);
        }
        cp_commit();
    };

    load_kv(0, 0);

    // stage Q (stride 48) into sP region
    {
        const uint4* src = (const uint4*)(qh + ((size_t)h * L_TOK + qbase) * DHP);
        uint4* dst = (uint4*)sP;
        #pragma unroll
        for (int p = 0; p < 3; p++) dst[tid + p * 256] = src[tid + p * 256];
    }
    for (int i = tid; i < 128 * 48; i += 256) sO[i] = 0.f;
    if (tid < 128) { sM[tid] = -1e30f; sL[tid] = 0.f; }
    __syncthreads();

    wmma::fragment<wmma::matrix_a, 16, 16, 16, bf16, wmma::row_major> qa[3];
    #pragma unroll
    for (int kd = 0; kd < 3; kd++)
        wmma::load_matrix_sync(qa[kd], sP + (w * 16) * 48 + kd * 16, 48);

    int ntiles = (Lk + AK - 1) / AK;
    for (int ti = 0; ti < ntiles; ti++) {
        int s = ti & 1;
        if (ti + 1 < ntiles) { load_kv(s ^ 1, (ti + 1) * AK); cp_wait<1>(); }
        else cp_wait<0>();
        __syncthreads();
        int k0 = ti * AK;

        // S = Q K^T (16 rows x 64 keys per warp)
        wmma::fragment<wmma::accumulator, 16, 16, 16, float> sacc[4];
        #pragma unroll
        for (int j = 0; j < 4; j++) wmma::fill_fragment(sacc[j], 0.f);
        #pragma unroll
        for (int kd = 0; kd < 3; kd++)
            #pragma unroll
            for (int j = 0; j < 4; j++) {
                wmma::fragment<wmma::matrix_b, 16, 16, 16, bf16, wmma::col_major> kb;
                wmma::load_matrix_sync(kb, sK + s * 3072 + (j * 16) * 48 + kd * 16, 48);
                wmma::mma_sync(sacc[j], qa[kd], kb, sacc[j]);
            }
        #pragma unroll
        for (int j = 0; j < 4; j++)
            wmma::store_matrix_sync(&sS[(w * 16) * 68 + j * 16], sacc[j], 68,
                                    wmma::mem_row_major);
        __syncwarp();

        // online softmax: 2 lanes per row
        {
            int r = w * 16 + (lane >> 1);
            int half = lane & 1;
            float* row = &sS[r * 68];
            float mx = -1e30f;
            #pragma unroll
            for (int c = 0; c < 32; c++) {
                int col = half * 32 + c;
                float sv = (k0 + col < Lk) ? row[col] : -1e30f;
                mx = fmaxf(mx, sv);
            }
            mx = fmaxf(mx, __shfl_xor_sync(0xffffffffu, mx, 1));
            float mold = sM[r];
            float mnew = fmaxf(mold, mx);
            float corr = __expf(mold - mnew);
            float sum = 0.f;
            bf16* prow = sP + r * 72;
            #pragma unroll
            for (int c = 0; c < 32; c++) {
                int col = half * 32 + c;
                float sv = (k0 + col < Lk) ? row[col] : -1e30f;
                float pe = __expf(sv - mnew);
                prow[col] = __float2bfloat16(pe);
                sum += pe;
            }
            sum += __shfl_xor_sync(0xffffffffu, sum, 1);
            if (half == 0) { sM[r] = mnew; sL[r] = sL[r] * corr + sum; }
            float* orow = &sO[r * 48];
            #pragma unroll
            for (int c = 0; c < 24; c++) orow[half * 24 + c] *= corr;
        }
        __syncwarp();

        // PV (16 rows x 48 dh per warp)
        wmma::fragment<wmma::accumulator, 16, 16, 16, float> pv[3];
        #pragma unroll
        for (int j = 0; j < 3; j++) wmma::fill_fragment(pv[j], 0.f);
        #pragma unroll
        for (int kk = 0; kk < 4; kk++) {
            wmma::fragment<wmma::matrix_a, 16, 16, 16, bf16, wmma::row_major> pa;
            wmma::load_matrix_sync(pa, sP + (w * 16) * 72 + kk * 16, 72);
            #pragma unroll
            for (int j = 0; j < 3; j++) {
                wmma::fragment<wmma::matrix_b, 16, 16, 16, bf16, wmma::row_major> vb;
                wmma::load_matrix_sync(vb, sV + s * 3072 + (kk * 16) * 48 + j * 16, 48);
                wmma::mma_sync(pv[j], pa, vb, pv[j]);
            }
        }
        #pragma unroll
        for (int j = 0; j < 3; j++)
            wmma::store_matrix_sync(&sS[(w * 16) * 68 + j * 16], pv[j], 68,
                                    wmma::mem_row_major);
        __syncwarp();
        {
            int r = w * 16 + (lane >> 1);
            int half = lane & 1;
            #pragma unroll
            for (int c = 0; c < 24; c++) {
                int col = half * 24 + c;
                sO[r * 48 + col] += sS[r * 68 + col];
            }
        }
        __syncthreads();
    }

    for (int i = tid; i < AQ * DH; i += 256) {
        int r = i / DH, j = i - r * DH;
        Obf[(size_t)(qbase + r) * C_DIM + h * DH + j] =
            __float2bfloat16(sO[r * 48 + j] / sL[r]);
    }
}

// ---------------- GEGLU ----------------
__global__ void geglu_kernel(const float* __restrict__ p, bf16* __restrict__ g)
{
    int idx = blockIdx.x * blockDim.x + threadIdx.x;
    if (idx >= L_TOK * FFI) return;
    int l = idx / FFI, i = idx - l * FFI;
    float a = p[(size_t)l * 2 * FFI + i];
    float x = p[(size_t)l * 2 * FFI + FFI + i];
    float ge = 0.5f * x * (1.f + erff(x * 0.70710678118654752f));
    g[idx] = __float2bfloat16(a * ge);
}

// ---------------------------------------------------------------------------
extern "C" void kernel_launch(void* const* d_in, const int* in_sizes, int n_in,
                              void* d_out, int out_size)
{
    const float* x       = (const float*)d_in[0];
    const float* context = (const float*)d_in[1];
    const float* gn_w    = (const float*)d_in[2];
    const float* gn_b    = (const float*)d_in[3];
    const float* w_in    = (const float*)d_in[4];
    const float* b_in    = (const float*)d_in[5];
    const float* ln1_w   = (const float*)d_in[6];
    const float* ln1_b   = (const float*)d_in[7];
    const float* wq1     = (const float*)d_in[8];
    const float* wk1     = (const float*)d_in[9];
    const float* wv1     = (const float*)d_in[10];
    const float* wo1     = (const float*)d_in[11];
    const float* bo1     = (const float*)d_in[12];
    const float* ln2_w   = (const float*)d_in[13];
    const float* ln2_b   = (const float*)d_in[14];
    const float* wq2     = (const float*)d_in[15];
    const float* wk2     = (const float*)d_in[16];
    const float* wv2     = (const float*)d_in[17];
    const float* wo2     = (const float*)d_in[18];
    const float* bo2     = (const float*)d_in[19];
    const float* ln3_w   = (const float*)d_in[20];
    const float* ln3_b   = (const float*)d_in[21];
    const float* wff1    = (const float*)d_in[22];
    const float* bff1    = (const float*)d_in[23];
    const float* wff2    = (const float*)d_in[24];
    const float* bff2    = (const float*)d_in[25];
    const float* w_out   = (const float*)d_in[26];
    const float* b_out   = (const float*)d_in[27];
    float* out = (float*)d_out;

    static float *t = nullptr, *p;
    static bf16 *xn, *hn, *q, *a, *gg, *tb, *qh, *kh, *vh, *k2h, *v2h, *ctx;
    static bf16 *cw_in, *cwq1, *cwk1, *cwv1, *cwo1, *cwq2, *cwk2, *cwv2, *cwo2,
                *cwff1, *cwff2, *cwout;
    static bool init_done = false;
    if (!init_done) {
        cudaGetSymbolAddress((void**)&t,  g_t);
        cudaGetSymbolAddress((void**)&p,  g_p);
        cudaGetSymbolAddress((void**)&xn, b_xn);
        cudaGetSymbolAddress((void**)&hn, b_hn);
        cudaGetSymbolAddress((void**)&q,  b_q);
        cudaGetSymbolAddress((void**)&a,  b_a);
        cudaGetSymbolAddress((void**)&gg, b_gg);
        cudaGetSymbolAddress((void**)&tb, b_t);
        cudaGetSymbolAddress((void**)&qh, b_qh);
        cudaGetSymbolAddress((void**)&kh, b_kh);
        cudaGetSymbolAddress((void**)&vh, b_vh);
        cudaGetSymbolAddress((void**)&k2h, b_k2h);
        cudaGetSymbolAddress((void**)&v2h, b_v2h);
        cudaGetSymbolAddress((void**)&ctx, b_ctx);
        cudaGetSymbolAddress((void**)&cw_in, b_w_in);
        cudaGetSymbolAddress((void**)&cwq1, b_wq1);
        cudaGetSymbolAddress((void**)&cwk1, b_wk1);
        cudaGetSymbolAddress((void**)&cwv1, b_wv1);
        cudaGetSymbolAddress((void**)&cwo1, b_wo1);
        cudaGetSymbolAddress((void**)&cwq2, b_wq2);
        cudaGetSymbolAddress((void**)&cwk2, b_wk2);
        cudaGetSymbolAddress((void**)&cwv2, b_wv2);
        cudaGetSymbolAddress((void**)&cwo2, b_wo2);
        cudaGetSymbolAddress((void**)&cwff1, b_wff1);
        cudaGetSymbolAddress((void**)&cwff2, b_wff2);
        cudaGetSymbolAddress((void**)&cwout, b_wout);
        cudaFuncSetAttribute(attn_bf16_kernel,
                             cudaFuncAttributeMaxDynamicSharedMemorySize,
                             ATTN_SMEM_BYTES);
        init_done = true;
    }

    const float scale = 0.15811388300841898f;  // 1/sqrt(40)
    const int CC4 = C_DIM * C_DIM / 4;

    // weight/context conversion to bf16
    cvt4_kernel<<<256, 256>>>(
        (const float4*)context, (__nv_bfloat162*)ctx,  LCTX * CTX_DIM / 4,
        (const float4*)w_in,    (__nv_bfloat162*)cw_in, CC4,
        (const float4*)wq1,     (__nv_bfloat162*)cwq1,  CC4,
        (const float4*)wk1,     (__nv_bfloat162*)cwk1,  CC4);
    cvt4_kernel<<<256, 256>>>(
        (const float4*)wv1,     (__nv_bfloat162*)cwv1,  CC4,
        (const float4*)wo1,     (__nv_bfloat162*)cwo1,  CC4,
        (const float4*)wq2,     (__nv_bfloat162*)cwq2,  CC4,
        (const float4*)wk2,     (__nv_bfloat162*)cwk2,  CTX_DIM * C_DIM / 4);
    cvt4_kernel<<<256, 256>>>(
        (const float4*)wv2,     (__nv_bfloat162*)cwv2,  CTX_DIM * C_DIM / 4,
        (const float4*)wo2,     (__nv_bfloat162*)cwo2,  CC4,
        (const float4*)wff1,    (__nv_bfloat162*)cwff1, C_DIM * 2 * FFI / 4,
        (const float4*)wff2,    (__nv_bfloat162*)cwff2, FFI * C_DIM / 4);
    cvt4_kernel<<<256, 256>>>(
        (const float4*)w_out,   (__nv_bfloat162*)cwout, CC4,
        nullptr, nullptr, 0, nullptr, nullptr, 0, nullptr, nullptr, 0);

    zero_pads_kernel<<<768, 256>>>((uint4*)qh, (uint4*)kh, (uint4*)vh,
                                   (uint4*)k2h, (uint4*)v2h);

    dim3 g320(C_DIM / 64, L_TOK / 64);           // (5, 64)
    dim3 gFF1(2 * FFI / 64, L_TOK / 64);         // (40, 64)
    dim3 gCtx(C_DIM / 64, 2);                    // (5, 2)
    dim3 attnGrid(L_TOK / AQ, HEADS);            // (32, 8)

    // GroupNorm + proj_in
    gn_stats_kernel<<<NGROUPS, 256>>>(x);
    gn_apply_kernel<<<dim3(L_TOK / 64, C_DIM / 32), 256>>>(x, gn_w, gn_b, xn);
    gemm_bf16_kernel<<<g320, 128>>>(xn, cw_in, b_in, nullptr, t, nullptr,
                                    nullptr, 0.f, 0, L_TOK, C_DIM, C_DIM, 0);

    // ---- self-attention ----
    ln_kernel<<<L_TOK / 4, 128>>>(t, ln1_w, ln1_b, hn);
    gemm_bf16_kernel<<<g320, 128>>>(hn, cwq1, nullptr, nullptr, nullptr, q,
                                    qh, scale, L_TOK, L_TOK, C_DIM, C_DIM, 0);
    gemm_bf16_kernel<<<g320, 128>>>(q, cwk1, nullptr, nullptr, nullptr, nullptr,
                                    kh, 1.f, L_TOK, L_TOK, C_DIM, C_DIM, 0);
    gemm_bf16_kernel<<<g320, 128>>>(q, cwv1, nullptr, nullptr, nullptr, nullptr,
                                    vh, 1.f, L_TOK, L_TOK, C_DIM, C_DIM, 0);
    attn_bf16_kernel<<<attnGrid, 256, ATTN_SMEM_BYTES>>>(qh, kh, vh, a,
                                                         L_TOK, L_TOK);
    gemm_bf16_kernel<<<g320, 128>>>(a, cwo1, bo1, t, t, nullptr,
                                    nullptr, 0.f, 0, L_TOK, C_DIM, C_DIM, 0);

    // ---- cross-attention ----
    ln_kernel<<<L_TOK / 4, 128>>>(t, ln2_w, ln2_b, hn);
    gemm_bf16_kernel<<<g320, 128>>>(hn, cwq2, nullptr, nullptr, nullptr, nullptr,
                                    qh, scale, L_TOK, L_TOK, C_DIM, C_DIM, 0);
    gemm_bf16_kernel<<<gCtx, 128>>>(ctx, cwk2, nullptr, nullptr, nullptr, nullptr,
                                    k2h, 1.f, LCTXP, LCTX, C_DIM, CTX_DIM, 0);
    gemm_bf16_kernel<<<gCtx, 128>>>(ctx, cwv2, nullptr, nullptr, nullptr, nullptr,
                                    v2h, 1.f, LCTXP, LCTX, C_DIM, CTX_DIM, 0);
    attn_bf16_kernel<<<attnGrid, 256, ATTN_SMEM_BYTES>>>(qh, k2h, v2h, a,
                                                         LCTX, LCTXP);
    gemm_bf16_kernel<<<g320, 128>>>(a, cwo2, bo2, t, t, nullptr,
                                    nullptr, 0.f, 0, L_TOK, C_DIM, C_DIM, 0);

    // ---- feed-forward (GEGLU) ----
    ln_kernel<<<L_TOK / 4, 128>>>(t, ln3_w, ln3_b, hn);
    gemm_bf16_kernel<<<gFF1, 128>>>(hn, cwff1, bff1, nullptr, p, nullptr,
                                    nullptr, 0.f, 0, L_TOK, 2 * FFI, C_DIM, 0);
    geglu_kernel<<<(L_TOK * FFI + 255) / 256, 256>>>(p, gg);
    gemm_bf16_kernel<<<g320, 128>>>(gg, cwff2, bff2, t, t, tb,
                                    nullptr, 0.f, 0, L_TOK, C_DIM, FFI, 0);

    // ---- proj_out (+ x residual), channel-major store ----
    gemm_bf16_kernel<<<g320, 128>>>(tb, cwout, b_out, x, out, nullptr,
                                    nullptr, 0.f, 0, L_TOK, C_DIM, C_DIM, 1);
}

// round 7
// speedup vs baseline: 2.8385x; 1.4710x over previous
#include <cuda_runtime.h>
#include <cuda_bf16.h>
#include <mma.h>
#include <math.h>
#include <cstdint>

using namespace nvcuda;

// ---------------------------------------------------------------------------
// SpatialTransformer — round 5: bf16 TC GEMMs (cp.async 2-stage) +
// FA2-style attention with register-resident softmax (mma.sync.m16n8k16).
// ---------------------------------------------------------------------------

#define L_TOK   4096
#define C_DIM   320
#define HEADS   8
#define DH      40
#define DHP     48
#define CTX_DIM 768
#define LCTX    77
#define LCTXP   128
#define FFI     1280
#define NGROUPS 32
#define CH_PER_G 10

typedef __nv_bfloat16 bf16;

// fp32 scratch
__device__ float g_t [L_TOK * C_DIM];
__device__ float g_p [L_TOK * 2 * FFI];
__device__ float g_mean[NGROUPS];
__device__ float g_rstd[NGROUPS];
// bf16 activations
__device__ bf16 b_xn[L_TOK * C_DIM];
__device__ bf16 b_hn[L_TOK * C_DIM];
__device__ bf16 b_q [L_TOK * C_DIM];
__device__ bf16 b_a [L_TOK * C_DIM];
__device__ bf16 b_gg[L_TOK * FFI];
__device__ bf16 b_t [L_TOK * C_DIM];
__device__ bf16 b_qh[HEADS * L_TOK * DHP];
__device__ bf16 b_kh[HEADS * L_TOK * DHP];
__device__ bf16 b_vh[HEADS * L_TOK * DHP];
__device__ bf16 b_k2h[HEADS * LCTXP * DHP];
__device__ bf16 b_v2h[HEADS * LCTXP * DHP];
__device__ bf16 b_ctx[LCTX * CTX_DIM];
// bf16 weights
__device__ bf16 b_w_in[C_DIM * C_DIM];
__device__ bf16 b_wq1[C_DIM * C_DIM];
__device__ bf16 b_wk1[C_DIM * C_DIM];
__device__ bf16 b_wv1[C_DIM * C_DIM];
__device__ bf16 b_wo1[C_DIM * C_DIM];
__device__ bf16 b_wq2[C_DIM * C_DIM];
__device__ bf16 b_wk2[CTX_DIM * C_DIM];
__device__ bf16 b_wv2[CTX_DIM * C_DIM];
__device__ bf16 b_wo2[C_DIM * C_DIM];
__device__ bf16 b_wff1[C_DIM * 2 * FFI];
__device__ bf16 b_wff2[FFI * C_DIM];
__device__ bf16 b_wout[C_DIM * C_DIM];

// ---------------- helpers ----------------
__device__ __forceinline__ unsigned int smem_u32(const void* p)
{ return (unsigned int)__cvta_generic_to_shared(p); }

__device__ __forceinline__ void cp16(unsigned int dst, const void* src, int sz)
{ asm volatile("cp.async.cg.shared.global [%0], [%1], 16, %2;\n"
               :: "r"(dst), "l"(src), "r"(sz)); }

__device__ __forceinline__ void cp_commit()
{ asm volatile("cp.async.commit_group;\n"); }

template<int N> __device__ __forceinline__ void cp_wait()
{ asm volatile("cp.async.wait_group %0;\n" :: "n"(N)); }

__device__ __forceinline__ float ex2(float x)
{ float r; asm("ex2.approx.f32 %0, %1;" : "=f"(r) : "f"(x)); return r; }

__device__ __forceinline__ void mma16816(float* c,
    unsigned a0, unsigned a1, unsigned a2, unsigned a3,
    unsigned b0, unsigned b1)
{
    asm volatile(
        "mma.sync.aligned.m16n8k16.row.col.f32.bf16.bf16.f32 "
        "{%0,%1,%2,%3}, {%4,%5,%6,%7}, {%8,%9}, {%0,%1,%2,%3};"
        : "+f"(c[0]), "+f"(c[1]), "+f"(c[2]), "+f"(c[3])
        : "r"(a0), "r"(a1), "r"(a2), "r"(a3), "r"(b0), "r"(b1));
}

// ---------------- fp32 -> bf16 conversion (4 jobs) ----------------
__global__ void cvt4_kernel(const float4* s0, __nv_bfloat162* d0, int n0,
                            const float4* s1, __nv_bfloat162* d1, int n1,
                            const float4* s2, __nv_bfloat162* d2, int n2,
                            const float4* s3, __nv_bfloat162* d3, int n3)
{
    int i0 = blockIdx.x * blockDim.x + threadIdx.x;
    int st = gridDim.x * blockDim.x;
    if (s0) for (int j = i0; j < n0; j += st) {
        float4 v = s0[j];
        d0[2*j]   = __floats2bfloat162_rn(v.x, v.y);
        d0[2*j+1] = __floats2bfloat162_rn(v.z, v.w);
    }
    if (s1) for (int j = i0; j < n1; j += st) {
        float4 v = s1[j];
        d1[2*j]   = __floats2bfloat162_rn(v.x, v.y);
        d1[2*j+1] = __floats2bfloat162_rn(v.z, v.w);
    }
    if (s2) for (int j = i0; j < n2; j += st) {
        float4 v = s2[j];
        d2[2*j]   = __floats2bfloat162_rn(v.x, v.y);
        d2[2*j+1] = __floats2bfloat162_rn(v.z, v.w);
    }
    if (s3) for (int j = i0; j < n3; j += st) {
        float4 v = s3[j];
        d3[2*j]   = __floats2bfloat162_rn(v.x, v.y);
        d3[2*j+1] = __floats2bfloat162_rn(v.z, v.w);
    }
}

// ---------------- zero head-major buffers ----------------
__global__ void zero_pads_kernel(uint4* a, uint4* b, uint4* c, uint4* d, uint4* e)
{
    const uint4 z = make_uint4(0, 0, 0, 0);
    int i = blockIdx.x * blockDim.x + threadIdx.x;
    int st = gridDim.x * blockDim.x;
    const int NB = HEADS * L_TOK * DHP / 8;
    const int NS = HEADS * LCTXP * DHP / 8;
    for (int j = i; j < NB; j += st) { a[j] = z; b[j] = z; c[j] = z; }
    for (int j = i; j < NS; j += st) { d[j] = z; e[j] = z; }
}

// ---------------- GroupNorm ----------------
__global__ void gn_stats_kernel(const float* __restrict__ x)
{
    int g = blockIdx.x;
    int tid = threadIdx.x;
    const int N4 = CH_PER_G * L_TOK / 4;
    float s = 0.f, ss = 0.f;
    const float4* base = (const float4*)(x + (size_t)g * CH_PER_G * L_TOK);
    for (int i = tid; i < N4; i += blockDim.x) {
        float4 v = base[i];
        s  += v.x + v.y + v.z + v.w;
        ss += v.x*v.x + v.y*v.y + v.z*v.z + v.w*v.w;
    }
    __shared__ float rs[256], rss[256];
    rs[tid] = s; rss[tid] = ss;
    __syncthreads();
    for (int o = 128; o > 0; o >>= 1) {
        if (tid < o) { rs[tid] += rs[tid + o]; rss[tid] += rss[tid + o]; }
        __syncthreads();
    }
    if (tid == 0) {
        const float NEL = (float)(CH_PER_G * L_TOK);
        float m = rs[0] / NEL;
        float var = rss[0] / NEL - m * m;
        g_mean[g] = m;
        g_rstd[g] = rsqrtf(var + 1e-6f);
    }
}

__global__ void gn_apply_kernel(const float* __restrict__ x,
                                const float* __restrict__ gw,
                                const float* __restrict__ gb,
                                bf16* __restrict__ out)
{
    __shared__ float tile[32][65];
    int hw0 = blockIdx.x * 64;
    int c0  = blockIdx.y * 32;
    #pragma unroll
    for (int p = 0; p < 8; p++) {
        int i = threadIdx.x + p * 256;
        int c = i >> 6, hw = i & 63;
        int gc = c0 + c;
        int g = gc / CH_PER_G;
        float v = (x[(size_t)gc * L_TOK + hw0 + hw] - g_mean[g]) * g_rstd[g]
                  * gw[gc] + gb[gc];
        tile[c][hw] = v;
    }
    __syncthreads();
    #pragma unroll
    for (int p = 0; p < 8; p++) {
        int i = threadIdx.x + p * 256;
        int hw = i >> 5, c = i & 31;
        out[(size_t)(hw0 + hw) * C_DIM + c0 + c] = __float2bfloat16(tile[c][hw]);
    }
}

// ---------------- LayerNorm ----------------
__global__ void ln_kernel(const float* __restrict__ in,
                          const float* __restrict__ w,
                          const float* __restrict__ b,
                          bf16* __restrict__ out)
{
    int token = blockIdx.x * (blockDim.x / 32) + (threadIdx.x >> 5);
    int lane = threadIdx.x & 31;
    if (token >= L_TOK) return;
    const float* row = in + (size_t)token * C_DIM;
    float s = 0.f, ss = 0.f;
    for (int j = lane; j < C_DIM; j += 32) {
        float v = row[j];
        s += v; ss += v * v;
    }
    #pragma unroll
    for (int o = 16; o > 0; o >>= 1) {
        s  += __shfl_xor_sync(0xffffffffu, s, o);
        ss += __shfl_xor_sync(0xffffffffu, ss, o);
    }
    float m = s / (float)C_DIM;
    float var = ss / (float)C_DIM - m * m;
    float r = rsqrtf(var + 1e-5f);
    bf16* orow = out + (size_t)token * C_DIM;
    for (int j = lane; j < C_DIM; j += 32)
        orow[j] = __float2bfloat16((row[j] - m) * r * w[j] + b[j]);
}

// ---------------- bf16 TC GEMM, 64x64x32, 2-stage cp.async ----------------
__global__ __launch_bounds__(128) void gemm_bf16_kernel(
    const bf16* __restrict__ A, const bf16* __restrict__ B,
    const float* __restrict__ bias, const float* __restrict__ res,
    float* __restrict__ Cf, bf16* __restrict__ Cbf,
    bf16* __restrict__ attnOut, float attnScale, int Lpad,
    int M, int N, int K, int transOut)
{
    struct InBuf { bf16 As[2][64][40]; bf16 Bs[2][32][72]; };
    __shared__ union SU { InBuf in; float Cs[64][68]; } sm;

    int bm = blockIdx.y * 64;
    int bn = blockIdx.x * 64;
    int tid = threadIdx.x;
    int w = tid >> 5, wm = w >> 1, wn = w & 1;

    wmma::fragment<wmma::accumulator, 16, 16, 16, float> acc[2][2];
    #pragma unroll
    for (int i = 0; i < 2; i++)
        #pragma unroll
        for (int j = 0; j < 2; j++) wmma::fill_fragment(acc[i][j], 0.f);

    auto issue = [&](int s, int k0) {
        #pragma unroll
        for (int p = 0; p < 2; p++) {
            int c = tid + p * 128;
            int row = c >> 2, ch = c & 3;
            int gm = bm + row;
            const bf16* src = A + (size_t)(gm < M ? gm : 0) * K + k0 + ch * 8;
            cp16(smem_u32(&sm.in.As[s][row][ch * 8]), src, (gm < M) ? 16 : 0);
        }
        #pragma unroll
        for (int p = 0; p < 2; p++) {
            int c = tid + p * 128;
            int row = c >> 3, ch = c & 7;
            const bf16* src = B + (size_t)(k0 + row) * N + bn + ch * 8;
            cp16(smem_u32(&sm.in.Bs[s][row][ch * 8]), src, 16);
        }
        cp_commit();
    };

    issue(0, 0);
    int nk = K / 32;
    for (int ki = 0; ki < nk; ki++) {
        int s = ki & 1;
        if (ki + 1 < nk) { issue(s ^ 1, (ki + 1) * 32); cp_wait<1>(); }
        else cp_wait<0>();
        __syncthreads();
        #pragma unroll
        for (int ks = 0; ks < 2; ks++) {
            wmma::fragment<wmma::matrix_a, 16, 16, 16, bf16, wmma::row_major> af[2];
            wmma::fragment<wmma::matrix_b, 16, 16, 16, bf16, wmma::row_major> bfr[2];
            wmma::load_matrix_sync(af[0], &sm.in.As[s][wm*32     ][ks*16], 40);
            wmma::load_matrix_sync(af[1], &sm.in.As[s][wm*32 + 16][ks*16], 40);
            wmma::load_matrix_sync(bfr[0], &sm.in.Bs[s][ks*16][wn*32     ], 72);
            wmma::load_matrix_sync(bfr[1], &sm.in.Bs[s][ks*16][wn*32 + 16], 72);
            #pragma unroll
            for (int i = 0; i < 2; i++)
                #pragma unroll
                for (int j = 0; j < 2; j++)
                    wmma::mma_sync(acc[i][j], af[i], bfr[j], acc[i][j]);
        }
        __syncthreads();
    }

    #pragma unroll
    for (int i = 0; i < 2; i++)
        #pragma unroll
        for (int j = 0; j < 2; j++)
            wmma::store_matrix_sync(&sm.Cs[wm*32 + i*16][wn*32 + j*16],
                                    acc[i][j], 68, wmma::mem_row_major);
    __syncthreads();
    #pragma unroll
    for (int p = 0; p < 32; p++) {
        int i = tid + p * 128;
        int m = i >> 6, n = i & 63;
        int gm = bm + m, gn = bn + n;
        if (gm >= M) continue;
        float v = sm.Cs[m][n];
        if (bias) v += bias[gn];
        if (Cf) {
            size_t idx = transOut ? ((size_t)gn * M + gm) : ((size_t)gm * N + gn);
            if (res) v += res[idx];
            Cf[idx] = v;
        }
        if (Cbf) Cbf[(size_t)gm * N + gn] = __float2bfloat16(v);
        if (attnOut) {
            int h = gn & 7, j = gn >> 3;
            attnOut[((size_t)h * Lpad + gm) * DHP + j] =
                __float2bfloat16(v * attnScale);
        }
    }
}

// ---------------- FA2 attention: register softmax, mma.sync ----------------
// 128 queries/block, 8 warps (16 rows each), 64-key tiles, cp.async dbl-buf.
// qh pre-scaled by (1/sqrt(dh))*log2(e); softmax in exp2 domain.
__global__ __launch_bounds__(256) void attn_reg_kernel(
    const bf16* __restrict__ qh, const bf16* __restrict__ kh,
    const bf16* __restrict__ vh, bf16* __restrict__ Obf,
    int Lk, int Lpad)
{
    __shared__ bf16 sK[2][64 * 48];
    __shared__ bf16 sV[2][64 * 48];
    __shared__ bf16 sQ[128 * 48];

    int h = blockIdx.y;
    int qbase = blockIdx.x * 128;
    int tid = threadIdx.x, w = tid >> 5, lane = tid & 31;
    int r0 = lane >> 2, cq = (lane & 3) * 2;

    auto load_kv = [&](int s, int k0) {
        const bf16* kp = kh + ((size_t)h * Lpad + k0) * DHP;
        const bf16* vp = vh + ((size_t)h * Lpad + k0) * DHP;
        #pragma unroll
        for (int p = 0; p < 3; p++) {
            int c = tid + p * 256;
            if (c < 384) cp16(smem_u32(&sK[s][c * 8]), kp + c * 8, 16);
            else         cp16(smem_u32(&sV[s][(c - 384) * 8]),
                              vp + (c - 384) * 8, 16);
        }
        cp_commit();
    };
    load_kv(0, 0);

    // stage Q
    {
        const uint4* src = (const uint4*)(qh + ((size_t)h * L_TOK + qbase) * DHP);
        uint4* dst = (uint4*)sQ;
        #pragma unroll
        for (int p = 0; p < 3; p++) dst[tid + p * 256] = src[tid + p * 256];
    }
    __syncthreads();

    // Q fragments: A operand m16n8k16, 3 k-steps over dh=48
    unsigned qa[3][4];
    {
        const bf16* qrow = sQ + (w * 16 + r0) * 48;
        #pragma unroll
        for (int kd = 0; kd < 3; kd++) {
            qa[kd][0] = *(const unsigned*)(qrow + kd * 16 + cq);
            qa[kd][1] = *(const unsigned*)(qrow + 8 * 48 + kd * 16 + cq);
            qa[kd][2] = *(const unsigned*)(qrow + kd * 16 + 8 + cq);
            qa[kd][3] = *(const unsigned*)(qrow + 8 * 48 + kd * 16 + 8 + cq);
        }
    }

    float O[6][4] = {};
    float m0 = -1e30f, m1 = -1e30f, l0 = 0.f, l1 = 0.f;

    int ntiles = (Lk + 63) / 64;
    for (int ti = 0; ti < ntiles; ti++) {
        int s = ti & 1, k0 = ti * 64;
        if (ti + 1 < ntiles) { load_kv(s ^ 1, k0 + 64); cp_wait<1>(); }
        else cp_wait<0>();
        __syncthreads();

        // S = Q K^T : 16 rows x 64 keys per warp, in registers
        float S[8][4];
        #pragma unroll
        for (int j = 0; j < 8; j++)
            S[j][0] = S[j][1] = S[j][2] = S[j][3] = 0.f;
        #pragma unroll
        for (int kd = 0; kd < 3; kd++)
            #pragma unroll
            for (int j = 0; j < 8; j++) {
                const bf16* kb = &sK[s][(j * 8 + r0) * 48 + kd * 16];
                unsigned b0 = *(const unsigned*)(kb + cq);
                unsigned b1 = *(const unsigned*)(kb + 8 + cq);
                mma16816(S[j], qa[kd][0], qa[kd][1], qa[kd][2], qa[kd][3], b0, b1);
            }

        if (k0 + 64 > Lk) {
            #pragma unroll
            for (int j = 0; j < 8; j++) {
                int col = k0 + j * 8 + cq;
                if (col >= Lk)     { S[j][0] = -1e30f; S[j][2] = -1e30f; }
                if (col + 1 >= Lk) { S[j][1] = -1e30f; S[j][3] = -1e30f; }
            }
        }

        // row max across 16 values + quad shuffle
        float mx0 = -1e30f, mx1 = -1e30f;
        #pragma unroll
        for (int j = 0; j < 8; j++) {
            mx0 = fmaxf(mx0, fmaxf(S[j][0], S[j][1]));
            mx1 = fmaxf(mx1, fmaxf(S[j][2], S[j][3]));
        }
        mx0 = fmaxf(mx0, __shfl_xor_sync(0xffffffffu, mx0, 1));
        mx0 = fmaxf(mx0, __shfl_xor_sync(0xffffffffu, mx0, 2));
        mx1 = fmaxf(mx1, __shfl_xor_sync(0xffffffffu, mx1, 1));
        mx1 = fmaxf(mx1, __shfl_xor_sync(0xffffffffu, mx1, 2));

        float mn0 = fmaxf(m0, mx0), mn1 = fmaxf(m1, mx1);
        float corr0 = ex2(m0 - mn0), corr1 = ex2(m1 - mn1);
        m0 = mn0; m1 = mn1;

        // P = 2^(S-m), packed straight into A fragments
        unsigned P[8][2];
        float sum0 = 0.f, sum1 = 0.f;
        #pragma unroll
        for (int j = 0; j < 8; j++) {
            float p0 = ex2(S[j][0] - mn0), p1 = ex2(S[j][1] - mn0);
            float p2 = ex2(S[j][2] - mn1), p3 = ex2(S[j][3] - mn1);
            sum0 += p0 + p1; sum1 += p2 + p3;
            __nv_bfloat162 u0 = __floats2bfloat162_rn(p0, p1);
            __nv_bfloat162 u1 = __floats2bfloat162_rn(p2, p3);
            P[j][0] = *(unsigned*)&u0;
            P[j][1] = *(unsigned*)&u1;
        }
        sum0 += __shfl_xor_sync(0xffffffffu, sum0, 1);
        sum0 += __shfl_xor_sync(0xffffffffu, sum0, 2);
        sum1 += __shfl_xor_sync(0xffffffffu, sum1, 1);
        sum1 += __shfl_xor_sync(0xffffffffu, sum1, 2);
        l0 = l0 * corr0 + sum0;
        l1 = l1 * corr1 + sum1;

        #pragma unroll
        for (int jd = 0; jd < 6; jd++) {
            O[jd][0] *= corr0; O[jd][1] *= corr0;
            O[jd][2] *= corr1; O[jd][3] *= corr1;
        }

        // O += P V  (V fragments via ldmatrix.x4.trans)
        #pragma unroll
        for (int t = 0; t < 4; t++) {
            #pragma unroll
            for (int p2 = 0; p2 < 3; p2++) {
                int g = lane >> 3;
                unsigned addr = smem_u32(
                    &sV[s][(t * 16 + (g & 1) * 8 + (lane & 7)) * 48
                           + p2 * 16 + (g >> 1) * 8]);
                unsigned v0, v1, v2, v3;
                asm volatile(
                    "ldmatrix.sync.aligned.m8n8.x4.trans.shared.b16 "
                    "{%0,%1,%2,%3}, [%4];"
                    : "=r"(v0), "=r"(v1), "=r"(v2), "=r"(v3) : "r"(addr));
                mma16816(O[2*p2],   P[2*t][0], P[2*t][1],
                                    P[2*t+1][0], P[2*t+1][1], v0, v1);
                mma16816(O[2*p2+1], P[2*t][0], P[2*t][1],
                                    P[2*t+1][0], P[2*t+1][1], v2, v3);
            }
        }
        __syncthreads();
    }

    float il0 = 1.f / l0, il1 = 1.f / l1;
    int tok = qbase + w * 16 + r0;
    #pragma unroll
    for (int jd = 0; jd < 5; jd++) {      // dh tiles 0..4 cover cols 0..39
        int col = jd * 8 + cq;
        __nv_bfloat162 o0 = __floats2bfloat162_rn(O[jd][0] * il0, O[jd][1] * il0);
        __nv_bfloat162 o1 = __floats2bfloat162_rn(O[jd][2] * il1, O[jd][3] * il1);
        *(__nv_bfloat162*)(Obf + (size_t)tok * C_DIM + h * DH + col) = o0;
        *(__nv_bfloat162*)(Obf + (size_t)(tok + 8) * C_DIM + h * DH + col) = o1;
    }
}

// ---------------- GEGLU ----------------
__global__ void geglu_kernel(const float* __restrict__ p, bf16* __restrict__ g)
{
    int idx = blockIdx.x * blockDim.x + threadIdx.x;
    if (idx >= L_TOK * FFI) return;
    int l = idx / FFI, i = idx - l * FFI;
    float a = p[(size_t)l * 2 * FFI + i];
    float x = p[(size_t)l * 2 * FFI + FFI + i];
    float ge = 0.5f * x * (1.f + erff(x * 0.70710678118654752f));
    g[idx] = __float2bfloat16(a * ge);
}

// ---------------------------------------------------------------------------
extern "C" void kernel_launch(void* const* d_in, const int* in_sizes, int n_in,
                              void* d_out, int out_size)
{
    const float* x       = (const float*)d_in[0];
    const float* context = (const float*)d_in[1];
    const float* gn_w    = (const float*)d_in[2];
    const float* gn_b    = (const float*)d_in[3];
    const float* w_in    = (const float*)d_in[4];
    const float* b_in    = (const float*)d_in[5];
    const float* ln1_w   = (const float*)d_in[6];
    const float* ln1_b   = (const float*)d_in[7];
    const float* wq1     = (const float*)d_in[8];
    const float* wk1     = (const float*)d_in[9];
    const float* wv1     = (const float*)d_in[10];
    const float* wo1     = (const float*)d_in[11];
    const float* bo1     = (const float*)d_in[12];
    const float* ln2_w   = (const float*)d_in[13];
    const float* ln2_b   = (const float*)d_in[14];
    const float* wq2     = (const float*)d_in[15];
    const float* wk2     = (const float*)d_in[16];
    const float* wv2     = (const float*)d_in[17];
    const float* wo2     = (const float*)d_in[18];
    const float* bo2     = (const float*)d_in[19];
    const float* ln3_w   = (const float*)d_in[20];
    const float* ln3_b   = (const float*)d_in[21];
    const float* wff1    = (const float*)d_in[22];
    const float* bff1    = (const float*)d_in[23];
    const float* wff2    = (const float*)d_in[24];
    const float* bff2    = (const float*)d_in[25];
    const float* w_out   = (const float*)d_in[26];
    const float* b_out   = (const float*)d_in[27];
    float* out = (float*)d_out;

    static float *t = nullptr, *p;
    static bf16 *xn, *hn, *q, *a, *gg, *tb, *qh, *kh, *vh, *k2h, *v2h, *ctx;
    static bf16 *cw_in, *cwq1, *cwk1, *cwv1, *cwo1, *cwq2, *cwk2, *cwv2, *cwo2,
                *cwff1, *cwff2, *cwout;
    static bool init_done = false;
    if (!init_done) {
        cudaGetSymbolAddress((void**)&t,  g_t);
        cudaGetSymbolAddress((void**)&p,  g_p);
        cudaGetSymbolAddress((void**)&xn, b_xn);
        cudaGetSymbolAddress((void**)&hn, b_hn);
        cudaGetSymbolAddress((void**)&q,  b_q);
        cudaGetSymbolAddress((void**)&a,  b_a);
        cudaGetSymbolAddress((void**)&gg, b_gg);
        cudaGetSymbolAddress((void**)&tb, b_t);
        cudaGetSymbolAddress((void**)&qh, b_qh);
        cudaGetSymbolAddress((void**)&kh, b_kh);
        cudaGetSymbolAddress((void**)&vh, b_vh);
        cudaGetSymbolAddress((void**)&k2h, b_k2h);
        cudaGetSymbolAddress((void**)&v2h, b_v2h);
        cudaGetSymbolAddress((void**)&ctx, b_ctx);
        cudaGetSymbolAddress((void**)&cw_in, b_w_in);
        cudaGetSymbolAddress((void**)&cwq1, b_wq1);
        cudaGetSymbolAddress((void**)&cwk1, b_wk1);
        cudaGetSymbolAddress((void**)&cwv1, b_wv1);
        cudaGetSymbolAddress((void**)&cwo1, b_wo1);
        cudaGetSymbolAddress((void**)&cwq2, b_wq2);
        cudaGetSymbolAddress((void**)&cwk2, b_wk2);
        cudaGetSymbolAddress((void**)&cwv2, b_wv2);
        cudaGetSymbolAddress((void**)&cwo2, b_wo2);
        cudaGetSymbolAddress((void**)&cwff1, b_wff1);
        cudaGetSymbolAddress((void**)&cwff2, b_wff2);
        cudaGetSymbolAddress((void**)&cwout, b_wout);
        init_done = true;
    }

    // 1/sqrt(40) * log2(e): softmax computed in exp2 domain
    const float scaleQ = 0.15811388300841898f * 1.4426950408889634f;
    const int CC4 = C_DIM * C_DIM / 4;

    cvt4_kernel<<<256, 256>>>(
        (const float4*)context, (__nv_bfloat162*)ctx,  LCTX * CTX_DIM / 4,
        (const float4*)w_in,    (__nv_bfloat162*)cw_in, CC4,
        (const float4*)wq1,     (__nv_bfloat162*)cwq1,  CC4,
        (const float4*)wk1,     (__nv_bfloat162*)cwk1,  CC4);
    cvt4_kernel<<<256, 256>>>(
        (const float4*)wv1,     (__nv_bfloat162*)cwv1,  CC4,
        (const float4*)wo1,     (__nv_bfloat162*)cwo1,  CC4,
        (const float4*)wq2,     (__nv_bfloat162*)cwq2,  CC4,
        (const float4*)wk2,     (__nv_bfloat162*)cwk2,  CTX_DIM * C_DIM / 4);
    cvt4_kernel<<<256, 256>>>(
        (const float4*)wv2,     (__nv_bfloat162*)cwv2,  CTX_DIM * C_DIM / 4,
        (const float4*)wo2,     (__nv_bfloat162*)cwo2,  CC4,
        (const float4*)wff1,    (__nv_bfloat162*)cwff1, C_DIM * 2 * FFI / 4,
        (const float4*)wff2,    (__nv_bfloat162*)cwff2, FFI * C_DIM / 4);
    cvt4_kernel<<<256, 256>>>(
        (const float4*)w_out,   (__nv_bfloat162*)cwout, CC4,
        nullptr, nullptr, 0, nullptr, nullptr, 0, nullptr, nullptr, 0);

    zero_pads_kernel<<<768, 256>>>((uint4*)qh, (uint4*)kh, (uint4*)vh,
                                   (uint4*)k2h, (uint4*)v2h);

    dim3 g320(C_DIM / 64, L_TOK / 64);
    dim3 gFF1(2 * FFI / 64, L_TOK / 64);
    dim3 gCtx(C_DIM / 64, 2);
    dim3 attnGrid(L_TOK / 128, HEADS);           // (32, 8)

    gn_stats_kernel<<<NGROUPS, 256>>>(x);
    gn_apply_kernel<<<dim3(L_TOK / 64, C_DIM / 32), 256>>>(x, gn_w, gn_b, xn);
    gemm_bf16_kernel<<<g320, 128>>>(xn, cw_in, b_in, nullptr, t, nullptr,
                                    nullptr, 0.f, 0, L_TOK, C_DIM, C_DIM, 0);

    // ---- self-attention ----
    ln_kernel<<<L_TOK / 4, 128>>>(t, ln1_w, ln1_b, hn);
    gemm_bf16_kernel<<<g320, 128>>>(hn, cwq1, nullptr, nullptr, nullptr, q,
                                    qh, scaleQ, L_TOK, L_TOK, C_DIM, C_DIM, 0);
    gemm_bf16_kernel<<<g320, 128>>>(q, cwk1, nullptr, nullptr, nullptr, nullptr,
                                    kh, 1.f, L_TOK, L_TOK, C_DIM, C_DIM, 0);
    gemm_bf16_kernel<<<g320, 128>>>(q, cwv1, nullptr, nullptr, nullptr, nullptr,
                                    vh, 1.f, L_TOK, L_TOK, C_DIM, C_DIM, 0);
    attn_reg_kernel<<<attnGrid, 256>>>(qh, kh, vh, a, L_TOK, L_TOK);
    gemm_bf16_kernel<<<g320, 128>>>(a, cwo1, bo1, t, t, nullptr,
                                    nullptr, 0.f, 0, L_TOK, C_DIM, C_DIM, 0);

    // ---- cross-attention ----
    ln_kernel<<<L_TOK / 4, 128>>>(t, ln2_w, ln2_b, hn);
    gemm_bf16_kernel<<<g320, 128>>>(hn, cwq2, nullptr, nullptr, nullptr, nullptr,
                                    qh, scaleQ, L_TOK, L_TOK, C_DIM, C_DIM, 0);
    gemm_bf16_kernel<<<gCtx, 128>>>(ctx, cwk2, nullptr, nullptr, nullptr, nullptr,
                                    k2h, 1.f, LCTXP, LCTX, C_DIM, CTX_DIM, 0);
    gemm_bf16_kernel<<<gCtx, 128>>>(ctx, cwv2, nullptr, nullptr, nullptr, nullptr,
                                    v2h, 1.f, LCTXP, LCTX, C_DIM, CTX_DIM, 0);
    attn_reg_kernel<<<attnGrid, 256>>>(qh, k2h, v2h, a, LCTX, LCTXP);
    gemm_bf16_kernel<<<g320, 128>>>(a, cwo2, bo2, t, t, nullptr,
                                    nullptr, 0.f, 0, L_TOK, C_DIM, C_DIM, 0);

    // ---- feed-forward (GEGLU) ----
    ln_kernel<<<L_TOK / 4, 128>>>(t, ln3_w, ln3_b, hn);
    gemm_bf16_kernel<<<gFF1, 128>>>(hn, cwff1, bff1, nullptr, p, nullptr,
                                    nullptr, 0.f, 0, L_TOK, 2 * FFI, C_DIM, 0);
    geglu_kernel<<<(L_TOK * FFI + 255) / 256, 256>>>(p, gg);
    gemm_bf16_kernel<<<g320, 128>>>(gg, cwff2, bff2, t, t, tb,
                                    nullptr, 0.f, 0, L_TOK, C_DIM, FFI, 0);

    // ---- proj_out (+ x residual), channel-major store ----
    gemm_bf16_kernel<<<g320, 128>>>(tb, cwout, b_out, x, out, nullptr,
                                    nullptr, 0.f, 0, L_TOK, C_DIM, C_DIM, 1);
}

// round 8
// speedup vs baseline: 4.2973x; 1.5140x over previous
#include <cuda_runtime.h>
#include <cuda_bf16.h>
#include <mma.h>
#include <math.h>
#include <cstdint>

using namespace nvcuda;

// ---------------------------------------------------------------------------
// SpatialTransformer — round 7: 128x64 GEMM tiles, fused GEGLU epilogue,
// merged K|V projection GEMMs. FA2 attention unchanged from round 5.
// ---------------------------------------------------------------------------

#define L_TOK   4096
#define C_DIM   320
#define HEADS   8
#define DH      40
#define DHP     48
#define CTX_DIM 768
#define LCTX    77
#define LCTXP   128
#define FFI     1280
#define NGROUPS 32
#define CH_PER_G 10

typedef __nv_bfloat16 bf16;

// fp32 scratch
__device__ float g_t [L_TOK * C_DIM];
__device__ float g_mean[NGROUPS];
__device__ float g_rstd[NGROUPS];
// bf16 activations
__device__ bf16 b_xn[L_TOK * C_DIM];
__device__ bf16 b_hn[L_TOK * C_DIM];
__device__ bf16 b_q [L_TOK * C_DIM];
__device__ bf16 b_a [L_TOK * C_DIM];
__device__ bf16 b_gg[L_TOK * FFI];
__device__ bf16 b_t [L_TOK * C_DIM];
__device__ bf16 b_qh[HEADS * L_TOK * DHP];
__device__ bf16 b_kh[HEADS * L_TOK * DHP];
__device__ bf16 b_vh[HEADS * L_TOK * DHP];
__device__ bf16 b_k2h[HEADS * LCTXP * DHP];
__device__ bf16 b_v2h[HEADS * LCTXP * DHP];
__device__ bf16 b_ctx[LCTX * CTX_DIM];
// bf16 weights
__device__ bf16 b_w_in[C_DIM * C_DIM];
__device__ bf16 b_wq1[C_DIM * C_DIM];
__device__ bf16 b_wkv1[C_DIM * 2 * C_DIM];     // [320][640] = wk1 | wv1
__device__ bf16 b_wo1[C_DIM * C_DIM];
__device__ bf16 b_wq2[C_DIM * C_DIM];
__device__ bf16 b_wkv2[CTX_DIM * 2 * C_DIM];   // [768][640] = wk2 | wv2
__device__ bf16 b_wo2[C_DIM * C_DIM];
__device__ bf16 b_wff1[C_DIM * 2 * FFI];
__device__ bf16 b_wff2[FFI * C_DIM];
__device__ bf16 b_wout[C_DIM * C_DIM];

// ---------------- helpers ----------------
__device__ __forceinline__ unsigned int smem_u32(const void* p)
{ return (unsigned int)__cvta_generic_to_shared(p); }

__device__ __forceinline__ void cp16(unsigned int dst, const void* src, int sz)
{ asm volatile("cp.async.cg.shared.global [%0], [%1], 16, %2;\n"
               :: "r"(dst), "l"(src), "r"(sz)); }

__device__ __forceinline__ void cp_commit()
{ asm volatile("cp.async.commit_group;\n"); }

template<int N> __device__ __forceinline__ void cp_wait()
{ asm volatile("cp.async.wait_group %0;\n" :: "n"(N)); }

__device__ __forceinline__ float ex2(float x)
{ float r; asm("ex2.approx.f32 %0, %1;" : "=f"(r) : "f"(x)); return r; }

__device__ __forceinline__ void mma16816(float* c,
    unsigned a0, unsigned a1, unsigned a2, unsigned a3,
    unsigned b0, unsigned b1)
{
    asm volatile(
        "mma.sync.aligned.m16n8k16.row.col.f32.bf16.bf16.f32 "
        "{%0,%1,%2,%3}, {%4,%5,%6,%7}, {%8,%9}, {%0,%1,%2,%3};"
        : "+f"(c[0]), "+f"(c[1]), "+f"(c[2]), "+f"(c[3])
        : "r"(a0), "r"(a1), "r"(a2), "r"(a3), "r"(b0), "r"(b1));
}

// ---------------- fp32 -> bf16 conversion (4 jobs) ----------------
__global__ void cvt4_kernel(const float4* s0, __nv_bfloat162* d0, int n0,
                            const float4* s1, __nv_bfloat162* d1, int n1,
                            const float4* s2, __nv_bfloat162* d2, int n2,
                            const float4* s3, __nv_bfloat162* d3, int n3)
{
    int i0 = blockIdx.x * blockDim.x + threadIdx.x;
    int st = gridDim.x * blockDim.x;
    if (s0) for (int j = i0; j < n0; j += st) {
        float4 v = s0[j];
        d0[2*j]   = __floats2bfloat162_rn(v.x, v.y);
        d0[2*j+1] = __floats2bfloat162_rn(v.z, v.w);
    }
    if (s1) for (int j = i0; j < n1; j += st) {
        float4 v = s1[j];
        d1[2*j]   = __floats2bfloat162_rn(v.x, v.y);
        d1[2*j+1] = __floats2bfloat162_rn(v.z, v.w);
    }
    if (s2) for (int j = i0; j < n2; j += st) {
        float4 v = s2[j];
        d2[2*j]   = __floats2bfloat162_rn(v.x, v.y);
        d2[2*j+1] = __floats2bfloat162_rn(v.z, v.w);
    }
    if (s3) for (int j = i0; j < n3; j += st) {
        float4 v = s3[j];
        d3[2*j]   = __floats2bfloat162_rn(v.x, v.y);
        d3[2*j+1] = __floats2bfloat162_rn(v.z, v.w);
    }
}

// merge wk|wv (fp32, KxC each) into dst bf16 [K][2C]
__global__ void merge_kv_kernel(const float4* wk, const float4* wv,
                                __nv_bfloat162* dst, int K)
{
    int n4 = K * C_DIM / 4;
    int i = blockIdx.x * blockDim.x + threadIdx.x;
    int st = gridDim.x * blockDim.x;
    for (int j = i; j < n4; j += st) {
        int k = j / (C_DIM / 4), c4 = j % (C_DIM / 4);
        float4 a = wk[j];
        float4 b = wv[j];
        __nv_bfloat162* row = dst + k * C_DIM;     // 2C bf16 = C bf162
        row[c4 * 2]     = __floats2bfloat162_rn(a.x, a.y);
        row[c4 * 2 + 1] = __floats2bfloat162_rn(a.z, a.w);
        row[C_DIM / 2 + c4 * 2]     = __floats2bfloat162_rn(b.x, b.y);
        row[C_DIM / 2 + c4 * 2 + 1] = __floats2bfloat162_rn(b.z, b.w);
    }
}

// ---------------- zero head-major buffers ----------------
__global__ void zero_pads_kernel(uint4* a, uint4* b, uint4* c, uint4* d, uint4* e)
{
    const uint4 z = make_uint4(0, 0, 0, 0);
    int i = blockIdx.x * blockDim.x + threadIdx.x;
    int st = gridDim.x * blockDim.x;
    const int NB = HEADS * L_TOK * DHP / 8;
    const int NS = HEADS * LCTXP * DHP / 8;
    for (int j = i; j < NB; j += st) { a[j] = z; b[j] = z; c[j] = z; }
    for (int j = i; j < NS; j += st) { d[j] = z; e[j] = z; }
}

// ---------------- GroupNorm ----------------
__global__ void gn_stats_kernel(const float* __restrict__ x)
{
    int g = blockIdx.x;
    int tid = threadIdx.x;
    const int N4 = CH_PER_G * L_TOK / 4;
    float s = 0.f, ss = 0.f;
    const float4* base = (const float4*)(x + (size_t)g * CH_PER_G * L_TOK);
    for (int i = tid; i < N4; i += blockDim.x) {
        float4 v = base[i];
        s  += v.x + v.y + v.z + v.w;
        ss += v.x*v.x + v.y*v.y + v.z*v.z + v.w*v.w;
    }
    __shared__ float rs[256], rss[256];
    rs[tid] = s; rss[tid] = ss;
    __syncthreads();
    for (int o = 128; o > 0; o >>= 1) {
        if (tid < o) { rs[tid] += rs[tid + o]; rss[tid] += rss[tid + o]; }
        __syncthreads();
    }
    if (tid == 0) {
        const float NEL = (float)(CH_PER_G * L_TOK);
        float m = rs[0] / NEL;
        float var = rss[0] / NEL - m * m;
        g_mean[g] = m;
        g_rstd[g] = rsqrtf(var + 1e-6f);
    }
}

__global__ void gn_apply_kernel(const float* __restrict__ x,
                                const float* __restrict__ gw,
                                const float* __restrict__ gb,
                                bf16* __restrict__ out)
{
    __shared__ float tile[32][65];
    int hw0 = blockIdx.x * 64;
    int c0  = blockIdx.y * 32;
    #pragma unroll
    for (int p = 0; p < 8; p++) {
        int i = threadIdx.x + p * 256;
        int c = i >> 6, hw = i & 63;
        int gc = c0 + c;
        int g = gc / CH_PER_G;
        float v = (x[(size_t)gc * L_TOK + hw0 + hw] - g_mean[g]) * g_rstd[g]
                  * gw[gc] + gb[gc];
        tile[c][hw] = v;
    }
    __syncthreads();
    #pragma unroll
    for (int p = 0; p < 8; p++) {
        int i = threadIdx.x + p * 256;
        int hw = i >> 5, c = i & 31;
        out[(size_t)(hw0 + hw) * C_DIM + c0 + c] = __float2bfloat16(tile[c][hw]);
    }
}

// ---------------- LayerNorm ----------------
__global__ void ln_kernel(const float* __restrict__ in,
                          const float* __restrict__ w,
                          const float* __restrict__ b,
                          bf16* __restrict__ out)
{
    int token = blockIdx.x * (blockDim.x / 32) + (threadIdx.x >> 5);
    int lane = threadIdx.x & 31;
    if (token >= L_TOK) return;
    const float* row = in + (size_t)token * C_DIM;
    float s = 0.f, ss = 0.f;
    for (int j = lane; j < C_DIM; j += 32) {
        float v = row[j];
        s += v; ss += v * v;
    }
    #pragma unroll
    for (int o = 16; o > 0; o >>= 1) {
        s  += __shfl_xor_sync(0xffffffffu, s, o);
        ss += __shfl_xor_sync(0xffffffffu, ss, o);
    }
    float m = s / (float)C_DIM;
    float var = ss / (float)C_DIM - m * m;
    float r = rsqrtf(var + 1e-5f);
    bf16* orow = out + (size_t)token * C_DIM;
    for (int j = lane; j < C_DIM; j += 32)
        orow[j] = __float2bfloat16((row[j] - m) * r * w[j] + b[j]);
}

// ---------------- bf16 TC GEMM, 128x64 tile, 256 thr, 2-stage cp.async -----
// Modes:
//  - normal: C[m,n] over N cols; optional bias/res/Cf/Cbf; transOut
//  - kv (attnK&&attnV, N=640): head-major store; cols<320 -> attnK else attnV
//  - geglu (ggOut, B has 2*FFI cols): dual-acc a/gate tiles, writes bf16 gg
__global__ __launch_bounds__(256) void gemm_bf16_kernel(
    const bf16* __restrict__ A, const bf16* __restrict__ B,
    const float* __restrict__ bias, const float* __restrict__ res,
    float* __restrict__ Cf, bf16* __restrict__ Cbf,
    bf16* __restrict__ attnK, bf16* __restrict__ attnV,
    float attnScale, int Lpad,
    bf16* __restrict__ ggOut,
    int M, int N, int K, int transOut)
{
    struct InBuf { bf16 As[2][128][40]; bf16 Bs[2][2][32][72]; };
    __shared__ union SU { InBuf in; float Cs[128][68]; } sm;

    const bool dual = (ggOut != nullptr);
    int bm = blockIdx.y * 128;
    int bn = blockIdx.x * 64;
    int tid = threadIdx.x;
    int w = tid >> 5, wm = w >> 1, wn = w & 1;

    wmma::fragment<wmma::accumulator, 16, 16, 16, float> acc[2][2], acc2[2][2];
    #pragma unroll
    for (int i = 0; i < 2; i++)
        #pragma unroll
        for (int j = 0; j < 2; j++) {
            wmma::fill_fragment(acc[i][j], 0.f);
            wmma::fill_fragment(acc2[i][j], 0.f);
        }

    auto issue = [&](int s, int k0) {
        #pragma unroll
        for (int p = 0; p < 2; p++) {
            int c = tid + p * 256;
            int row = c >> 2, ch = c & 3;
            int gm = bm + row;
            const bf16* src = A + (size_t)(gm < M ? gm : 0) * K + k0 + ch * 8;
            cp16(smem_u32(&sm.in.As[s][row][ch * 8]), src, (gm < M) ? 16 : 0);
        }
        {
            int row = tid >> 3, ch = tid & 7;
            const bf16* src = B + (size_t)(k0 + row) * N + bn + ch * 8;
            cp16(smem_u32(&sm.in.Bs[s][0][row][ch * 8]), src, 16);
            if (dual) {
                const bf16* src2 = src + FFI;
                cp16(smem_u32(&sm.in.Bs[s][1][row][ch * 8]), src2, 16);
            }
        }
        cp_commit();
    };

    issue(0, 0);
    int nk = K / 32;
    for (int ki = 0; ki < nk; ki++) {
        int s = ki & 1;
        if (ki + 1 < nk) { issue(s ^ 1, (ki + 1) * 32); cp_wait<1>(); }
        else cp_wait<0>();
        __syncthreads();
        #pragma unroll
        for (int ks = 0; ks < 2; ks++) {
            wmma::fragment<wmma::matrix_a, 16, 16, 16, bf16, wmma::row_major> af[2];
            wmma::fragment<wmma::matrix_b, 16, 16, 16, bf16, wmma::row_major> bfr[2];
            wmma::load_matrix_sync(af[0], &sm.in.As[s][wm*32     ][ks*16], 40);
            wmma::load_matrix_sync(af[1], &sm.in.As[s][wm*32 + 16][ks*16], 40);
            wmma::load_matrix_sync(bfr[0], &sm.in.Bs[s][0][ks*16][wn*32     ], 72);
            wmma::load_matrix_sync(bfr[1], &sm.in.Bs[s][0][ks*16][wn*32 + 16], 72);
            #pragma unroll
            for (int i = 0; i < 2; i++)
                #pragma unroll
                for (int j = 0; j < 2; j++)
                    wmma::mma_sync(acc[i][j], af[i], bfr[j], acc[i][j]);
            if (dual) {
                wmma::load_matrix_sync(bfr[0], &sm.in.Bs[s][1][ks*16][wn*32     ], 72);
                wmma::load_matrix_sync(bfr[1], &sm.in.Bs[s][1][ks*16][wn*32 + 16], 72);
                #pragma unroll
                for (int i = 0; i < 2; i++)
                    #pragma unroll
                    for (int j = 0; j < 2; j++)
                        wmma::mma_sync(acc2[i][j], af[i], bfr[j], acc2[i][j]);
            }
        }
        __syncthreads();
    }

    // ---- epilogue ----
    #pragma unroll
    for (int i = 0; i < 2; i++)
        #pragma unroll
        for (int j = 0; j < 2; j++)
            wmma::store_matrix_sync(&sm.Cs[wm*32 + i*16][wn*32 + j*16],
                                    acc[i][j], 68, wmma::mem_row_major);
    __syncthreads();

    if (dual) {
        // stage 'a' values into registers, then overwrite Cs with gate tile
        float rA[32];
        #pragma unroll
        for (int p = 0; p < 32; p++) {
            int i = tid + p * 256;
            rA[p] = sm.Cs[i >> 6][i & 63];
        }
        __syncthreads();
        #pragma unroll
        for (int i = 0; i < 2; i++)
            #pragma unroll
            for (int j = 0; j < 2; j++)
                wmma::store_matrix_sync(&sm.Cs[wm*32 + i*16][wn*32 + j*16],
                                        acc2[i][j], 68, wmma::mem_row_major);
        __syncthreads();
        #pragma unroll
        for (int p = 0; p < 32; p++) {
            int i = tid + p * 256;
            int m = i >> 6, n = i & 63;
            int gm = bm + m, gn = bn + n;
            float av = rA[p] + bias[gn];
            float gv = sm.Cs[m][n] + bias[gn + FFI];
            float ge = 0.5f * gv * (1.f + erff(gv * 0.70710678118654752f));
            ggOut[(size_t)gm * FFI + gn] = __float2bfloat16(av * ge);
        }
        return;
    }

    #pragma unroll
    for (int p = 0; p < 32; p++) {
        int i = tid + p * 256;
        int m = i >> 6, n = i & 63;
        int gm = bm + m, gn = bn + n;
        if (gm >= M) continue;
        float v = sm.Cs[m][n];
        if (bias) v += bias[gn];
        if (Cf) {
            size_t idx = transOut ? ((size_t)gn * M + gm) : ((size_t)gm * N + gn);
            if (res) v += res[idx];
            Cf[idx] = v;
        }
        if (Cbf) Cbf[(size_t)gm * N + gn] = __float2bfloat16(v);
        if (attnK) {
            bf16* dst;
            int cc;
            if (gn < C_DIM) { dst = attnK; cc = gn; }
            else            { dst = attnV; cc = gn - C_DIM; }
            if (attnV == nullptr) { dst = attnK; cc = gn; }   // q-mode (N=320)
            int h = cc & 7, j = cc >> 3;
            dst[((size_t)h * Lpad + gm) * DHP + j] =
                __float2bfloat16(v * attnScale);
        }
    }
}

// ---------------- FA2 attention (unchanged from round 5) ----------------
__global__ __launch_bounds__(256) void attn_reg_kernel(
    const bf16* __restrict__ qh, const bf16* __restrict__ kh,
    const bf16* __restrict__ vh, bf16* __restrict__ Obf,
    int Lk, int Lpad)
{
    __shared__ bf16 sK[2][64 * 48];
    __shared__ bf16 sV[2][64 * 48];
    __shared__ bf16 sQ[128 * 48];

    int h = blockIdx.y;
    int qbase = blockIdx.x * 128;
    int tid = threadIdx.x, w = tid >> 5, lane = tid & 31;
    int r0 = lane >> 2, cq = (lane & 3) * 2;

    auto load_kv = [&](int s, int k0) {
        const bf16* kp = kh + ((size_t)h * Lpad + k0) * DHP;
        const bf16* vp = vh + ((size_t)h * Lpad + k0) * DHP;
        #pragma unroll
        for (int p = 0; p < 3; p++) {
            int c = tid + p * 256;
            if (c < 384) cp16(smem_u32(&sK[s][c * 8]), kp + c * 8, 16);
            else         cp16(smem_u32(&sV[s][(c - 384) * 8]),
                              vp + (c - 384) * 8, 16);
        }
        cp_commit();
    };
    load_kv(0, 0);

    {
        const uint4* src = (const uint4*)(qh + ((size_t)h * L_TOK + qbase) * DHP);
        uint4* dst = (uint4*)sQ;
        #pragma unroll
        for (int p = 0; p < 3; p++) dst[tid + p * 256] = src[tid + p * 256];
    }
    __syncthreads();

    unsigned qa[3][4];
    {
        const bf16* qrow = sQ + (w * 16 + r0) * 48;
        #pragma unroll
        for (int kd = 0; kd < 3; kd++) {
            qa[kd][0] = *(const unsigned*)(qrow + kd * 16 + cq);
            qa[kd][1] = *(const unsigned*)(qrow + 8 * 48 + kd * 16 + cq);
            qa[kd][2] = *(const unsigned*)(qrow + kd * 16 + 8 + cq);
            qa[kd][3] = *(const unsigned*)(qrow + 8 * 48 + kd * 16 + 8 + cq);
        }
    }

    float O[6][4] = {};
    float m0 = -1e30f, m1 = -1e30f, l0 = 0.f, l1 = 0.f;

    int ntiles = (Lk + 63) / 64;
    for (int ti = 0; ti < ntiles; ti++) {
        int s = ti & 1, k0 = ti * 64;
        if (ti + 1 < ntiles) { load_kv(s ^ 1, k0 + 64); cp_wait<1>(); }
        else cp_wait<0>();
        __syncthreads();

        float S[8][4];
        #pragma unroll
        for (int j = 0; j < 8; j++)
            S[j][0] = S[j][1] = S[j][2] = S[j][3] = 0.f;
        #pragma unroll
        for (int kd = 0; kd < 3; kd++)
            #pragma unroll
            for (int j = 0; j < 8; j++) {
                const bf16* kb = &sK[s][(j * 8 + r0) * 48 + kd * 16];
                unsigned b0 = *(const unsigned*)(kb + cq);
                unsigned b1 = *(const unsigned*)(kb + 8 + cq);
                mma16816(S[j], qa[kd][0], qa[kd][1], qa[kd][2], qa[kd][3], b0, b1);
            }

        if (k0 + 64 > Lk) {
            #pragma unroll
            for (int j = 0; j < 8; j++) {
                int col = k0 + j * 8 + cq;
                if (col >= Lk)     { S[j][0] = -1e30f; S[j][2] = -1e30f; }
                if (col + 1 >= Lk) { S[j][1] = -1e30f; S[j][3] = -1e30f; }
            }
        }

        float mx0 = -1e30f, mx1 = -1e30f;
        #pragma unroll
        for (int j = 0; j < 8; j++) {
            mx0 = fmaxf(mx0, fmaxf(S[j][0], S[j][1]));
            mx1 = fmaxf(mx1, fmaxf(S[j][2], S[j][3]));
        }
        mx0 = fmaxf(mx0, __shfl_xor_sync(0xffffffffu, mx0, 1));
        mx0 = fmaxf(mx0, __shfl_xor_sync(0xffffffffu, mx0, 2));
        mx1 = fmaxf(mx1, __shfl_xor_sync(0xffffffffu, mx1, 1));
        mx1 = fmaxf(mx1, __shfl_xor_sync(0xffffffffu, mx1, 2));

        float mn0 = fmaxf(m0, mx0), mn1 = fmaxf(m1, mx1);
        float corr0 = ex2(m0 - mn0), corr1 = ex2(m1 - mn1);
        m0 = mn0; m1 = mn1;

        unsigned P[8][2];
        float sum0 = 0.f, sum1 = 0.f;
        #pragma unroll
        for (int j = 0; j < 8; j++) {
            float p0 = ex2(S[j][0] - mn0), p1 = ex2(S[j][1] - mn0);
            float p2 = ex2(S[j][2] - mn1), p3 = ex2(S[j][3] - mn1);
            sum0 += p0 + p1; sum1 += p2 + p3;
            __nv_bfloat162 u0 = __floats2bfloat162_rn(p0, p1);
            __nv_bfloat162 u1 = __floats2bfloat162_rn(p2, p3);
            P[j][0] = *(unsigned*)&u0;
            P[j][1] = *(unsigned*)&u1;
        }
        sum0 += __shfl_xor_sync(0xffffffffu, sum0, 1);
        sum0 += __shfl_xor_sync(0xffffffffu, sum0, 2);
        sum1 += __shfl_xor_sync(0xffffffffu, sum1, 1);
        sum1 += __shfl_xor_sync(0xffffffffu, sum1, 2);
        l0 = l0 * corr0 + sum0;
        l1 = l1 * corr1 + sum1;

        #pragma unroll
        for (int jd = 0; jd < 6; jd++) {
            O[jd][0] *= corr0; O[jd][1] *= corr0;
            O[jd][2] *= corr1; O[jd][3] *= corr1;
        }

        #pragma unroll
        for (int t = 0; t < 4; t++) {
            #pragma unroll
            for (int p2 = 0; p2 < 3; p2++) {
                int g = lane >> 3;
                unsigned addr = smem_u32(
                    &sV[s][(t * 16 + (g & 1) * 8 + (lane & 7)) * 48
                           + p2 * 16 + (g >> 1) * 8]);
                unsigned v0, v1, v2, v3;
                asm volatile(
                    "ldmatrix.sync.aligned.m8n8.x4.trans.shared.b16 "
                    "{%0,%1,%2,%3}, [%4];"
                    : "=r"(v0), "=r"(v1), "=r"(v2), "=r"(v3) : "r"(addr));
                mma16816(O[2*p2],   P[2*t][0], P[2*t][1],
                                    P[2*t+1][0], P[2*t+1][1], v0, v1);
                mma16816(O[2*p2+1], P[2*t][0], P[2*t][1],
                                    P[2*t+1][0], P[2*t+1][1], v2, v3);
            }
        }
        __syncthreads();
    }

    float il0 = 1.f / l0, il1 = 1.f / l1;
    int tok = qbase + w * 16 + r0;
    #pragma unroll
    for (int jd = 0; jd < 5; jd++) {
        int col = jd * 8 + cq;
        __nv_bfloat162 o0 = __floats2bfloat162_rn(O[jd][0] * il0, O[jd][1] * il0);
        __nv_bfloat162 o1 = __floats2bfloat162_rn(O[jd][2] * il1, O[jd][3] * il1);
        *(__nv_bfloat162*)(Obf + (size_t)tok * C_DIM + h * DH + col) = o0;
        *(__nv_bfloat162*)(Obf + (size_t)(tok + 8) * C_DIM + h * DH + col) = o1;
    }
}

// ---------------------------------------------------------------------------
extern "C" void kernel_launch(void* const* d_in, const int* in_sizes, int n_in,
                              void* d_out, int out_size)
{
    const float* x       = (const float*)d_in[0];
    const float* context = (const float*)d_in[1];
    const float* gn_w    = (const float*)d_in[2];
    const float* gn_b    = (const float*)d_in[3];
    const float* w_in    = (const float*)d_in[4];
    const float* b_in    = (const float*)d_in[5];
    const float* ln1_w   = (const float*)d_in[6];
    const float* ln1_b   = (const float*)d_in[7];
    const float* wq1     = (const float*)d_in[8];
    const float* wk1     = (const float*)d_in[9];
    const float* wv1     = (const float*)d_in[10];
    const float* wo1     = (const float*)d_in[11];
    const float* bo1     = (const float*)d_in[12];
    const float* ln2_w   = (const float*)d_in[13];
    const float* ln2_b   = (const float*)d_in[14];
    const float* wq2     = (const float*)d_in[15];
    const float* wk2     = (const float*)d_in[16];
    const float* wv2     = (const float*)d_in[17];
    const float* wo2     = (const float*)d_in[18];
    const float* bo2     = (const float*)d_in[19];
    const float* ln3_w   = (const float*)d_in[20];
    const float* ln3_b   = (const float*)d_in[21];
    const float* wff1    = (const float*)d_in[22];
    const float* bff1    = (const float*)d_in[23];
    const float* wff2    = (const float*)d_in[24];
    const float* bff2    = (const float*)d_in[25];
    const float* w_out   = (const float*)d_in[26];
    const float* b_out   = (const float*)d_in[27];
    float* out = (float*)d_out;

    static float *t = nullptr;
    static bf16 *xn, *hn, *q, *a, *gg, *tb, *qh, *kh, *vh, *k2h, *v2h, *ctx;
    static bf16 *cw_in, *cwq1, *cwkv1, *cwo1, *cwq2, *cwkv2, *cwo2,
                *cwff1, *cwff2, *cwout;
    static bool init_done = false;
    if (!init_done) {
        cudaGetSymbolAddress((void**)&t,  g_t);
        cudaGetSymbolAddress((void**)&xn, b_xn);
        cudaGetSymbolAddress((void**)&hn, b_hn);
        cudaGetSymbolAddress((void**)&q,  b_q);
        cudaGetSymbolAddress((void**)&a,  b_a);
        cudaGetSymbolAddress((void**)&gg, b_gg);
        cudaGetSymbolAddress((void**)&tb, b_t);
        cudaGetSymbolAddress((void**)&qh, b_qh);
        cudaGetSymbolAddress((void**)&kh, b_kh);
        cudaGetSymbolAddress((void**)&vh, b_vh);
        cudaGetSymbolAddress((void**)&k2h, b_k2h);
        cudaGetSymbolAddress((void**)&v2h, b_v2h);
        cudaGetSymbolAddress((void**)&ctx, b_ctx);
        cudaGetSymbolAddress((void**)&cw_in, b_w_in);
        cudaGetSymbolAddress((void**)&cwq1, b_wq1);
        cudaGetSymbolAddress((void**)&cwkv1, b_wkv1);
        cudaGetSymbolAddress((void**)&cwo1, b_wo1);
        cudaGetSymbolAddress((void**)&cwq2, b_wq2);
        cudaGetSymbolAddress((void**)&cwkv2, b_wkv2);
        cudaGetSymbolAddress((void**)&cwo2, b_wo2);
        cudaGetSymbolAddress((void**)&cwff1, b_wff1);
        cudaGetSymbolAddress((void**)&cwff2, b_wff2);
        cudaGetSymbolAddress((void**)&cwout, b_wout);
        init_done = true;
    }

    const float scaleQ = 0.15811388300841898f * 1.4426950408889634f;
    const int CC4 = C_DIM * C_DIM / 4;

    cvt4_kernel<<<256, 256>>>(
        (const float4*)context, (__nv_bfloat162*)ctx,  LCTX * CTX_DIM / 4,
        (const float4*)w_in,    (__nv_bfloat162*)cw_in, CC4,
        (const float4*)wq1,     (__nv_bfloat162*)cwq1,  CC4,
        (const float4*)wo1,     (__nv_bfloat162*)cwo1,  CC4);
    cvt4_kernel<<<256, 256>>>(
        (const float4*)wq2,     (__nv_bfloat162*)cwq2,  CC4,
        (const float4*)wo2,     (__nv_bfloat162*)cwo2,  CC4,
        (const float4*)wff1,    (__nv_bfloat162*)cwff1, C_DIM * 2 * FFI / 4,
        (const float4*)wff2,    (__nv_bfloat162*)cwff2, FFI * C_DIM / 4);
    cvt4_kernel<<<256, 256>>>(
        (const float4*)w_out,   (__nv_bfloat162*)cwout, CC4,
        nullptr, nullptr, 0, nullptr, nullptr, 0, nullptr, nullptr, 0);
    merge_kv_kernel<<<128, 256>>>((const float4*)wk1, (const float4*)wv1,
                                  (__nv_bfloat162*)cwkv1, C_DIM);
    merge_kv_kernel<<<128, 256>>>((const float4*)wk2, (const float4*)wv2,
                                  (__nv_bfloat162*)cwkv2, CTX_DIM);

    zero_pads_kernel<<<768, 256>>>((uint4*)qh, (uint4*)kh, (uint4*)vh,
                                   (uint4*)k2h, (uint4*)v2h);

    dim3 g320(C_DIM / 64, L_TOK / 128);          // (5, 32)
    dim3 gKV(2 * C_DIM / 64, L_TOK / 128);       // (10, 32)
    dim3 gKVc(2 * C_DIM / 64, 1);                // (10, 1)  M=77
    dim3 gFF1(FFI / 64, L_TOK / 128);            // (20, 32) dual-tile
    dim3 gFF2(C_DIM / 64, L_TOK / 128);          // (5, 32)
    dim3 attnGrid(L_TOK / 128, HEADS);           // (32, 8)

    gn_stats_kernel<<<NGROUPS, 256>>>(x);
    gn_apply_kernel<<<dim3(L_TOK / 64, C_DIM / 32), 256>>>(x, gn_w, gn_b, xn);
    gemm_bf16_kernel<<<g320, 256>>>(xn, cw_in, b_in, nullptr, t, nullptr,
                                    nullptr, nullptr, 0.f, 0, nullptr,
                                    L_TOK, C_DIM, C_DIM, 0);

    // ---- self-attention ----
    ln_kernel<<<L_TOK / 4, 128>>>(t, ln1_w, ln1_b, hn);
    gemm_bf16_kernel<<<g320, 256>>>(hn, cwq1, nullptr, nullptr, nullptr, q,
                                    qh, nullptr, scaleQ, L_TOK, nullptr,
                                    L_TOK, C_DIM, C_DIM, 0);
    gemm_bf16_kernel<<<gKV, 256>>>(q, cwkv1, nullptr, nullptr, nullptr, nullptr,
                                   kh, vh, 1.f, L_TOK, nullptr,
                                   L_TOK, 2 * C_DIM, C_DIM, 0);
    attn_reg_kernel<<<attnGrid, 256>>>(qh, kh, vh, a, L_TOK, L_TOK);
    gemm_bf16_kernel<<<g320, 256>>>(a, cwo1, bo1, t, t, nullptr,
                                    nullptr, nullptr, 0.f, 0, nullptr,
                                    L_TOK, C_DIM, C_DIM, 0);

    // ---- cross-attention ----
    ln_kernel<<<L_TOK / 4, 128>>>(t, ln2_w, ln2_b, hn);
    gemm_bf16_kernel<<<g320, 256>>>(hn, cwq2, nullptr, nullptr, nullptr, nullptr,
                                    qh, nullptr, scaleQ, L_TOK, nullptr,
                                    L_TOK, C_DIM, C_DIM, 0);
    gemm_bf16_kernel<<<gKVc, 256>>>(ctx, cwkv2, nullptr, nullptr, nullptr, nullptr,
                                    k2h, v2h, 1.f, LCTXP, nullptr,
                                    LCTX, 2 * C_DIM, CTX_DIM, 0);
    attn_reg_kernel<<<attnGrid, 256>>>(qh, k2h, v2h, a, LCTX, LCTXP);
    gemm_bf16_kernel<<<g320, 256>>>(a, cwo2, bo2, t, t, nullptr,
                                    nullptr, nullptr, 0.f, 0, nullptr,
                                    L_TOK, C_DIM, C_DIM, 0);

    // ---- feed-forward: fused FF1 + GEGLU, then FF2 ----
    ln_kernel<<<L_TOK / 4, 128>>>(t, ln3_w, ln3_b, hn);
    gemm_bf16_kernel<<<gFF1, 256>>>(hn, cwff1, bff1, nullptr, nullptr, nullptr,
                                    nullptr, nullptr, 0.f, 0, gg,
                                    L_TOK, 2 * FFI, C_DIM, 0);
    gemm_bf16_kernel<<<gFF2, 256>>>(gg, cwff2, bff2, t, t, tb,
                                    nullptr, nullptr, 0.f, 0, nullptr,
                                    L_TOK, C_DIM, FFI, 0);

    // ---- proj_out (+ x residual), channel-major store ----
    gemm_bf16_kernel<<<g320, 256>>>(tb, cwout, b_out, x, out, nullptr,
                                    nullptr, nullptr, 0.f, 0, nullptr,
                                    L_TOK, C_DIM, C_DIM, 1);
}

// round 9
// speedup vs baseline: 4.5888x; 1.0678x over previous
#include <cuda_runtime.h>
#include <cuda_bf16.h>
#include <mma.h>
#include <math.h>
#include <cstdint>

using namespace nvcuda;

// ---------------------------------------------------------------------------
// SpatialTransformer — round 8: 3-stage cp.async pipelines (GEMM + attention,
// single barrier per iter), vectorized LN, wide GN stats, merged prep.
// ---------------------------------------------------------------------------

#define L_TOK   4096
#define C_DIM   320
#define HEADS   8
#define DH      40
#define DHP     48
#define CTX_DIM 768
#define LCTX    77
#define LCTXP   128
#define FFI     1280
#define NGROUPS 32
#define CH_PER_G 10

typedef __nv_bfloat16 bf16;

// fp32 scratch
__device__ float g_t [L_TOK * C_DIM];
__device__ float g_mean[NGROUPS];
__device__ float g_rstd[NGROUPS];
// bf16 activations
__device__ bf16 b_xn[L_TOK * C_DIM];
__device__ bf16 b_hn[L_TOK * C_DIM];
__device__ bf16 b_q [L_TOK * C_DIM];
__device__ bf16 b_a [L_TOK * C_DIM];
__device__ bf16 b_gg[L_TOK * FFI];
__device__ bf16 b_t [L_TOK * C_DIM];
__device__ bf16 b_qh[HEADS * L_TOK * DHP];
__device__ bf16 b_kh[HEADS * L_TOK * DHP];
__device__ bf16 b_vh[HEADS * L_TOK * DHP];
__device__ bf16 b_k2h[HEADS * LCTXP * DHP];
__device__ bf16 b_v2h[HEADS * LCTXP * DHP];
__device__ bf16 b_ctx[LCTX * CTX_DIM];
// bf16 weights
__device__ bf16 b_w_in[C_DIM * C_DIM];
__device__ bf16 b_wq1[C_DIM * C_DIM];
__device__ bf16 b_wkv1[C_DIM * 2 * C_DIM];
__device__ bf16 b_wo1[C_DIM * C_DIM];
__device__ bf16 b_wq2[C_DIM * C_DIM];
__device__ bf16 b_wkv2[CTX_DIM * 2 * C_DIM];
__device__ bf16 b_wo2[C_DIM * C_DIM];
__device__ bf16 b_wff1[C_DIM * 2 * FFI];
__device__ bf16 b_wff2[FFI * C_DIM];
__device__ bf16 b_wout[C_DIM * C_DIM];

// ---------------- helpers ----------------
__device__ __forceinline__ unsigned int smem_u32(const void* p)
{ return (unsigned int)__cvta_generic_to_shared(p); }

__device__ __forceinline__ void cp16(unsigned int dst, const void* src, int sz)
{ asm volatile("cp.async.cg.shared.global [%0], [%1], 16, %2;\n"
               :: "r"(dst), "l"(src), "r"(sz)); }

__device__ __forceinline__ void cp_commit()
{ asm volatile("cp.async.commit_group;\n"); }

template<int N> __device__ __forceinline__ void cp_wait()
{ asm volatile("cp.async.wait_group %0;\n" :: "n"(N)); }

__device__ __forceinline__ float ex2(float x)
{ float r; asm("ex2.approx.f32 %0, %1;" : "=f"(r) : "f"(x)); return r; }

__device__ __forceinline__ void mma16816(float* c,
    unsigned a0, unsigned a1, unsigned a2, unsigned a3,
    unsigned b0, unsigned b1)
{
    asm volatile(
        "mma.sync.aligned.m16n8k16.row.col.f32.bf16.bf16.f32 "
        "{%0,%1,%2,%3}, {%4,%5,%6,%7}, {%8,%9}, {%0,%1,%2,%3};"
        : "+f"(c[0]), "+f"(c[1]), "+f"(c[2]), "+f"(c[3])
        : "r"(a0), "r"(a1), "r"(a2), "r"(a3), "r"(b0), "r"(b1));
}

// ---------------- prep: fp32 -> bf16 (9 jobs, one launch) ----------------
struct CvtJobs {
    const float4* s[9];
    __nv_bfloat162* d[9];
    int n[9];
};

__global__ void cvt_all_kernel(CvtJobs J)
{
    int i0 = blockIdx.x * blockDim.x + threadIdx.x;
    int st = gridDim.x * blockDim.x;
    #pragma unroll
    for (int q = 0; q < 9; q++) {
        const float4* s = J.s[q];
        __nv_bfloat162* d = J.d[q];
        int n = J.n[q];
        for (int j = i0; j < n; j += st) {
            float4 v = s[j];
            d[2*j]   = __floats2bfloat162_rn(v.x, v.y);
            d[2*j+1] = __floats2bfloat162_rn(v.z, v.w);
        }
    }
}

// merge wk|wv pairs into [K][2C] bf16 (both attention blocks, one launch)
__global__ void merge_kv2_kernel(const float4* wk1, const float4* wv1,
                                 __nv_bfloat162* d1,
                                 const float4* wk2, const float4* wv2,
                                 __nv_bfloat162* d2)
{
    int i0 = blockIdx.x * blockDim.x + threadIdx.x;
    int st = gridDim.x * blockDim.x;
    const int C4 = C_DIM / 4;
    {
        int n4 = C_DIM * C4;
        for (int j = i0; j < n4; j += st) {
            int k = j / C4, c4 = j % C4;
            float4 a = wk1[j];
            float4 b = wv1[j];
            __nv_bfloat162* row = d1 + k * C_DIM;
            row[c4*2]   = __floats2bfloat162_rn(a.x, a.y);
            row[c4*2+1] = __floats2bfloat162_rn(a.z, a.w);
            row[C_DIM/2 + c4*2]   = __floats2bfloat162_rn(b.x, b.y);
            row[C_DIM/2 + c4*2+1] = __floats2bfloat162_rn(b.z, b.w);
        }
    }
    {
        int n4 = CTX_DIM * C4;
        for (int j = i0; j < n4; j += st) {
            int k = j / C4, c4 = j % C4;
            float4 a = wk2[j];
            float4 b = wv2[j];
            __nv_bfloat162* row = d2 + k * C_DIM;
            row[c4*2]   = __floats2bfloat162_rn(a.x, a.y);
            row[c4*2+1] = __floats2bfloat162_rn(a.z, a.w);
            row[C_DIM/2 + c4*2]   = __floats2bfloat162_rn(b.x, b.y);
            row[C_DIM/2 + c4*2+1] = __floats2bfloat162_rn(b.z, b.w);
        }
    }
}

// ---------------- zero head-major buffers ----------------
__global__ void zero_pads_kernel(uint4* a, uint4* b, uint4* c, uint4* d, uint4* e)
{
    const uint4 z = make_uint4(0, 0, 0, 0);
    int i = blockIdx.x * blockDim.x + threadIdx.x;
    int st = gridDim.x * blockDim.x;
    const int NB = HEADS * L_TOK * DHP / 8;
    const int NS = HEADS * LCTXP * DHP / 8;
    for (int j = i; j < NB; j += st) { a[j] = z; b[j] = z; c[j] = z; }
    for (int j = i; j < NS; j += st) { d[j] = z; e[j] = z; }
}

// ---------------- GroupNorm ----------------
__global__ __launch_bounds__(1024) void gn_stats_kernel(const float* __restrict__ x)
{
    int g = blockIdx.x;
    int tid = threadIdx.x;
    const int N4 = CH_PER_G * L_TOK / 4;   // 10240
    float s = 0.f, ss = 0.f;
    const float4* base = (const float4*)(x + (size_t)g * CH_PER_G * L_TOK);
    for (int i = tid; i < N4; i += 1024) {
        float4 v = base[i];
        s  += v.x + v.y + v.z + v.w;
        ss += v.x*v.x + v.y*v.y + v.z*v.z + v.w*v.w;
    }
    __shared__ float rs[1024], rss[1024];
    rs[tid] = s; rss[tid] = ss;
    __syncthreads();
    for (int o = 512; o > 0; o >>= 1) {
        if (tid < o) { rs[tid] += rs[tid + o]; rss[tid] += rss[tid + o]; }
        __syncthreads();
    }
    if (tid == 0) {
        const float NEL = (float)(CH_PER_G * L_TOK);
        float m = rs[0] / NEL;
        float var = rss[0] / NEL - m * m;
        g_mean[g] = m;
        g_rstd[g] = rsqrtf(var + 1e-6f);
    }
}

__global__ void gn_apply_kernel(const float* __restrict__ x,
                                const float* __restrict__ gw,
                                const float* __restrict__ gb,
                                bf16* __restrict__ out)
{
    __shared__ float tile[32][65];
    int hw0 = blockIdx.x * 64;
    int c0  = blockIdx.y * 32;
    #pragma unroll
    for (int p = 0; p < 8; p++) {
        int i = threadIdx.x + p * 256;
        int c = i >> 6, hw = i & 63;
        int gc = c0 + c;
        int g = gc / CH_PER_G;
        float v = (x[(size_t)gc * L_TOK + hw0 + hw] - g_mean[g]) * g_rstd[g]
                  * gw[gc] + gb[gc];
        tile[c][hw] = v;
    }
    __syncthreads();
    #pragma unroll
    for (int p = 0; p < 8; p++) {
        int i = threadIdx.x + p * 256;
        int hw = i >> 5, c = i & 31;
        out[(size_t)(hw0 + hw) * C_DIM + c0 + c] = __float2bfloat16(tile[c][hw]);
    }
}

// ---------------- LayerNorm (warp/token, vectorized) ----------------
__global__ __launch_bounds__(256) void ln_kernel(
    const float* __restrict__ in, const float* __restrict__ w,
    const float* __restrict__ b, bf16* __restrict__ out)
{
    int token = blockIdx.x * 8 + (threadIdx.x >> 5);
    int lane = threadIdx.x & 31;
    const float4* row4 = (const float4*)(in + (size_t)token * C_DIM); // 80
    float s = 0.f, ss = 0.f;
    #pragma unroll
    for (int j = 0; j < 3; j++) {
        int idx = lane + j * 32;
        if (idx < 80) {
            float4 v = row4[idx];
            s  += v.x + v.y + v.z + v.w;
            ss += v.x*v.x + v.y*v.y + v.z*v.z + v.w*v.w;
        }
    }
    #pragma unroll
    for (int o = 16; o > 0; o >>= 1) {
        s  += __shfl_xor_sync(0xffffffffu, s, o);
        ss += __shfl_xor_sync(0xffffffffu, ss, o);
    }
    float m = s / (float)C_DIM;
    float var = ss / (float)C_DIM - m * m;
    float r = rsqrtf(var + 1e-5f);

    const float2* row2 = (const float2*)(in + (size_t)token * C_DIM); // 160
    const float2* w2 = (const float2*)w;
    const float2* b2 = (const float2*)b;
    __nv_bfloat162* o2 = (__nv_bfloat162*)(out + (size_t)token * C_DIM);
    #pragma unroll
    for (int j = 0; j < 5; j++) {
        int idx = lane + j * 32;
        float2 v = row2[idx];
        float2 ww = w2[idx];
        float2 bb = b2[idx];
        o2[idx] = __floats2bfloat162_rn((v.x - m) * r * ww.x + bb.x,
                                        (v.y - m) * r * ww.y + bb.y);
    }
}

// ---------------- bf16 TC GEMM, 128x64, 256 thr, 3-stage cp.async ---------
struct GemmBuf { bf16 As[3][128][40]; bf16 Bs[3][2][32][72]; };
#define GEMM_SMEM ((int)sizeof(GemmBuf))

__global__ __launch_bounds__(256) void gemm_bf16_kernel(
    const bf16* __restrict__ A, const bf16* __restrict__ B,
    const float* __restrict__ bias, const float* __restrict__ res,
    float* __restrict__ Cf, bf16* __restrict__ Cbf,
    bf16* __restrict__ attnK, bf16* __restrict__ attnV,
    float attnScale, int Lpad,
    bf16* __restrict__ ggOut,
    int M, int N, int K, int transOut)
{
    extern __shared__ char smraw[];
    GemmBuf* in = (GemmBuf*)smraw;
    float (*Cs)[68] = (float(*)[68])smraw;   // aliases in; used after final sync

    const bool dual = (ggOut != nullptr);
    int bm = blockIdx.y * 128;
    int bn = blockIdx.x * 64;
    int tid = threadIdx.x;
    int w = tid >> 5, wm = w >> 1, wn = w & 1;

    wmma::fragment<wmma::accumulator, 16, 16, 16, float> acc[2][2], acc2[2][2];
    #pragma unroll
    for (int i = 0; i < 2; i++)
        #pragma unroll
        for (int j = 0; j < 2; j++) {
            wmma::fill_fragment(acc[i][j], 0.f);
            wmma::fill_fragment(acc2[i][j], 0.f);
        }

    auto issue = [&](int s, int k0) {
        #pragma unroll
        for (int p = 0; p < 2; p++) {
            int c = tid + p * 256;
            int row = c >> 2, ch = c & 3;
            int gm = bm + row;
            const bf16* src = A + (size_t)(gm < M ? gm : 0) * K + k0 + ch * 8;
            cp16(smem_u32(&in->As[s][row][ch * 8]), src, (gm < M) ? 16 : 0);
        }
        {
            int row = tid >> 3, ch = tid & 7;
            const bf16* src = B + (size_t)(k0 + row) * N + bn + ch * 8;
            cp16(smem_u32(&in->Bs[s][0][row][ch * 8]), src, 16);
            if (dual)
                cp16(smem_u32(&in->Bs[s][1][row][ch * 8]), src + FFI, 16);
        }
        cp_commit();
    };

    int nk = K / 32;
    issue(0, 0);
    issue(1, 32);
    for (int ki = 0; ki < nk; ki++) {
        int s = ki - (ki / 3) * 3;
        if (ki == nk - 1) cp_wait<0>(); else cp_wait<1>();
        __syncthreads();
        #pragma unroll
        for (int ks = 0; ks < 2; ks++) {
            wmma::fragment<wmma::matrix_a, 16, 16, 16, bf16, wmma::row_major> af[2];
            wmma::fragment<wmma::matrix_b, 16, 16, 16, bf16, wmma::row_major> bfr[2];
            wmma::load_matrix_sync(af[0], &in->As[s][wm*32     ][ks*16], 40);
            wmma::load_matrix_sync(af[1], &in->As[s][wm*32 + 16][ks*16], 40);
            wmma::load_matrix_sync(bfr[0], &in->Bs[s][0][ks*16][wn*32     ], 72);
            wmma::load_matrix_sync(bfr[1], &in->Bs[s][0][ks*16][wn*32 + 16], 72);
            #pragma unroll
            for (int i = 0; i < 2; i++)
                #pragma unroll
                for (int j = 0; j < 2; j++)
                    wmma::mma_sync(acc[i][j], af[i], bfr[j], acc[i][j]);
            if (dual) {
                wmma::load_matrix_sync(bfr[0], &in->Bs[s][1][ks*16][wn*32     ], 72);
                wmma::load_matrix_sync(bfr[1], &in->Bs[s][1][ks*16][wn*32 + 16], 72);
                #pragma unroll
                for (int i = 0; i < 2; i++)
                    #pragma unroll
                    for (int j = 0; j < 2; j++)
                        wmma::mma_sync(acc2[i][j], af[i], bfr[j], acc2[i][j]);
            }
        }
        if (ki + 2 < nk) {
            int s2 = (ki + 2) - ((ki + 2) / 3) * 3;
            issue(s2, (ki + 2) * 32);
        }
    }
    __syncthreads();

    // ---- epilogue ----
    #pragma unroll
    for (int i = 0; i < 2; i++)
        #pragma unroll
        for (int j = 0; j < 2; j++)
            wmma::store_matrix_sync(&Cs[wm*32 + i*16][wn*32 + j*16],
                                    acc[i][j], 68, wmma::mem_row_major);
    __syncthreads();

    if (dual) {
        float rA[32];
        #pragma unroll
        for (int p = 0; p < 32; p++) {
            int i = tid + p * 256;
            rA[p] = Cs[i >> 6][i & 63];
        }
        __syncthreads();
        #pragma unroll
        for (int i = 0; i < 2; i++)
            #pragma unroll
            for (int j = 0; j < 2; j++)
                wmma::store_matrix_sync(&Cs[wm*32 + i*16][wn*32 + j*16],
                                        acc2[i][j], 68, wmma::mem_row_major);
        __syncthreads();
        #pragma unroll
        for (int p = 0; p < 32; p++) {
            int i = tid + p * 256;
            int m = i >> 6, n = i & 63;
            int gm = bm + m, gn = bn + n;
            float av = rA[p] + bias[gn];
            float gv = Cs[m][n] + bias[gn + FFI];
            float ge = 0.5f * gv * (1.f + erff(gv * 0.70710678118654752f));
            ggOut[(size_t)gm * FFI + gn] = __float2bfloat16(av * ge);
        }
        return;
    }

    #pragma unroll
    for (int p = 0; p < 32; p++) {
        int i = tid + p * 256;
        int m = i >> 6, n = i & 63;
        int gm = bm + m, gn = bn + n;
        if (gm >= M) continue;
        float v = Cs[m][n];
        if (bias) v += bias[gn];
        if (Cf) {
            size_t idx = transOut ? ((size_t)gn * M + gm) : ((size_t)gm * N + gn);
            if (res) v += res[idx];
            Cf[idx] = v;
        }
        if (Cbf) Cbf[(size_t)gm * N + gn] = __float2bfloat16(v);
        if (attnK) {
            bf16* dst;
            int cc;
            if (gn < C_DIM) { dst = attnK; cc = gn; }
            else            { dst = attnV; cc = gn - C_DIM; }
            if (attnV == nullptr) { dst = attnK; cc = gn; }
            int h = cc & 7, j = cc >> 3;
            dst[((size_t)h * Lpad + gm) * DHP + j] =
                __float2bfloat16(v * attnScale);
        }
    }
}

// ---------------- FA2 attention, 3-stage K/V pipeline ----------------
#define ATTN_SMEM (3 * 3072 * 2 * 2 + 128 * 48 * 2)   // 49152

__global__ __launch_bounds__(256) void attn_reg_kernel(
    const bf16* __restrict__ qh, const bf16* __restrict__ kh,
    const bf16* __restrict__ vh, bf16* __restrict__ Obf,
    int Lk, int Lpad)
{
    extern __shared__ char smraw[];
    bf16* sK = (bf16*)smraw;            // [3][64*48]
    bf16* sV = sK + 3 * 3072;           // [3][64*48]
    bf16* sQ = sV + 3 * 3072;           // [128*48]

    int h = blockIdx.y;
    int qbase = blockIdx.x * 128;
    int tid = threadIdx.x, w = tid >> 5, lane = tid & 31;
    int r0 = lane >> 2, cq = (lane & 3) * 2;

    auto load_kv = [&](int s, int k0) {
        const bf16* kp = kh + ((size_t)h * Lpad + k0) * DHP;
        const bf16* vp = vh + ((size_t)h * Lpad + k0) * DHP;
        #pragma unroll
        for (int p = 0; p < 3; p++) {
            int c = tid + p * 256;
            if (c < 384) cp16(smem_u32(&sK[s * 3072 + c * 8]), kp + c * 8, 16);
            else         cp16(smem_u32(&sV[s * 3072 + (c - 384) * 8]),
                              vp + (c - 384) * 8, 16);
        }
        cp_commit();
    };

    int ntiles = (Lk + 63) / 64;
    load_kv(0, 0);
    if (ntiles > 1) load_kv(1, 64);

    {
        const uint4* src = (const uint4*)(qh + ((size_t)h * L_TOK + qbase) * DHP);
        uint4* dst = (uint4*)sQ;
        #pragma unroll
        for (int p = 0; p < 3; p++) dst[tid + p * 256] = src[tid + p * 256];
    }
    __syncthreads();

    unsigned qa[3][4];
    {
        const bf16* qrow = sQ + (w * 16 + r0) * 48;
        #pragma unroll
        for (int kd = 0; kd < 3; kd++) {
            qa[kd][0] = *(const unsigned*)(qrow + kd * 16 + cq);
            qa[kd][1] = *(const unsigned*)(qrow + 8 * 48 + kd * 16 + cq);
            qa[kd][2] = *(const unsigned*)(qrow + kd * 16 + 8 + cq);
            qa[kd][3] = *(const unsigned*)(qrow + 8 * 48 + kd * 16 + 8 + cq);
        }
    }

    float O[6][4] = {};
    float m0 = -1e30f, m1 = -1e30f, l0 = 0.f, l1 = 0.f;

    for (int ti = 0; ti < ntiles; ti++) {
        int s = ti - (ti / 3) * 3;
        int k0 = ti * 64;
        if (ti == ntiles - 1) cp_wait<0>(); else cp_wait<1>();
        __syncthreads();

        float S[8][4];
        #pragma unroll
        for (int j = 0; j < 8; j++)
            S[j][0] = S[j][1] = S[j][2] = S[j][3] = 0.f;
        #pragma unroll
        for (int kd = 0; kd < 3; kd++)
            #pragma unroll
            for (int j = 0; j < 8; j++) {
                const bf16* kb = &sK[s * 3072 + (j * 8 + r0) * 48 + kd * 16];
                unsigned b0 = *(const unsigned*)(kb + cq);
                unsigned b1 = *(const unsigned*)(kb + 8 + cq);
                mma16816(S[j], qa[kd][0], qa[kd][1], qa[kd][2], qa[kd][3], b0, b1);
            }

        if (k0 + 64 > Lk) {
            #pragma unroll
            for (int j = 0; j < 8; j++) {
                int col = k0 + j * 8 + cq;
                if (col >= Lk)     { S[j][0] = -1e30f; S[j][2] = -1e30f; }
                if (col + 1 >= Lk) { S[j][1] = -1e30f; S[j][3] = -1e30f; }
            }
        }

        float mx0 = -1e30f, mx1 = -1e30f;
        #pragma unroll
        for (int j = 0; j < 8; j++) {
            mx0 = fmaxf(mx0, fmaxf(S[j][0], S[j][1]));
            mx1 = fmaxf(mx1, fmaxf(S[j][2], S[j][3]));
        }
        mx0 = fmaxf(mx0, __shfl_xor_sync(0xffffffffu, mx0, 1));
        mx0 = fmaxf(mx0, __shfl_xor_sync(0xffffffffu, mx0, 2));
        mx1 = fmaxf(mx1, __shfl_xor_sync(0xffffffffu, mx1, 1));
        mx1 = fmaxf(mx1, __shfl_xor_sync(0xffffffffu, mx1, 2));

        float mn0 = fmaxf(m0, mx0), mn1 = fmaxf(m1, mx1);
        float corr0 = ex2(m0 - mn0), corr1 = ex2(m1 - mn1);
        m0 = mn0; m1 = mn1;

        unsigned P[8][2];
        float sum0 = 0.f, sum1 = 0.f;
        #pragma unroll
        for (int j = 0; j < 8; j++) {
            float p0 = ex2(S[j][0] - mn0), p1 = ex2(S[j][1] - mn0);
            float p2 = ex2(S[j][2] - mn1), p3 = ex2(S[j][3] - mn1);
            sum0 += p0 + p1; sum1 += p2 + p3;
            __nv_bfloat162 u0 = __floats2bfloat162_rn(p0, p1);
            __nv_bfloat162 u1 = __floats2bfloat162_rn(p2, p3);
            P[j][0] = *(unsigned*)&u0;
            P[j][1] = *(unsigned*)&u1;
        }
        sum0 += __shfl_xor_sync(0xffffffffu, sum0, 1);
        sum0 += __shfl_xor_sync(0xffffffffu, sum0, 2);
        sum1 += __shfl_xor_sync(0xffffffffu, sum1, 1);
        sum1 += __shfl_xor_sync(0xffffffffu, sum1, 2);
        l0 = l0 * corr0 + sum0;
        l1 = l1 * corr1 + sum1;

        #pragma unroll
        for (int jd = 0; jd < 6; jd++) {
            O[jd][0] *= corr0; O[jd][1] *= corr0;
            O[jd][2] *= corr1; O[jd][3] *= corr1;
        }

        #pragma unroll
        for (int t = 0; t < 4; t++) {
            #pragma unroll
            for (int p2 = 0; p2 < 3; p2++) {
                int g = lane >> 3;
                unsigned addr = smem_u32(
                    &sV[s * 3072 + (t * 16 + (g & 1) * 8 + (lane & 7)) * 48
                        + p2 * 16 + (g >> 1) * 8]);
                unsigned v0, v1, v2, v3;
                asm volatile(
                    "ldmatrix.sync.aligned.m8n8.x4.trans.shared.b16 "
                    "{%0,%1,%2,%3}, [%4];"
                    : "=r"(v0), "=r"(v1), "=r"(v2), "=r"(v3) : "r"(addr));
                mma16816(O[2*p2],   P[2*t][0], P[2*t][1],
                                    P[2*t+1][0], P[2*t+1][1], v0, v1);
                mma16816(O[2*p2+1], P[2*t][0], P[2*t][1],
                                    P[2*t+1][0], P[2*t+1][1], v2, v3);
            }
        }

        if (ti + 2 < ntiles) {
            int s2 = (ti + 2) - ((ti + 2) / 3) * 3;
            load_kv(s2, (ti + 2) * 64);
        }
    }

    float il0 = 1.f / l0, il1 = 1.f / l1;
    int tok = qbase + w * 16 + r0;
    #pragma unroll
    for (int jd = 0; jd < 5; jd++) {
        int col = jd * 8 + cq;
        __nv_bfloat162 o0 = __floats2bfloat162_rn(O[jd][0] * il0, O[jd][1] * il0);
        __nv_bfloat162 o1 = __floats2bfloat162_rn(O[jd][2] * il1, O[jd][3] * il1);
        *(__nv_bfloat162*)(Obf + (size_t)tok * C_DIM + h * DH + col) = o0;
        *(__nv_bfloat162*)(Obf + (size_t)(tok + 8) * C_DIM + h * DH + col) = o1;
    }
}

// ---------------------------------------------------------------------------
extern "C" void kernel_launch(void* const* d_in, const int* in_sizes, int n_in,
                              void* d_out, int out_size)
{
    const float* x       = (const float*)d_in[0];
    const float* context = (const float*)d_in[1];
    const float* gn_w    = (const float*)d_in[2];
    const float* gn_b    = (const float*)d_in[3];
    const float* w_in    = (const float*)d_in[4];
    const float* b_in    = (const float*)d_in[5];
    const float* ln1_w   = (const float*)d_in[6];
    const float* ln1_b   = (const float*)d_in[7];
    const float* wq1     = (const float*)d_in[8];
    const float* wk1     = (const float*)d_in[9];
    const float* wv1     = (const float*)d_in[10];
    const float* wo1     = (const float*)d_in[11];
    const float* bo1     = (const float*)d_in[12];
    const float* ln2_w   = (const float*)d_in[13];
    const float* ln2_b   = (const float*)d_in[14];
    const float* wq2     = (const float*)d_in[15];
    const float* wk2     = (const float*)d_in[16];
    const float* wv2     = (const float*)d_in[17];
    const float* wo2     = (const float*)d_in[18];
    const float* bo2     = (const float*)d_in[19];
    const float* ln3_w   = (const float*)d_in[20];
    const float* ln3_b   = (const float*)d_in[21];
    const float* wff1    = (const float*)d_in[22];
    const float* bff1    = (const float*)d_in[23];
    const float* wff2    = (const float*)d_in[24];
    const float* bff2    = (const float*)d_in[25];
    const float* w_out   = (const float*)d_in[26];
    const float* b_out   = (const float*)d_in[27];
    float* out = (float*)d_out;

    static float *t = nullptr;
    static bf16 *xn, *hn, *q, *a, *gg, *tb, *qh, *kh, *vh, *k2h, *v2h, *ctx;
    static bf16 *cw_in, *cwq1, *cwkv1, *cwo1, *cwq2, *cwkv2, *cwo2,
                *cwff1, *cwff2, *cwout;
    static bool init_done = false;
    if (!init_done) {
        cudaGetSymbolAddress((void**)&t,  g_t);
        cudaGetSymbolAddress((void**)&xn, b_xn);
        cudaGetSymbolAddress((void**)&hn, b_hn);
        cudaGetSymbolAddress((void**)&q,  b_q);
        cudaGetSymbolAddress((void**)&a,  b_a);
        cudaGetSymbolAddress((void**)&gg, b_gg);
        cudaGetSymbolAddress((void**)&tb, b_t);
        cudaGetSymbolAddress((void**)&qh, b_qh);
        cudaGetSymbolAddress((void**)&kh, b_kh);
        cudaGetSymbolAddress((void**)&vh, b_vh);
        cudaGetSymbolAddress((void**)&k2h, b_k2h);
        cudaGetSymbolAddress((void**)&v2h, b_v2h);
        cudaGetSymbolAddress((void**)&ctx, b_ctx);
        cudaGetSymbolAddress((void**)&cw_in, b_w_in);
        cudaGetSymbolAddress((void**)&cwq1, b_wq1);
        cudaGetSymbolAddress((void**)&cwkv1, b_wkv1);
        cudaGetSymbolAddress((void**)&cwo1, b_wo1);
        cudaGetSymbolAddress((void**)&cwq2, b_wq2);
        cudaGetSymbolAddress((void**)&cwkv2, b_wkv2);
        cudaGetSymbolAddress((void**)&cwo2, b_wo2);
        cudaGetSymbolAddress((void**)&cwff1, b_wff1);
        cudaGetSymbolAddress((void**)&cwff2, b_wff2);
        cudaGetSymbolAddress((void**)&cwout, b_wout);
        cudaFuncSetAttribute(gemm_bf16_kernel,
                             cudaFuncAttributeMaxDynamicSharedMemorySize,
                             GEMM_SMEM);
        cudaFuncSetAttribute(attn_reg_kernel,
                             cudaFuncAttributeMaxDynamicSharedMemorySize,
                             ATTN_SMEM);
        init_done = true;
    }

    const float scaleQ = 0.15811388300841898f * 1.4426950408889634f;
    const int CC4 = C_DIM * C_DIM / 4;

    CvtJobs J;
    J.s[0] = (const float4*)context; J.d[0] = (__nv_bfloat162*)ctx;   J.n[0] = LCTX * CTX_DIM / 4;
    J.s[1] = (const float4*)w_in;    J.d[1] = (__nv_bfloat162*)cw_in; J.n[1] = CC4;
    J.s[2] = (const float4*)wq1;     J.d[2] = (__nv_bfloat162*)cwq1;  J.n[2] = CC4;
    J.s[3] = (const float4*)wo1;     J.d[3] = (__nv_bfloat162*)cwo1;  J.n[3] = CC4;
    J.s[4] = (const float4*)wq2;     J.d[4] = (__nv_bfloat162*)cwq2;  J.n[4] = CC4;
    J.s[5] = (const float4*)wo2;     J.d[5] = (__nv_bfloat162*)cwo2;  J.n[5] = CC4;
    J.s[6] = (const float4*)wff1;    J.d[6] = (__nv_bfloat162*)cwff1; J.n[6] = C_DIM * 2 * FFI / 4;
    J.s[7] = (const float4*)wff2;    J.d[7] = (__nv_bfloat162*)cwff2; J.n[7] = FFI * C_DIM / 4;
    J.s[8] = (const float4*)w_out;   J.d[8] = (__nv_bfloat162*)cwout; J.n[8] = CC4;
    cvt_all_kernel<<<512, 256>>>(J);
    merge_kv2_kernel<<<256, 256>>>((const float4*)wk1, (const float4*)wv1,
                                   (__nv_bfloat162*)cwkv1,
                                   (const float4*)wk2, (const float4*)wv2,
                                   (__nv_bfloat162*)cwkv2);
    zero_pads_kernel<<<768, 256>>>((uint4*)qh, (uint4*)kh, (uint4*)vh,
                                   (uint4*)k2h, (uint4*)v2h);

    dim3 g320(C_DIM / 64, L_TOK / 128);          // (5, 32)
    dim3 gKV(2 * C_DIM / 64, L_TOK / 128);       // (10, 32)
    dim3 gKVc(2 * C_DIM / 64, 1);                // (10, 1)
    dim3 gFF1(FFI / 64, L_TOK / 128);            // (20, 32)
    dim3 gFF2(C_DIM / 64, L_TOK / 128);          // (5, 32)
    dim3 attnGrid(L_TOK / 128, HEADS);           // (32, 8)

    gn_stats_kernel<<<NGROUPS, 1024>>>(x);
    gn_apply_kernel<<<dim3(L_TOK / 64, C_DIM / 32), 256>>>(x, gn_w, gn_b, xn);
    gemm_bf16_kernel<<<g320, 256, GEMM_SMEM>>>(xn, cw_in, b_in, nullptr, t, nullptr,
                                    nullptr, nullptr, 0.f, 0, nullptr,
                                    L_TOK, C_DIM, C_DIM, 0);

    // ---- self-attention ----
    ln_kernel<<<L_TOK / 8, 256>>>(t, ln1_w, ln1_b, hn);
    gemm_bf16_kernel<<<g320, 256, GEMM_SMEM>>>(hn, cwq1, nullptr, nullptr, nullptr, q,
                                    qh, nullptr, scaleQ, L_TOK, nullptr,
                                    L_TOK, C_DIM, C_DIM, 0);
    gemm_bf16_kernel<<<gKV, 256, GEMM_SMEM>>>(q, cwkv1, nullptr, nullptr, nullptr, nullptr,
                                   kh, vh, 1.f, L_TOK, nullptr,
                                   L_TOK, 2 * C_DIM, C_DIM, 0);
    attn_reg_kernel<<<attnGrid, 256, ATTN_SMEM>>>(qh, kh, vh, a, L_TOK, L_TOK);
    gemm_bf16_kernel<<<g320, 256, GEMM_SMEM>>>(a, cwo1, bo1, t, t, nullptr,
                                    nullptr, nullptr, 0.f, 0, nullptr,
                                    L_TOK, C_DIM, C_DIM, 0);

    // ---- cross-attention ----
    ln_kernel<<<L_TOK / 8, 256>>>(t, ln2_w, ln2_b, hn);
    gemm_bf16_kernel<<<g320, 256, GEMM_SMEM>>>(hn, cwq2, nullptr, nullptr, nullptr, nullptr,
                                    qh, nullptr, scaleQ, L_TOK, nullptr,
                                    L_TOK, C_DIM, C_DIM, 0);
    gemm_bf16_kernel<<<gKVc, 256, GEMM_SMEM>>>(ctx, cwkv2, nullptr, nullptr, nullptr, nullptr,
                                    k2h, v2h, 1.f, LCTXP, nullptr,
                                    LCTX, 2 * C_DIM, CTX_DIM, 0);
    attn_reg_kernel<<<attnGrid, 256, ATTN_SMEM>>>(qh, k2h, v2h, a, LCTX, LCTXP);
    gemm_bf16_kernel<<<g320, 256, GEMM_SMEM>>>(a, cwo2, bo2, t, t, nullptr,
                                    nullptr, nullptr, 0.f, 0, nullptr,
                                    L_TOK, C_DIM, C_DIM, 0);

    // ---- feed-forward: fused FF1 + GEGLU, then FF2 ----
    ln_kernel<<<L_TOK / 8, 256>>>(t, ln3_w, ln3_b, hn);
    gemm_bf16_kernel<<<gFF1, 256, GEMM_SMEM>>>(hn, cwff1, bff1, nullptr, nullptr, nullptr,
                                    nullptr, nullptr, 0.f, 0, gg,
                                    L_TOK, 2 * FFI, C_DIM, 0);
    gemm_bf16_kernel<<<gFF2, 256, GEMM_SMEM>>>(gg, cwff2, bff2, t, t, tb,
                                    nullptr, nullptr, 0.f, 0, nullptr,
                                    L_TOK, C_DIM, FFI, 0);

    // ---- proj_out (+ x residual), channel-major store ----
    gemm_bf16_kernel<<<g320, 256, GEMM_SMEM>>>(tb, cwout, b_out, x, out, nullptr,
                                    nullptr, nullptr, 0.f, 0, nullptr,
                                    L_TOK, C_DIM, C_DIM, 1);
}

// round 10
// speedup vs baseline: 5.0805x; 1.1072x over previous
#include <cuda_runtime.h>
#include <cuda_bf16.h>
#include <mma.h>
#include <math.h>
#include <cstdint>

using namespace nvcuda;

// ---------------------------------------------------------------------------
// SpatialTransformer — round 9: DUAL-templated GEMM (regs/smem cut for the
// common path -> higher occupancy), no zero_pads (zero-init globals),
// 2-phase GroupNorm stats, coalesced transOut epilogue.
// ---------------------------------------------------------------------------

#define L_TOK   4096
#define C_DIM   320
#define HEADS   8
#define DH      40
#define DHP     48
#define CTX_DIM 768
#define LCTX    77
#define LCTXP   128
#define FFI     1280
#define NGROUPS 32
#define CH_PER_G 10

typedef __nv_bfloat16 bf16;

// fp32 scratch
__device__ float g_t [L_TOK * C_DIM];
__device__ float g_part[NGROUPS * 8 * 2];
__device__ float g_mean[NGROUPS];
__device__ float g_rstd[NGROUPS];
// bf16 activations (zero-initialized at module load; pad lanes never written)
__device__ bf16 b_xn[L_TOK * C_DIM];
__device__ bf16 b_hn[L_TOK * C_DIM];
__device__ bf16 b_q [L_TOK * C_DIM];
__device__ bf16 b_a [L_TOK * C_DIM];
__device__ bf16 b_gg[L_TOK * FFI];
__device__ bf16 b_t [L_TOK * C_DIM];
__device__ bf16 b_qh[HEADS * L_TOK * DHP];
__device__ bf16 b_kh[HEADS * L_TOK * DHP];
__device__ bf16 b_vh[HEADS * L_TOK * DHP];
__device__ bf16 b_k2h[HEADS * LCTXP * DHP];
__device__ bf16 b_v2h[HEADS * LCTXP * DHP];
__device__ bf16 b_ctx[LCTX * CTX_DIM];
// bf16 weights
__device__ bf16 b_w_in[C_DIM * C_DIM];
__device__ bf16 b_wq1[C_DIM * C_DIM];
__device__ bf16 b_wkv1[C_DIM * 2 * C_DIM];
__device__ bf16 b_wo1[C_DIM * C_DIM];
__device__ bf16 b_wq2[C_DIM * C_DIM];
__device__ bf16 b_wkv2[CTX_DIM * 2 * C_DIM];
__device__ bf16 b_wo2[C_DIM * C_DIM];
__device__ bf16 b_wff1[C_DIM * 2 * FFI];
__device__ bf16 b_wff2[FFI * C_DIM];
__device__ bf16 b_wout[C_DIM * C_DIM];

// ---------------- helpers ----------------
__device__ __forceinline__ unsigned int smem_u32(const void* p)
{ return (unsigned int)__cvta_generic_to_shared(p); }

__device__ __forceinline__ void cp16(unsigned int dst, const void* src, int sz)
{ asm volatile("cp.async.cg.shared.global [%0], [%1], 16, %2;\n"
               :: "r"(dst), "l"(src), "r"(sz)); }

__device__ __forceinline__ void cp_commit()
{ asm volatile("cp.async.commit_group;\n"); }

template<int N> __device__ __forceinline__ void cp_wait()
{ asm volatile("cp.async.wait_group %0;\n" :: "n"(N)); }

__device__ __forceinline__ float ex2(float x)
{ float r; asm("ex2.approx.f32 %0, %1;" : "=f"(r) : "f"(x)); return r; }

__device__ __forceinline__ void mma16816(float* c,
    unsigned a0, unsigned a1, unsigned a2, unsigned a3,
    unsigned b0, unsigned b1)
{
    asm volatile(
        "mma.sync.aligned.m16n8k16.row.col.f32.bf16.bf16.f32 "
        "{%0,%1,%2,%3}, {%4,%5,%6,%7}, {%8,%9}, {%0,%1,%2,%3};"
        : "+f"(c[0]), "+f"(c[1]), "+f"(c[2]), "+f"(c[3])
        : "r"(a0), "r"(a1), "r"(a2), "r"(a3), "r"(b0), "r"(b1));
}

// ---------------- prep: fp32 -> bf16 (9 jobs, one launch) ----------------
struct CvtJobs {
    const float4* s[9];
    __nv_bfloat162* d[9];
    int n[9];
};

__global__ void cvt_all_kernel(CvtJobs J)
{
    int i0 = blockIdx.x * blockDim.x + threadIdx.x;
    int st = gridDim.x * blockDim.x;
    #pragma unroll
    for (int q = 0; q < 9; q++) {
        const float4* s = J.s[q];
        __nv_bfloat162* d = J.d[q];
        int n = J.n[q];
        for (int j = i0; j < n; j += st) {
            float4 v = s[j];
            d[2*j]   = __floats2bfloat162_rn(v.x, v.y);
            d[2*j+1] = __floats2bfloat162_rn(v.z, v.w);
        }
    }
}

__global__ void merge_kv2_kernel(const float4* wk1, const float4* wv1,
                                 __nv_bfloat162* d1,
                                 const float4* wk2, const float4* wv2,
                                 __nv_bfloat162* d2)
{
    int i0 = blockIdx.x * blockDim.x + threadIdx.x;
    int st = gridDim.x * blockDim.x;
    const int C4 = C_DIM / 4;
    {
        int n4 = C_DIM * C4;
        for (int j = i0; j < n4; j += st) {
            int k = j / C4, c4 = j % C4;
            float4 a = wk1[j];
            float4 b = wv1[j];
            __nv_bfloat162* row = d1 + k * C_DIM;
            row[c4*2]   = __floats2bfloat162_rn(a.x, a.y);
            row[c4*2+1] = __floats2bfloat162_rn(a.z, a.w);
            row[C_DIM/2 + c4*2]   = __floats2bfloat162_rn(b.x, b.y);
            row[C_DIM/2 + c4*2+1] = __floats2bfloat162_rn(b.z, b.w);
        }
    }
    {
        int n4 = CTX_DIM * C4;
        for (int j = i0; j < n4; j += st) {
            int k = j / C4, c4 = j % C4;
            float4 a = wk2[j];
            float4 b = wv2[j];
            __nv_bfloat162* row = d2 + k * C_DIM;
            row[c4*2]   = __floats2bfloat162_rn(a.x, a.y);
            row[c4*2+1] = __floats2bfloat162_rn(a.z, a.w);
            row[C_DIM/2 + c4*2]   = __floats2bfloat162_rn(b.x, b.y);
            row[C_DIM/2 + c4*2+1] = __floats2bfloat162_rn(b.z, b.w);
        }
    }
}

// ---------------- GroupNorm: 2-phase stats ----------------
__global__ __launch_bounds__(256) void gn_part_kernel(const float* __restrict__ x)
{
    int b = blockIdx.x;            // 0..255
    int g = b >> 3, seg = b & 7;
    int tid = threadIdx.x;
    const int SEG4 = CH_PER_G * L_TOK / 4 / 8;   // 1280
    const float4* base = (const float4*)(x + (size_t)g * CH_PER_G * L_TOK)
                         + seg * SEG4;
    float s = 0.f, ss = 0.f;
    for (int i = tid; i < SEG4; i += 256) {
        float4 v = base[i];
        s  += v.x + v.y + v.z + v.w;
        ss += v.x*v.x + v.y*v.y + v.z*v.z + v.w*v.w;
    }
    __shared__ float rs[256], rss[256];
    rs[tid] = s; rss[tid] = ss;
    __syncthreads();
    for (int o = 128; o > 0; o >>= 1) {
        if (tid < o) { rs[tid] += rs[tid + o]; rss[tid] += rss[tid + o]; }
        __syncthreads();
    }
    if (tid == 0) {
        g_part[b * 2]     = rs[0];
        g_part[b * 2 + 1] = rss[0];
    }
}

__global__ void gn_final_kernel()
{
    int g = threadIdx.x;
    if (g >= NGROUPS) return;
    float s = 0.f, ss = 0.f;
    #pragma unroll
    for (int k = 0; k < 8; k++) {
        s  += g_part[(g * 8 + k) * 2];
        ss += g_part[(g * 8 + k) * 2 + 1];
    }
    const float NEL = (float)(CH_PER_G * L_TOK);
    float m = s / NEL;
    float var = ss / NEL - m * m;
    g_mean[g] = m;
    g_rstd[g] = rsqrtf(var + 1e-6f);
}

__global__ void gn_apply_kernel(const float* __restrict__ x,
                                const float* __restrict__ gw,
                                const float* __restrict__ gb,
                                bf16* __restrict__ out)
{
    __shared__ float tile[32][65];
    int hw0 = blockIdx.x * 64;
    int c0  = blockIdx.y * 32;
    #pragma unroll
    for (int p = 0; p < 8; p++) {
        int i = threadIdx.x + p * 256;
        int c = i >> 6, hw = i & 63;
        int gc = c0 + c;
        int g = gc / CH_PER_G;
        float v = (x[(size_t)gc * L_TOK + hw0 + hw] - g_mean[g]) * g_rstd[g]
                  * gw[gc] + gb[gc];
        tile[c][hw] = v;
    }
    __syncthreads();
    #pragma unroll
    for (int p = 0; p < 8; p++) {
        int i = threadIdx.x + p * 256;
        int hw = i >> 5, c = i & 31;
        out[(size_t)(hw0 + hw) * C_DIM + c0 + c] = __float2bfloat16(tile[c][hw]);
    }
}

// ---------------- LayerNorm (warp/token, vectorized) ----------------
__global__ __launch_bounds__(256) void ln_kernel(
    const float* __restrict__ in, const float* __restrict__ w,
    const float* __restrict__ b, bf16* __restrict__ out)
{
    int token = blockIdx.x * 8 + (threadIdx.x >> 5);
    int lane = threadIdx.x & 31;
    const float4* row4 = (const float4*)(in + (size_t)token * C_DIM);
    float s = 0.f, ss = 0.f;
    #pragma unroll
    for (int j = 0; j < 3; j++) {
        int idx = lane + j * 32;
        if (idx < 80) {
            float4 v = row4[idx];
            s  += v.x + v.y + v.z + v.w;
            ss += v.x*v.x + v.y*v.y + v.z*v.z + v.w*v.w;
        }
    }
    #pragma unroll
    for (int o = 16; o > 0; o >>= 1) {
        s  += __shfl_xor_sync(0xffffffffu, s, o);
        ss += __shfl_xor_sync(0xffffffffu, ss, o);
    }
    float m = s / (float)C_DIM;
    float var = ss / (float)C_DIM - m * m;
    float r = rsqrtf(var + 1e-5f);

    const float2* row2 = (const float2*)(in + (size_t)token * C_DIM);
    const float2* w2 = (const float2*)w;
    const float2* b2 = (const float2*)b;
    __nv_bfloat162* o2 = (__nv_bfloat162*)(out + (size_t)token * C_DIM);
    #pragma unroll
    for (int j = 0; j < 5; j++) {
        int idx = lane + j * 32;
        float2 v = row2[idx];
        float2 ww = w2[idx];
        float2 bb = b2[idx];
        o2[idx] = __floats2bfloat162_rn((v.x - m) * r * ww.x + bb.x,
                                        (v.y - m) * r * ww.y + bb.y);
    }
}

// ---------------- bf16 TC GEMM, 128x64, 256 thr, 3-stage, DUAL templated ---
template<bool DUAL> struct GemmBufT {
    bf16 As[3][128][40];
    bf16 Bs[3][DUAL ? 2 : 1][32][72];
};
#define GEMM_SMEM_S ((int)sizeof(GemmBufT<false>))
#define GEMM_SMEM_D ((int)sizeof(GemmBufT<true>))

template<bool DUAL>
__global__ __launch_bounds__(256) void gemm_bf16_kernel(
    const bf16* __restrict__ A, const bf16* __restrict__ B,
    const float* __restrict__ bias, const float* __restrict__ res,
    float* __restrict__ Cf, bf16* __restrict__ Cbf,
    bf16* __restrict__ attnK, bf16* __restrict__ attnV,
    float attnScale, int Lpad,
    bf16* __restrict__ ggOut,
    int M, int N, int K, int transOut)
{
    extern __shared__ char smraw[];
    GemmBufT<DUAL>* in = (GemmBufT<DUAL>*)smraw;
    float (*Cs)[68] = (float(*)[68])smraw;

    int bm = blockIdx.y * 128;
    int bn = blockIdx.x * 64;
    int tid = threadIdx.x;
    int w = tid >> 5, wm = w >> 1, wn = w & 1;

    wmma::fragment<wmma::accumulator, 16, 16, 16, float> acc[2][2];
    wmma::fragment<wmma::accumulator, 16, 16, 16, float> acc2[DUAL ? 2 : 1][2];
    #pragma unroll
    for (int i = 0; i < 2; i++)
        #pragma unroll
        for (int j = 0; j < 2; j++) wmma::fill_fragment(acc[i][j], 0.f);
    if (DUAL) {
        #pragma unroll
        for (int i = 0; i < 2; i++)
            #pragma unroll
            for (int j = 0; j < 2; j++) wmma::fill_fragment(acc2[i][j], 0.f);
    }

    auto issue = [&](int s, int k0) {
        #pragma unroll
        for (int p = 0; p < 2; p++) {
            int c = tid + p * 256;
            int row = c >> 2, ch = c & 3;
            int gm = bm + row;
            const bf16* src = A + (size_t)(gm < M ? gm : 0) * K + k0 + ch * 8;
            cp16(smem_u32(&in->As[s][row][ch * 8]), src, (gm < M) ? 16 : 0);
        }
        {
            int row = tid >> 3, ch = tid & 7;
            const bf16* src = B + (size_t)(k0 + row) * N + bn + ch * 8;
            cp16(smem_u32(&in->Bs[s][0][row][ch * 8]), src, 16);
            if (DUAL)
                cp16(smem_u32(&in->Bs[s][DUAL ? 1 : 0][row][ch * 8]), src + FFI, 16);
        }
        cp_commit();
    };

    int nk = K / 32;
    issue(0, 0);
    issue(1, 32);
    for (int ki = 0; ki < nk; ki++) {
        int s = ki - (ki / 3) * 3;
        if (ki == nk - 1) cp_wait<0>(); else cp_wait<1>();
        __syncthreads();
        #pragma unroll
        for (int ks = 0; ks < 2; ks++) {
            wmma::fragment<wmma::matrix_a, 16, 16, 16, bf16, wmma::row_major> af[2];
            wmma::fragment<wmma::matrix_b, 16, 16, 16, bf16, wmma::row_major> bfr[2];
            wmma::load_matrix_sync(af[0], &in->As[s][wm*32     ][ks*16], 40);
            wmma::load_matrix_sync(af[1], &in->As[s][wm*32 + 16][ks*16], 40);
            wmma::load_matrix_sync(bfr[0], &in->Bs[s][0][ks*16][wn*32     ], 72);
            wmma::load_matrix_sync(bfr[1], &in->Bs[s][0][ks*16][wn*32 + 16], 72);
            #pragma unroll
            for (int i = 0; i < 2; i++)
                #pragma unroll
                for (int j = 0; j < 2; j++)
                    wmma::mma_sync(acc[i][j], af[i], bfr[j], acc[i][j]);
            if (DUAL) {
                wmma::load_matrix_sync(bfr[0], &in->Bs[s][DUAL?1:0][ks*16][wn*32     ], 72);
                wmma::load_matrix_sync(bfr[1], &in->Bs[s][DUAL?1:0][ks*16][wn*32 + 16], 72);
                #pragma unroll
                for (int i = 0; i < 2; i++)
                    #pragma unroll
                    for (int j = 0; j < 2; j++)
                        wmma::mma_sync(acc2[i][j], af[i], bfr[j], acc2[i][j]);
            }
        }
        if (ki + 2 < nk) {
            int s2 = (ki + 2) - ((ki + 2) / 3) * 3;
            issue(s2, (ki + 2) * 32);
        }
    }
    __syncthreads();

    // ---- epilogue ----
    #pragma unroll
    for (int i = 0; i < 2; i++)
        #pragma unroll
        for (int j = 0; j < 2; j++)
            wmma::store_matrix_sync(&Cs[wm*32 + i*16][wn*32 + j*16],
                                    acc[i][j], 68, wmma::mem_row_major);
    __syncthreads();

    if (DUAL) {
        float rA[32];
        #pragma unroll
        for (int p = 0; p < 32; p++) {
            int i = tid + p * 256;
            rA[p] = Cs[i >> 6][i & 63];
        }
        __syncthreads();
        #pragma unroll
        for (int i = 0; i < 2; i++)
            #pragma unroll
            for (int j = 0; j < 2; j++)
                wmma::store_matrix_sync(&Cs[wm*32 + i*16][wn*32 + j*16],
                                        acc2[i][j], 68, wmma::mem_row_major);
        __syncthreads();
        #pragma unroll
        for (int p = 0; p < 32; p++) {
            int i = tid + p * 256;
            int m = i >> 6, n = i & 63;
            int gm = bm + m, gn = bn + n;
            float av = rA[p] + bias[gn];
            float gv = Cs[m][n] + bias[gn + FFI];
            float ge = 0.5f * gv * (1.f + erff(gv * 0.70710678118654752f));
            ggOut[(size_t)gm * FFI + gn] = __float2bfloat16(av * ge);
        }
        return;
    }

    if (transOut) {
        // coalesced: consecutive threads -> consecutive m (output col-major)
        #pragma unroll
        for (int p = 0; p < 32; p++) {
            int i = tid + p * 256;
            int m = i & 127, n = i >> 7;
            int gm = bm + m, gn = bn + n;
            float v = Cs[m][n];
            if (bias) v += bias[gn];
            size_t idx = (size_t)gn * M + gm;
            if (res) v += res[idx];
            Cf[idx] = v;
        }
        return;
    }

    #pragma unroll
    for (int p = 0; p < 32; p++) {
        int i = tid + p * 256;
        int m = i >> 6, n = i & 63;
        int gm = bm + m, gn = bn + n;
        if (gm >= M) continue;
        float v = Cs[m][n];
        if (bias) v += bias[gn];
        if (Cf) {
            size_t idx = (size_t)gm * N + gn;
            if (res) v += res[idx];
            Cf[idx] = v;
        }
        if (Cbf) Cbf[(size_t)gm * N + gn] = __float2bfloat16(v);
        if (attnK) {
            bf16* dst;
            int cc;
            if (gn < C_DIM) { dst = attnK; cc = gn; }
            else            { dst = attnV; cc = gn - C_DIM; }
            if (attnV == nullptr) { dst = attnK; cc = gn; }
            int h = cc & 7, j = cc >> 3;
            dst[((size_t)h * Lpad + gm) * DHP + j] =
                __float2bfloat16(v * attnScale);
        }
    }
}

// ---------------- FA2 attention, 3-stage K/V pipeline ----------------
#define ATTN_SMEM (3 * 3072 * 2 * 2 + 128 * 48 * 2)   // 49152

__global__ __launch_bounds__(256) void attn_reg_kernel(
    const bf16* __restrict__ qh, const bf16* __restrict__ kh,
    const bf16* __restrict__ vh, bf16* __restrict__ Obf,
    int Lk, int Lpad)
{
    extern __shared__ char smraw[];
    bf16* sK = (bf16*)smraw;
    bf16* sV = sK + 3 * 3072;
    bf16* sQ = sV + 3 * 3072;

    int h = blockIdx.y;
    int qbase = blockIdx.x * 128;
    int tid = threadIdx.x, w = tid >> 5, lane = tid & 31;
    int r0 = lane >> 2, cq = (lane & 3) * 2;

    auto load_kv = [&](int s, int k0) {
        const bf16* kp = kh + ((size_t)h * Lpad + k0) * DHP;
        const bf16* vp = vh + ((size_t)h * Lpad + k0) * DHP;
        #pragma unroll
        for (int p = 0; p < 3; p++) {
            int c = tid + p * 256;
            if (c < 384) cp16(smem_u32(&sK[s * 3072 + c * 8]), kp + c * 8, 16);
            else         cp16(smem_u32(&sV[s * 3072 + (c - 384) * 8]),
                              vp + (c - 384) * 8, 16);
        }
        cp_commit();
    };

    int ntiles = (Lk + 63) / 64;
    load_kv(0, 0);
    if (ntiles > 1) load_kv(1, 64);

    {
        const uint4* src = (const uint4*)(qh + ((size_t)h * L_TOK + qbase) * DHP);
        uint4* dst = (uint4*)sQ;
        #pragma unroll
        for (int p = 0; p < 3; p++) dst[tid + p * 256] = src[tid + p * 256];
    }
    __syncthreads();

    unsigned qa[3][4];
    {
        const bf16* qrow = sQ + (w * 16 + r0) * 48;
        #pragma unroll
        for (int kd = 0; kd < 3; kd++) {
            qa[kd][0] = *(const unsigned*)(qrow + kd * 16 + cq);
            qa[kd][1] = *(const unsigned*)(qrow + 8 * 48 + kd * 16 + cq);
            qa[kd][2] = *(const unsigned*)(qrow + kd * 16 + 8 + cq);
            qa[kd][3] = *(const unsigned*)(qrow + 8 * 48 + kd * 16 + 8 + cq);
        }
    }

    float O[6][4] = {};
    float m0 = -1e30f, m1 = -1e30f, l0 = 0.f, l1 = 0.f;

    for (int ti = 0; ti < ntiles; ti++) {
        int s = ti - (ti / 3) * 3;
        int k0 = ti * 64;
        if (ti == ntiles - 1) cp_wait<0>(); else cp_wait<1>();
        __syncthreads();

        float S[8][4];
        #pragma unroll
        for (int j = 0; j < 8; j++)
            S[j][0] = S[j][1] = S[j][2] = S[j][3] = 0.f;
        #pragma unroll
        for (int kd = 0; kd < 3; kd++)
            #pragma unroll
            for (int j = 0; j < 8; j++) {
                const bf16* kb = &sK[s * 3072 + (j * 8 + r0) * 48 + kd * 16];
                unsigned b0 = *(const unsigned*)(kb + cq);
                unsigned b1 = *(const unsigned*)(kb + 8 + cq);
                mma16816(S[j], qa[kd][0], qa[kd][1], qa[kd][2], qa[kd][3], b0, b1);
            }

        if (k0 + 64 > Lk) {
            #pragma unroll
            for (int j = 0; j < 8; j++) {
                int col = k0 + j * 8 + cq;
                if (col >= Lk)     { S[j][0] = -1e30f; S[j][2] = -1e30f; }
                if (col + 1 >= Lk) { S[j][1] = -1e30f; S[j][3] = -1e30f; }
            }
        }

        float mx0 = -1e30f, mx1 = -1e30f;
        #pragma unroll
        for (int j = 0; j < 8; j++) {
            mx0 = fmaxf(mx0, fmaxf(S[j][0], S[j][1]));
            mx1 = fmaxf(mx1, fmaxf(S[j][2], S[j][3]));
        }
        mx0 = fmaxf(mx0, __shfl_xor_sync(0xffffffffu, mx0, 1));
        mx0 = fmaxf(mx0, __shfl_xor_sync(0xffffffffu, mx0, 2));
        mx1 = fmaxf(mx1, __shfl_xor_sync(0xffffffffu, mx1, 1));
        mx1 = fmaxf(mx1, __shfl_xor_sync(0xffffffffu, mx1, 2));

        float mn0 = fmaxf(m0, mx0), mn1 = fmaxf(m1, mx1);
        float corr0 = ex2(m0 - mn0), corr1 = ex2(m1 - mn1);
        m0 = mn0; m1 = mn1;

        unsigned P[8][2];
        float sum0 = 0.f, sum1 = 0.f;
        #pragma unroll
        for (int j = 0; j < 8; j++) {
            float p0 = ex2(S[j][0] - mn0), p1 = ex2(S[j][1] - mn0);
            float p2 = ex2(S[j][2] - mn1), p3 = ex2(S[j][3] - mn1);
            sum0 += p0 + p1; sum1 += p2 + p3;
            __nv_bfloat162 u0 = __floats2bfloat162_rn(p0, p1);
            __nv_bfloat162 u1 = __floats2bfloat162_rn(p2, p3);
            P[j][0] = *(unsigned*)&u0;
            P[j][1] = *(unsigned*)&u1;
        }
        sum0 += __shfl_xor_sync(0xffffffffu, sum0, 1);
        sum0 += __shfl_xor_sync(0xffffffffu, sum0, 2);
        sum1 += __shfl_xor_sync(0xffffffffu, sum1, 1);
        sum1 += __shfl_xor_sync(0xffffffffu, sum1, 2);
        l0 = l0 * corr0 + sum0;
        l1 = l1 * corr1 + sum1;

        #pragma unroll
        for (int jd = 0; jd < 6; jd++) {
            O[jd][0] *= corr0; O[jd][1] *= corr0;
            O[jd][2] *= corr1; O[jd][3] *= corr1;
        }

        #pragma unroll
        for (int t = 0; t < 4; t++) {
            #pragma unroll
            for (int p2 = 0; p2 < 3; p2++) {
                int g = lane >> 3;
                unsigned addr = smem_u32(
                    &sV[s * 3072 + (t * 16 + (g & 1) * 8 + (lane & 7)) * 48
                        + p2 * 16 + (g >> 1) * 8]);
                unsigned v0, v1, v2, v3;
                asm volatile(
                    "ldmatrix.sync.aligned.m8n8.x4.trans.shared.b16 "
                    "{%0,%1,%2,%3}, [%4];"
                    : "=r"(v0), "=r"(v1), "=r"(v2), "=r"(v3) : "r"(addr));
                mma16816(O[2*p2],   P[2*t][0], P[2*t][1],
                                    P[2*t+1][0], P[2*t+1][1], v0, v1);
                mma16816(O[2*p2+1], P[2*t][0], P[2*t][1],
                                    P[2*t+1][0], P[2*t+1][1], v2, v3);
            }
        }

        if (ti + 2 < ntiles) {
            int s2 = (ti + 2) - ((ti + 2) / 3) * 3;
            load_kv(s2, (ti + 2) * 64);
        }
    }

    float il0 = 1.f / l0, il1 = 1.f / l1;
    int tok = qbase + w * 16 + r0;
    #pragma unroll
    for (int jd = 0; jd < 5; jd++) {
        int col = jd * 8 + cq;
        __nv_bfloat162 o0 = __floats2bfloat162_rn(O[jd][0] * il0, O[jd][1] * il0);
        __nv_bfloat162 o1 = __floats2bfloat162_rn(O[jd][2] * il1, O[jd][3] * il1);
        *(__nv_bfloat162*)(Obf + (size_t)tok * C_DIM + h * DH + col) = o0;
        *(__nv_bfloat162*)(Obf + (size_t)(tok + 8) * C_DIM + h * DH + col) = o1;
    }
}

// ---------------------------------------------------------------------------
extern "C" void kernel_launch(void* const* d_in, const int* in_sizes, int n_in,
                              void* d_out, int out_size)
{
    const float* x       = (const float*)d_in[0];
    const float* context = (const float*)d_in[1];
    const float* gn_w    = (const float*)d_in[2];
    const float* gn_b    = (const float*)d_in[3];
    const float* w_in    = (const float*)d_in[4];
    const float* b_in    = (const float*)d_in[5];
    const float* ln1_w   = (const float*)d_in[6];
    const float* ln1_b   = (const float*)d_in[7];
    const float* wq1     = (const float*)d_in[8];
    const float* wk1     = (const float*)d_in[9];
    const float* wv1     = (const float*)d_in[10];
    const float* wo1     = (const float*)d_in[11];
    const float* bo1     = (const float*)d_in[12];
    const float* ln2_w   = (const float*)d_in[13];
    const float* ln2_b   = (const float*)d_in[14];
    const float* wq2     = (const float*)d_in[15];
    const float* wk2     = (const float*)d_in[16];
    const float* wv2     = (const float*)d_in[17];
    const float* wo2     = (const float*)d_in[18];
    const float* bo2     = (const float*)d_in[19];
    const float* ln3_w   = (const float*)d_in[20];
    const float* ln3_b   = (const float*)d_in[21];
    const float* wff1    = (const float*)d_in[22];
    const float* bff1    = (const float*)d_in[23];
    const float* wff2    = (const float*)d_in[24];
    const float* bff2    = (const float*)d_in[25];
    const float* w_out   = (const float*)d_in[26];
    const float* b_out   = (const float*)d_in[27];
    float* out = (float*)d_out;

    static float *t = nullptr;
    static bf16 *xn, *hn, *q, *a, *gg, *tb, *qh, *kh, *vh, *k2h, *v2h, *ctx;
    static bf16 *cw_in, *cwq1, *cwkv1, *cwo1, *cwq2, *cwkv2, *cwo2,
                *cwff1, *cwff2, *cwout;
    static bool init_done = false;
    if (!init_done) {
        cudaGetSymbolAddress((void**)&t,  g_t);
        cudaGetSymbolAddress((void**)&xn, b_xn);
        cudaGetSymbolAddress((void**)&hn, b_hn);
        cudaGetSymbolAddress((void**)&q,  b_q);
        cudaGetSymbolAddress((void**)&a,  b_a);
        cudaGetSymbolAddress((void**)&gg, b_gg);
        cudaGetSymbolAddress((void**)&tb, b_t);
        cudaGetSymbolAddress((void**)&qh, b_qh);
        cudaGetSymbolAddress((void**)&kh, b_kh);
        cudaGetSymbolAddress((void**)&vh, b_vh);
        cudaGetSymbolAddress((void**)&k2h, b_k2h);
        cudaGetSymbolAddress((void**)&v2h, b_v2h);
        cudaGetSymbolAddress((void**)&ctx, b_ctx);
        cudaGetSymbolAddress((void**)&cw_in, b_w_in);
        cudaGetSymbolAddress((void**)&cwq1, b_wq1);
        cudaGetSymbolAddress((void**)&cwkv1, b_wkv1);
        cudaGetSymbolAddress((void**)&cwo1, b_wo1);
        cudaGetSymbolAddress((void**)&cwq2, b_wq2);
        cudaGetSymbolAddress((void**)&cwkv2, b_wkv2);
        cudaGetSymbolAddress((void**)&cwo2, b_wo2);
        cudaGetSymbolAddress((void**)&cwff1, b_wff1);
        cudaGetSymbolAddress((void**)&cwff2, b_wff2);
        cudaGetSymbolAddress((void**)&cwout, b_wout);
        cudaFuncSetAttribute(gemm_bf16_kernel<false>,
                             cudaFuncAttributeMaxDynamicSharedMemorySize,
                             GEMM_SMEM_S);
        cudaFuncSetAttribute(gemm_bf16_kernel<true>,
                             cudaFuncAttributeMaxDynamicSharedMemorySize,
                             GEMM_SMEM_D);
        cudaFuncSetAttribute(attn_reg_kernel,
                             cudaFuncAttributeMaxDynamicSharedMemorySize,
                             ATTN_SMEM);
        init_done = true;
    }

    const float scaleQ = 0.15811388300841898f * 1.4426950408889634f;
    const int CC4 = C_DIM * C_DIM / 4;

    CvtJobs J;
    J.s[0] = (const float4*)context; J.d[0] = (__nv_bfloat162*)ctx;   J.n[0] = LCTX * CTX_DIM / 4;
    J.s[1] = (const float4*)w_in;    J.d[1] = (__nv_bfloat162*)cw_in; J.n[1] = CC4;
    J.s[2] = (const float4*)wq1;     J.d[2] = (__nv_bfloat162*)cwq1;  J.n[2] = CC4;
    J.s[3] = (const float4*)wo1;     J.d[3] = (__nv_bfloat162*)cwo1;  J.n[3] = CC4;
    J.s[4] = (const float4*)wq2;     J.d[4] = (__nv_bfloat162*)cwq2;  J.n[4] = CC4;
    J.s[5] = (const float4*)wo2;     J.d[5] = (__nv_bfloat162*)cwo2;  J.n[5] = CC4;
    J.s[6] = (const float4*)wff1;    J.d[6] = (__nv_bfloat162*)cwff1; J.n[6] = C_DIM * 2 * FFI / 4;
    J.s[7] = (const float4*)wff2;    J.d[7] = (__nv_bfloat162*)cwff2; J.n[7] = FFI * C_DIM / 4;
    J.s[8] = (const float4*)w_out;   J.d[8] = (__nv_bfloat162*)cwout; J.n[8] = CC4;
    cvt_all_kernel<<<512, 256>>>(J);
    merge_kv2_kernel<<<256, 256>>>((const float4*)wk1, (const float4*)wv1,
                                   (__nv_bfloat162*)cwkv1,
                                   (const float4*)wk2, (const float4*)wv2,
                                   (__nv_bfloat162*)cwkv2);

    dim3 g320(C_DIM / 64, L_TOK / 128);
    dim3 gKV(2 * C_DIM / 64, L_TOK / 128);
    dim3 gKVc(2 * C_DIM / 64, 1);
    dim3 gFF1(FFI / 64, L_TOK / 128);
    dim3 gFF2(C_DIM / 64, L_TOK / 128);
    dim3 attnGrid(L_TOK / 128, HEADS);

    gn_part_kernel<<<256, 256>>>(x);
    gn_final_kernel<<<1, 32>>>();
    gn_apply_kernel<<<dim3(L_TOK / 64, C_DIM / 32), 256>>>(x, gn_w, gn_b, xn);
    gemm_bf16_kernel<false><<<g320, 256, GEMM_SMEM_S>>>(xn, cw_in, b_in, nullptr, t, nullptr,
                                    nullptr, nullptr, 0.f, 0, nullptr,
                                    L_TOK, C_DIM, C_DIM, 0);

    // ---- self-attention ----
    ln_kernel<<<L_TOK / 8, 256>>>(t, ln1_w, ln1_b, hn);
    gemm_bf16_kernel<false><<<g320, 256, GEMM_SMEM_S>>>(hn, cwq1, nullptr, nullptr, nullptr, q,
                                    qh, nullptr, scaleQ, L_TOK, nullptr,
                                    L_TOK, C_DIM, C_DIM, 0);
    gemm_bf16_kernel<false><<<gKV, 256, GEMM_SMEM_S>>>(q, cwkv1, nullptr, nullptr, nullptr, nullptr,
                                   kh, vh, 1.f, L_TOK, nullptr,
                                   L_TOK, 2 * C_DIM, C_DIM, 0);
    attn_reg_kernel<<<attnGrid, 256, ATTN_SMEM>>>(qh, kh, vh, a, L_TOK, L_TOK);
    gemm_bf16_kernel<false><<<g320, 256, GEMM_SMEM_S>>>(a, cwo1, bo1, t, t, nullptr,
                                    nullptr, nullptr, 0.f, 0, nullptr,
                                    L_TOK, C_DIM, C_DIM, 0);

    // ---- cross-attention ----
    ln_kernel<<<L_TOK / 8, 256>>>(t, ln2_w, ln2_b, hn);
    gemm_bf16_kernel<false><<<g320, 256, GEMM_SMEM_S>>>(hn, cwq2, nullptr, nullptr, nullptr, nullptr,
                                    qh, nullptr, scaleQ, L_TOK, nullptr,
                                    L_TOK, C_DIM, C_DIM, 0);
    gemm_bf16_kernel<false><<<gKVc, 256, GEMM_SMEM_S>>>(ctx, cwkv2, nullptr, nullptr, nullptr, nullptr,
                                    k2h, v2h, 1.f, LCTXP, nullptr,
                                    LCTX, 2 * C_DIM, CTX_DIM, 0);
    attn_reg_kernel<<<attnGrid, 256, ATTN_SMEM>>>(qh, k2h, v2h, a, LCTX, LCTXP);
    gemm_bf16_kernel<false><<<g320, 256, GEMM_SMEM_S>>>(a, cwo2, bo2, t, t, nullptr,
                                    nullptr, nullptr, 0.f, 0, nullptr,
                                    L_TOK, C_DIM, C_DIM, 0);

    // ---- feed-forward: fused FF1 + GEGLU, then FF2 ----
    ln_kernel<<<L_TOK / 8, 256>>>(t, ln3_w, ln3_b, hn);
    gemm_bf16_kernel<true><<<gFF1, 256, GEMM_SMEM_D>>>(hn, cwff1, bff1, nullptr, nullptr, nullptr,
                                    nullptr, nullptr, 0.f, 0, gg,
                                    L_TOK, 2 * FFI, C_DIM, 0);
    gemm_bf16_kernel<false><<<gFF2, 256, GEMM_SMEM_S>>>(gg, cwff2, bff2, t, t, tb,
                                    nullptr, nullptr, 0.f, 0, nullptr,
                                    L_TOK, C_DIM, FFI, 0);

    // ---- proj_out (+ x residual), channel-major store ----
    gemm_bf16_kernel<false><<<g320, 256, GEMM_SMEM_S>>>(tb, cwout, b_out, x, out, nullptr,
                                    nullptr, nullptr, 0.f, 0, nullptr,
                                    L_TOK, C_DIM, C_DIM, 1);
}

// round 11
// speedup vs baseline: 5.3489x; 1.0528x over previous
#include <cuda_runtime.h>
#include <cuda_bf16.h>
#include <mma.h>
#include <math.h>
#include <cstdint>

using namespace nvcuda;

// ---------------------------------------------------------------------------
// SpatialTransformer — round 10: fused prep (cvt+merge+gn-partials in one
// launch), gn_final folded into gn_apply, exact dh=40 attention mma
// (m16n8k8 tail + 8-col PV tile). GEMMs unchanged from round 9.
// ---------------------------------------------------------------------------

#define L_TOK   4096
#define C_DIM   320
#define HEADS   8
#define DH      40
#define DHP     48
#define CTX_DIM 768
#define LCTX    77
#define LCTXP   128
#define FFI     1280
#define NGROUPS 32
#define CH_PER_G 10

typedef __nv_bfloat16 bf16;

// fp32 scratch
__device__ float g_t [L_TOK * C_DIM];
__device__ float g_part[NGROUPS * 8 * 2];
// bf16 activations (zero-initialized; pad lanes never written)
__device__ bf16 b_xn[L_TOK * C_DIM];
__device__ bf16 b_hn[L_TOK * C_DIM];
__device__ bf16 b_q [L_TOK * C_DIM];
__device__ bf16 b_a [L_TOK * C_DIM];
__device__ bf16 b_gg[L_TOK * FFI];
__device__ bf16 b_t [L_TOK * C_DIM];
__device__ bf16 b_qh[HEADS * L_TOK * DHP];
__device__ bf16 b_kh[HEADS * L_TOK * DHP];
__device__ bf16 b_vh[HEADS * L_TOK * DHP];
__device__ bf16 b_k2h[HEADS * LCTXP * DHP];
__device__ bf16 b_v2h[HEADS * LCTXP * DHP];
__device__ bf16 b_ctx[LCTX * CTX_DIM];
// bf16 weights
__device__ bf16 b_w_in[C_DIM * C_DIM];
__device__ bf16 b_wq1[C_DIM * C_DIM];
__device__ bf16 b_wkv1[C_DIM * 2 * C_DIM];
__device__ bf16 b_wo1[C_DIM * C_DIM];
__device__ bf16 b_wq2[C_DIM * C_DIM];
__device__ bf16 b_wkv2[CTX_DIM * 2 * C_DIM];
__device__ bf16 b_wo2[C_DIM * C_DIM];
__device__ bf16 b_wff1[C_DIM * 2 * FFI];
__device__ bf16 b_wff2[FFI * C_DIM];
__device__ bf16 b_wout[C_DIM * C_DIM];

// ---------------- helpers ----------------
__device__ __forceinline__ unsigned int smem_u32(const void* p)
{ return (unsigned int)__cvta_generic_to_shared(p); }

__device__ __forceinline__ void cp16(unsigned int dst, const void* src, int sz)
{ asm volatile("cp.async.cg.shared.global [%0], [%1], 16, %2;\n"
               :: "r"(dst), "l"(src), "r"(sz)); }

__device__ __forceinline__ void cp_commit()
{ asm volatile("cp.async.commit_group;\n"); }

template<int N> __device__ __forceinline__ void cp_wait()
{ asm volatile("cp.async.wait_group %0;\n" :: "n"(N)); }

__device__ __forceinline__ float ex2(float x)
{ float r; asm("ex2.approx.f32 %0, %1;" : "=f"(r) : "f"(x)); return r; }

__device__ __forceinline__ void mma16816(float* c,
    unsigned a0, unsigned a1, unsigned a2, unsigned a3,
    unsigned b0, unsigned b1)
{
    asm volatile(
        "mma.sync.aligned.m16n8k16.row.col.f32.bf16.bf16.f32 "
        "{%0,%1,%2,%3}, {%4,%5,%6,%7}, {%8,%9}, {%0,%1,%2,%3};"
        : "+f"(c[0]), "+f"(c[1]), "+f"(c[2]), "+f"(c[3])
        : "r"(a0), "r"(a1), "r"(a2), "r"(a3), "r"(b0), "r"(b1));
}

__device__ __forceinline__ void mma16808(float* c,
    unsigned a0, unsigned a1, unsigned b0)
{
    asm volatile(
        "mma.sync.aligned.m16n8k8.row.col.f32.bf16.bf16.f32 "
        "{%0,%1,%2,%3}, {%4,%5}, {%6}, {%0,%1,%2,%3};"
        : "+f"(c[0]), "+f"(c[1]), "+f"(c[2]), "+f"(c[3])
        : "r"(a0), "r"(a1), "r"(b0));
}

// ---------------- fused prep: cvt (9 jobs) + merge kv (2) + gn partials ----
struct CvtJobs {
    const float4* s[9];
    __nv_bfloat162* d[9];
    int n[9];
};

__global__ __launch_bounds__(256) void prep_kernel(
    CvtJobs J,
    const float4* wk1, const float4* wv1, __nv_bfloat162* dkv1,
    const float4* wk2, const float4* wv2, __nv_bfloat162* dkv2,
    const float* __restrict__ x)
{
    int i0 = blockIdx.x * blockDim.x + threadIdx.x;
    int st = gridDim.x * blockDim.x;
    #pragma unroll
    for (int q = 0; q < 9; q++) {
        const float4* s = J.s[q];
        __nv_bfloat162* d = J.d[q];
        int n = J.n[q];
        for (int j = i0; j < n; j += st) {
            float4 v = s[j];
            d[2*j]   = __floats2bfloat162_rn(v.x, v.y);
            d[2*j+1] = __floats2bfloat162_rn(v.z, v.w);
        }
    }
    const int C4 = C_DIM / 4;
    {
        int n4 = C_DIM * C4;
        for (int j = i0; j < n4; j += st) {
            int k = j / C4, c4 = j % C4;
            float4 a = wk1[j];
            float4 b = wv1[j];
            __nv_bfloat162* row = dkv1 + k * C_DIM;
            row[c4*2]   = __floats2bfloat162_rn(a.x, a.y);
            row[c4*2+1] = __floats2bfloat162_rn(a.z, a.w);
            row[C_DIM/2 + c4*2]   = __floats2bfloat162_rn(b.x, b.y);
            row[C_DIM/2 + c4*2+1] = __floats2bfloat162_rn(b.z, b.w);
        }
    }
    {
        int n4 = CTX_DIM * C4;
        for (int j = i0; j < n4; j += st) {
            int k = j / C4, c4 = j % C4;
            float4 a = wk2[j];
            float4 b = wv2[j];
            __nv_bfloat162* row = dkv2 + k * C_DIM;
            row[c4*2]   = __floats2bfloat162_rn(a.x, a.y);
            row[c4*2+1] = __floats2bfloat162_rn(a.z, a.w);
            row[C_DIM/2 + c4*2]   = __floats2bfloat162_rn(b.x, b.y);
            row[C_DIM/2 + c4*2+1] = __floats2bfloat162_rn(b.z, b.w);
        }
    }
    // gn partial sums: blocks 0..255
    if (blockIdx.x < 256) {
        int b = blockIdx.x;
        int g = b >> 3, seg = b & 7;
        int tid = threadIdx.x;
        const int SEG4 = CH_PER_G * L_TOK / 4 / 8;   // 1280
        const float4* base = (const float4*)(x + (size_t)g * CH_PER_G * L_TOK)
                             + seg * SEG4;
        float s = 0.f, ss = 0.f;
        for (int i = tid; i < SEG4; i += 256) {
            float4 v = base[i];
            s  += v.x + v.y + v.z + v.w;
            ss += v.x*v.x + v.y*v.y + v.z*v.z + v.w*v.w;
        }
        __shared__ float rs[256], rss[256];
        rs[tid] = s; rss[tid] = ss;
        __syncthreads();
        for (int o = 128; o > 0; o >>= 1) {
            if (tid < o) { rs[tid] += rs[tid + o]; rss[tid] += rss[tid + o]; }
            __syncthreads();
        }
        if (tid == 0) {
            g_part[b * 2]     = rs[0];
            g_part[b * 2 + 1] = rss[0];
        }
    }
}

// ---------------- GroupNorm apply (finalizes stats in-block) ----------------
__global__ void gn_apply_kernel(const float* __restrict__ x,
                                const float* __restrict__ gw,
                                const float* __restrict__ gb,
                                bf16* __restrict__ out)
{
    __shared__ float tile[32][65];
    __shared__ float smean[NGROUPS], srstd[NGROUPS];
    if (threadIdx.x < NGROUPS) {
        int g = threadIdx.x;
        float s = 0.f, ss = 0.f;
        #pragma unroll
        for (int k = 0; k < 8; k++) {
            s  += g_part[(g * 8 + k) * 2];
            ss += g_part[(g * 8 + k) * 2 + 1];
        }
        const float NEL = (float)(CH_PER_G * L_TOK);
        float m = s / NEL;
        float var = ss / NEL - m * m;
        smean[g] = m;
        srstd[g] = rsqrtf(var + 1e-6f);
    }
    __syncthreads();

    int hw0 = blockIdx.x * 64;
    int c0  = blockIdx.y * 32;
    #pragma unroll
    for (int p = 0; p < 8; p++) {
        int i = threadIdx.x + p * 256;
        int c = i >> 6, hw = i & 63;
        int gc = c0 + c;
        int g = gc / CH_PER_G;
        float v = (x[(size_t)gc * L_TOK + hw0 + hw] - smean[g]) * srstd[g]
                  * gw[gc] + gb[gc];
        tile[c][hw] = v;
    }
    __syncthreads();
    #pragma unroll
    for (int p = 0; p < 8; p++) {
        int i = threadIdx.x + p * 256;
        int hw = i >> 5, c = i & 31;
        out[(size_t)(hw0 + hw) * C_DIM + c0 + c] = __float2bfloat16(tile[c][hw]);
    }
}

// ---------------- LayerNorm (warp/token, vectorized) ----------------
__global__ __launch_bounds__(256) void ln_kernel(
    const float* __restrict__ in, const float* __restrict__ w,
    const float* __restrict__ b, bf16* __restrict__ out)
{
    int token = blockIdx.x * 8 + (threadIdx.x >> 5);
    int lane = threadIdx.x & 31;
    const float4* row4 = (const float4*)(in + (size_t)token * C_DIM);
    float s = 0.f, ss = 0.f;
    #pragma unroll
    for (int j = 0; j < 3; j++) {
        int idx = lane + j * 32;
        if (idx < 80) {
            float4 v = row4[idx];
            s  += v.x + v.y + v.z + v.w;
            ss += v.x*v.x + v.y*v.y + v.z*v.z + v.w*v.w;
        }
    }
    #pragma unroll
    for (int o = 16; o > 0; o >>= 1) {
        s  += __shfl_xor_sync(0xffffffffu, s, o);
        ss += __shfl_xor_sync(0xffffffffu, ss, o);
    }
    float m = s / (float)C_DIM;
    float var = ss / (float)C_DIM - m * m;
    float r = rsqrtf(var + 1e-5f);

    const float2* row2 = (const float2*)(in + (size_t)token * C_DIM);
    const float2* w2 = (const float2*)w;
    const float2* b2 = (const float2*)b;
    __nv_bfloat162* o2 = (__nv_bfloat162*)(out + (size_t)token * C_DIM);
    #pragma unroll
    for (int j = 0; j < 5; j++) {
        int idx = lane + j * 32;
        float2 v = row2[idx];
        float2 ww = w2[idx];
        float2 bb = b2[idx];
        o2[idx] = __floats2bfloat162_rn((v.x - m) * r * ww.x + bb.x,
                                        (v.y - m) * r * ww.y + bb.y);
    }
}

// ---------------- bf16 TC GEMM, 128x64, 256 thr, 3-stage, DUAL templated ---
template<bool DUAL> struct GemmBufT {
    bf16 As[3][128][40];
    bf16 Bs[3][DUAL ? 2 : 1][32][72];
};
#define GEMM_SMEM_S ((int)sizeof(GemmBufT<false>))
#define GEMM_SMEM_D ((int)sizeof(GemmBufT<true>))

template<bool DUAL>
__global__ __launch_bounds__(256) void gemm_bf16_kernel(
    const bf16* __restrict__ A, const bf16* __restrict__ B,
    const float* __restrict__ bias, const float* __restrict__ res,
    float* __restrict__ Cf, bf16* __restrict__ Cbf,
    bf16* __restrict__ attnK, bf16* __restrict__ attnV,
    float attnScale, int Lpad,
    bf16* __restrict__ ggOut,
    int M, int N, int K, int transOut)
{
    extern __shared__ char smraw[];
    GemmBufT<DUAL>* in = (GemmBufT<DUAL>*)smraw;
    float (*Cs)[68] = (float(*)[68])smraw;

    int bm = blockIdx.y * 128;
    int bn = blockIdx.x * 64;
    int tid = threadIdx.x;
    int w = tid >> 5, wm = w >> 1, wn = w & 1;

    wmma::fragment<wmma::accumulator, 16, 16, 16, float> acc[2][2];
    wmma::fragment<wmma::accumulator, 16, 16, 16, float> acc2[DUAL ? 2 : 1][2];
    #pragma unroll
    for (int i = 0; i < 2; i++)
        #pragma unroll
        for (int j = 0; j < 2; j++) wmma::fill_fragment(acc[i][j], 0.f);
    if (DUAL) {
        #pragma unroll
        for (int i = 0; i < 2; i++)
            #pragma unroll
            for (int j = 0; j < 2; j++) wmma::fill_fragment(acc2[i][j], 0.f);
    }

    auto issue = [&](int s, int k0) {
        #pragma unroll
        for (int p = 0; p < 2; p++) {
            int c = tid + p * 256;
            int row = c >> 2, ch = c & 3;
            int gm = bm + row;
            const bf16* src = A + (size_t)(gm < M ? gm : 0) * K + k0 + ch * 8;
            cp16(smem_u32(&in->As[s][row][ch * 8]), src, (gm < M) ? 16 : 0);
        }
        {
            int row = tid >> 3, ch = tid & 7;
            const bf16* src = B + (size_t)(k0 + row) * N + bn + ch * 8;
            cp16(smem_u32(&in->Bs[s][0][row][ch * 8]), src, 16);
            if (DUAL)
                cp16(smem_u32(&in->Bs[s][DUAL ? 1 : 0][row][ch * 8]), src + FFI, 16);
        }
        cp_commit();
    };

    int nk = K / 32;
    issue(0, 0);
    issue(1, 32);
    for (int ki = 0; ki < nk; ki++) {
        int s = ki - (ki / 3) * 3;
        if (ki == nk - 1) cp_wait<0>(); else cp_wait<1>();
        __syncthreads();
        #pragma unroll
        for (int ks = 0; ks < 2; ks++) {
            wmma::fragment<wmma::matrix_a, 16, 16, 16, bf16, wmma::row_major> af[2];
            wmma::fragment<wmma::matrix_b, 16, 16, 16, bf16, wmma::row_major> bfr[2];
            wmma::load_matrix_sync(af[0], &in->As[s][wm*32     ][ks*16], 40);
            wmma::load_matrix_sync(af[1], &in->As[s][wm*32 + 16][ks*16], 40);
            wmma::load_matrix_sync(bfr[0], &in->Bs[s][0][ks*16][wn*32     ], 72);
            wmma::load_matrix_sync(bfr[1], &in->Bs[s][0][ks*16][wn*32 + 16], 72);
            #pragma unroll
            for (int i = 0; i < 2; i++)
                #pragma unroll
                for (int j = 0; j < 2; j++)
                    wmma::mma_sync(acc[i][j], af[i], bfr[j], acc[i][j]);
            if (DUAL) {
                wmma::load_matrix_sync(bfr[0], &in->Bs[s][DUAL?1:0][ks*16][wn*32     ], 72);
                wmma::load_matrix_sync(bfr[1], &in->Bs[s][DUAL?1:0][ks*16][wn*32 + 16], 72);
                #pragma unroll
                for (int i = 0; i < 2; i++)
                    #pragma unroll
                    for (int j = 0; j < 2; j++)
                        wmma::mma_sync(acc2[i][j], af[i], bfr[j], acc2[i][j]);
            }
        }
        if (ki + 2 < nk) {
            int s2 = (ki + 2) - ((ki + 2) / 3) * 3;
            issue(s2, (ki + 2) * 32);
        }
    }
    __syncthreads();

    // ---- epilogue ----
    #pragma unroll
    for (int i = 0; i < 2; i++)
        #pragma unroll
        for (int j = 0; j < 2; j++)
            wmma::store_matrix_sync(&Cs[wm*32 + i*16][wn*32 + j*16],
                                    acc[i][j], 68, wmma::mem_row_major);
    __syncthreads();

    if (DUAL) {
        float rA[32];
        #pragma unroll
        for (int p = 0; p < 32; p++) {
            int i = tid + p * 256;
            rA[p] = Cs[i >> 6][i & 63];
        }
        __syncthreads();
        #pragma unroll
        for (int i = 0; i < 2; i++)
            #pragma unroll
            for (int j = 0; j < 2; j++)
                wmma::store_matrix_sync(&Cs[wm*32 + i*16][wn*32 + j*16],
                                        acc2[i][j], 68, wmma::mem_row_major);
        __syncthreads();
        #pragma unroll
        for (int p = 0; p < 32; p++) {
            int i = tid + p * 256;
            int m = i >> 6, n = i & 63;
            int gm = bm + m, gn = bn + n;
            float av = rA[p] + bias[gn];
            float gv = Cs[m][n] + bias[gn + FFI];
            float ge = 0.5f * gv * (1.f + erff(gv * 0.70710678118654752f));
            ggOut[(size_t)gm * FFI + gn] = __float2bfloat16(av * ge);
        }
        return;
    }

    if (transOut) {
        #pragma unroll
        for (int p = 0; p < 32; p++) {
            int i = tid + p * 256;
            int m = i & 127, n = i >> 7;
            int gm = bm + m, gn = bn + n;
            float v = Cs[m][n];
            if (bias) v += bias[gn];
            size_t idx = (size_t)gn * M + gm;
            if (res) v += res[idx];
            Cf[idx] = v;
        }
        return;
    }

    #pragma unroll
    for (int p = 0; p < 32; p++) {
        int i = tid + p * 256;
        int m = i >> 6, n = i & 63;
        int gm = bm + m, gn = bn + n;
        if (gm >= M) continue;
        float v = Cs[m][n];
        if (bias) v += bias[gn];
        if (Cf) {
            size_t idx = (size_t)gm * N + gn;
            if (res) v += res[idx];
            Cf[idx] = v;
        }
        if (Cbf) Cbf[(size_t)gm * N + gn] = __float2bfloat16(v);
        if (attnK) {
            bf16* dst;
            int cc;
            if (gn < C_DIM) { dst = attnK; cc = gn; }
            else            { dst = attnV; cc = gn - C_DIM; }
            if (attnV == nullptr) { dst = attnK; cc = gn; }
            int h = cc & 7, j = cc >> 3;
            dst[((size_t)h * Lpad + gm) * DHP + j] =
                __float2bfloat16(v * attnScale);
        }
    }
}

// ---------------- FA2 attention, exact dh=40, 3-stage K/V pipeline ---------
#define ATTN_SMEM (3 * 3072 * 2 * 2 + 128 * 48 * 2)   // 49152

__global__ __launch_bounds__(256) void attn_reg_kernel(
    const bf16* __restrict__ qh, const bf16* __restrict__ kh,
    const bf16* __restrict__ vh, bf16* __restrict__ Obf,
    int Lk, int Lpad)
{
    extern __shared__ char smraw[];
    bf16* sK = (bf16*)smraw;
    bf16* sV = sK + 3 * 3072;
    bf16* sQ = sV + 3 * 3072;

    int h = blockIdx.y;
    int qbase = blockIdx.x * 128;
    int tid = threadIdx.x, w = tid >> 5, lane = tid & 31;
    int r0 = lane >> 2, cq = (lane & 3) * 2;

    auto load_kv = [&](int s, int k0) {
        const bf16* kp = kh + ((size_t)h * Lpad + k0) * DHP;
        const bf16* vp = vh + ((size_t)h * Lpad + k0) * DHP;
        #pragma unroll
        for (int p = 0; p < 3; p++) {
            int c = tid + p * 256;
            if (c < 384) cp16(smem_u32(&sK[s * 3072 + c * 8]), kp + c * 8, 16);
            else         cp16(smem_u32(&sV[s * 3072 + (c - 384) * 8]),
                              vp + (c - 384) * 8, 16);
        }
        cp_commit();
    };

    int ntiles = (Lk + 63) / 64;
    load_kv(0, 0);
    if (ntiles > 1) load_kv(1, 64);

    {
        const uint4* src = (const uint4*)(qh + ((size_t)h * L_TOK + qbase) * DHP);
        uint4* dst = (uint4*)sQ;
        #pragma unroll
        for (int p = 0; p < 3; p++) dst[tid + p * 256] = src[tid + p * 256];
    }
    __syncthreads();

    // Q fragments: 2 full k16 steps (dh 0..31) + 1 k8 step (dh 32..39)
    unsigned qa[2][4], qa8[2];
    {
        const bf16* qrow = sQ + (w * 16 + r0) * 48;
        #pragma unroll
        for (int kd = 0; kd < 2; kd++) {
            qa[kd][0] = *(const unsigned*)(qrow + kd * 16 + cq);
            qa[kd][1] = *(const unsigned*)(qrow + 8 * 48 + kd * 16 + cq);
            qa[kd][2] = *(const unsigned*)(qrow + kd * 16 + 8 + cq);
            qa[kd][3] = *(const unsigned*)(qrow + 8 * 48 + kd * 16 + 8 + cq);
        }
        qa8[0] = *(const unsigned*)(qrow + 32 + cq);
        qa8[1] = *(const unsigned*)(qrow + 8 * 48 + 32 + cq);
    }

    float O[5][4] = {};
    float m0 = -1e30f, m1 = -1e30f, l0 = 0.f, l1 = 0.f;

    for (int ti = 0; ti < ntiles; ti++) {
        int s = ti - (ti / 3) * 3;
        int k0 = ti * 64;
        if (ti == ntiles - 1) cp_wait<0>(); else cp_wait<1>();
        __syncthreads();

        float S[8][4];
        #pragma unroll
        for (int j = 0; j < 8; j++)
            S[j][0] = S[j][1] = S[j][2] = S[j][3] = 0.f;
        #pragma unroll
        for (int j = 0; j < 8; j++) {
            const bf16* kb = &sK[s * 3072 + (j * 8 + r0) * 48];
            #pragma unroll
            for (int kd = 0; kd < 2; kd++) {
                unsigned b0 = *(const unsigned*)(kb + kd * 16 + cq);
                unsigned b1 = *(const unsigned*)(kb + kd * 16 + 8 + cq);
                mma16816(S[j], qa[kd][0], qa[kd][1], qa[kd][2], qa[kd][3], b0, b1);
            }
            unsigned b8 = *(const unsigned*)(kb + 32 + cq);
            mma16808(S[j], qa8[0], qa8[1], b8);
        }

        if (k0 + 64 > Lk) {
            #pragma unroll
            for (int j = 0; j < 8; j++) {
                int col = k0 + j * 8 + cq;
                if (col >= Lk)     { S[j][0] = -1e30f; S[j][2] = -1e30f; }
                if (col + 1 >= Lk) { S[j][1] = -1e30f; S[j][3] = -1e30f; }
            }
        }

        float mx0 = -1e30f, mx1 = -1e30f;
        #pragma unroll
        for (int j = 0; j < 8; j++) {
            mx0 = fmaxf(mx0, fmaxf(S[j][0], S[j][1]));
            mx1 = fmaxf(mx1, fmaxf(S[j][2], S[j][3]));
        }
        mx0 = fmaxf(mx0, __shfl_xor_sync(0xffffffffu, mx0, 1));
        mx0 = fmaxf(mx0, __shfl_xor_sync(0xffffffffu, mx0, 2));
        mx1 = fmaxf(mx1, __shfl_xor_sync(0xffffffffu, mx1, 1));
        mx1 = fmaxf(mx1, __shfl_xor_sync(0xffffffffu, mx1, 2));

        float mn0 = fmaxf(m0, mx0), mn1 = fmaxf(m1, mx1);
        float corr0 = ex2(m0 - mn0), corr1 = ex2(m1 - mn1);
        m0 = mn0; m1 = mn1;

        unsigned P[8][2];
        float sum0 = 0.f, sum1 = 0.f;
        #pragma unroll
        for (int j = 0; j < 8; j++) {
            float p0 = ex2(S[j][0] - mn0), p1 = ex2(S[j][1] - mn0);
            float p2 = ex2(S[j][2] - mn1), p3 = ex2(S[j][3] - mn1);
            sum0 += p0 + p1; sum1 += p2 + p3;
            __nv_bfloat162 u0 = __floats2bfloat162_rn(p0, p1);
            __nv_bfloat162 u1 = __floats2bfloat162_rn(p2, p3);
            P[j][0] = *(unsigned*)&u0;
            P[j][1] = *(unsigned*)&u1;
        }
        sum0 += __shfl_xor_sync(0xffffffffu, sum0, 1);
        sum0 += __shfl_xor_sync(0xffffffffu, sum0, 2);
        sum1 += __shfl_xor_sync(0xffffffffu, sum1, 1);
        sum1 += __shfl_xor_sync(0xffffffffu, sum1, 2);
        l0 = l0 * corr0 + sum0;
        l1 = l1 * corr1 + sum1;

        #pragma unroll
        for (int jd = 0; jd < 5; jd++) {
            O[jd][0] *= corr0; O[jd][1] *= corr0;
            O[jd][2] *= corr1; O[jd][3] *= corr1;
        }

        // O += P V : dh tiles {0-15, 16-31} via x4, {32-39} via x2
        #pragma unroll
        for (int t = 0; t < 4; t++) {
            int g = lane >> 3;
            #pragma unroll
            for (int p2 = 0; p2 < 2; p2++) {
                unsigned addr = smem_u32(
                    &sV[s * 3072 + (t * 16 + (g & 1) * 8 + (lane & 7)) * 48
                        + p2 * 16 + (g >> 1) * 8]);
                unsigned v0, v1, v2, v3;
                asm volatile(
                    "ldmatrix.sync.aligned.m8n8.x4.trans.shared.b16 "
                    "{%0,%1,%2,%3}, [%4];"
                    : "=r"(v0), "=r"(v1), "=r"(v2), "=r"(v3) : "r"(addr));
                mma16816(O[2*p2],   P[2*t][0], P[2*t][1],
                                    P[2*t+1][0], P[2*t+1][1], v0, v1);
                mma16816(O[2*p2+1], P[2*t][0], P[2*t][1],
                                    P[2*t+1][0], P[2*t+1][1], v2, v3);
            }
            {
                unsigned addr = smem_u32(
                    &sV[s * 3072 + (t * 16 + ((lane >> 3) & 1) * 8 + (lane & 7)) * 48
                        + 32]);
                unsigned v0, v1;
                asm volatile(
                    "ldmatrix.sync.aligned.m8n8.x2.trans.shared.b16 "
                    "{%0,%1}, [%2];"
                    : "=r"(v0), "=r"(v1) : "r"(addr));
                mma16816(O[4], P[2*t][0], P[2*t][1],
                               P[2*t+1][0], P[2*t+1][1], v0, v1);
            }
        }

        if (ti + 2 < ntiles) {
            int s2 = (ti + 2) - ((ti + 2) / 3) * 3;
            load_kv(s2, (ti + 2) * 64);
        }
    }

    float il0 = 1.f / l0, il1 = 1.f / l1;
    int tok = qbase + w * 16 + r0;
    #pragma unroll
    for (int jd = 0; jd < 5; jd++) {
        int col = jd * 8 + cq;
        __nv_bfloat162 o0 = __floats2bfloat162_rn(O[jd][0] * il0, O[jd][1] * il0);
        __nv_bfloat162 o1 = __floats2bfloat162_rn(O[jd][2] * il1, O[jd][3] * il1);
        *(__nv_bfloat162*)(Obf + (size_t)tok * C_DIM + h * DH + col) = o0;
        *(__nv_bfloat162*)(Obf + (size_t)(tok + 8) * C_DIM + h * DH + col) = o1;
    }
}

// ---------------------------------------------------------------------------
extern "C" void kernel_launch(void* const* d_in, const int* in_sizes, int n_in,
                              void* d_out, int out_size)
{
    const float* x       = (const float*)d_in[0];
    const float* context = (const float*)d_in[1];
    const float* gn_w    = (const float*)d_in[2];
    const float* gn_b    = (const float*)d_in[3];
    const float* w_in    = (const float*)d_in[4];
    const float* b_in    = (const float*)d_in[5];
    const float* ln1_w   = (const float*)d_in[6];
    const float* ln1_b   = (const float*)d_in[7];
    const float* wq1     = (const float*)d_in[8];
    const float* wk1     = (const float*)d_in[9];
    const float* wv1     = (const float*)d_in[10];
    const float* wo1     = (const float*)d_in[11];
    const float* bo1     = (const float*)d_in[12];
    const float* ln2_w   = (const float*)d_in[13];
    const float* ln2_b   = (const float*)d_in[14];
    const float* wq2     = (const float*)d_in[15];
    const float* wk2     = (const float*)d_in[16];
    const float* wv2     = (const float*)d_in[17];
    const float* wo2     = (const float*)d_in[18];
    const float* bo2     = (const float*)d_in[19];
    const float* ln3_w   = (const float*)d_in[20];
    const float* ln3_b   = (const float*)d_in[21];
    const float* wff1    = (const float*)d_in[22];
    const float* bff1    = (const float*)d_in[23];
    const float* wff2    = (const float*)d_in[24];
    const float* bff2    = (const float*)d_in[25];
    const float* w_out   = (const float*)d_in[26];
    const float* b_out   = (const float*)d_in[27];
    float* out = (float*)d_out;

    static float *t = nullptr;
    static bf16 *xn, *hn, *q, *a, *gg, *tb, *qh, *kh, *vh, *k2h, *v2h, *ctx;
    static bf16 *cw_in, *cwq1, *cwkv1, *cwo1, *cwq2, *cwkv2, *cwo2,
                *cwff1, *cwff2, *cwout;
    static bool init_done = false;
    if (!init_done) {
        cudaGetSymbolAddress((void**)&t,  g_t);
        cudaGetSymbolAddress((void**)&xn, b_xn);
        cudaGetSymbolAddress((void**)&hn, b_hn);
        cudaGetSymbolAddress((void**)&q,  b_q);
        cudaGetSymbolAddress((void**)&a,  b_a);
        cudaGetSymbolAddress((void**)&gg, b_gg);
        cudaGetSymbolAddress((void**)&tb, b_t);
        cudaGetSymbolAddress((void**)&qh, b_qh);
        cudaGetSymbolAddress((void**)&kh, b_kh);
        cudaGetSymbolAddress((void**)&vh, b_vh);
        cudaGetSymbolAddress((void**)&k2h, b_k2h);
        cudaGetSymbolAddress((void**)&v2h, b_v2h);
        cudaGetSymbolAddress((void**)&ctx, b_ctx);
        cudaGetSymbolAddress((void**)&cw_in, b_w_in);
        cudaGetSymbolAddress((void**)&cwq1, b_wq1);
        cudaGetSymbolAddress((void**)&cwkv1, b_wkv1);
        cudaGetSymbolAddress((void**)&cwo1, b_wo1);
        cudaGetSymbolAddress((void**)&cwq2, b_wq2);
        cudaGetSymbolAddress((void**)&cwkv2, b_wkv2);
        cudaGetSymbolAddress((void**)&cwo2, b_wo2);
        cudaGetSymbolAddress((void**)&cwff1, b_wff1);
        cudaGetSymbolAddress((void**)&cwff2, b_wff2);
        cudaGetSymbolAddress((void**)&cwout, b_wout);
        cudaFuncSetAttribute(gemm_bf16_kernel<false>,
                             cudaFuncAttributeMaxDynamicSharedMemorySize,
                             GEMM_SMEM_S);
        cudaFuncSetAttribute(gemm_bf16_kernel<true>,
                             cudaFuncAttributeMaxDynamicSharedMemorySize,
                             GEMM_SMEM_D);
        cudaFuncSetAttribute(attn_reg_kernel,
                             cudaFuncAttributeMaxDynamicSharedMemorySize,
                             ATTN_SMEM);
        init_done = true;
    }

    const float scaleQ = 0.15811388300841898f * 1.4426950408889634f;
    const int CC4 = C_DIM * C_DIM / 4;

    CvtJobs J;
    J.s[0] = (const float4*)context; J.d[0] = (__nv_bfloat162*)ctx;   J.n[0] = LCTX * CTX_DIM / 4;
    J.s[1] = (const float4*)w_in;    J.d[1] = (__nv_bfloat162*)cw_in; J.n[1] = CC4;
    J.s[2] = (const float4*)wq1;     J.d[2] = (__nv_bfloat162*)cwq1;  J.n[2] = CC4;
    J.s[3] = (const float4*)wo1;     J.d[3] = (__nv_bfloat162*)cwo1;  J.n[3] = CC4;
    J.s[4] = (const float4*)wq2;     J.d[4] = (__nv_bfloat162*)cwq2;  J.n[4] = CC4;
    J.s[5] = (const float4*)wo2;     J.d[5] = (__nv_bfloat162*)cwo2;  J.n[5] = CC4;
    J.s[6] = (const float4*)wff1;    J.d[6] = (__nv_bfloat162*)cwff1; J.n[6] = C_DIM * 2 * FFI / 4;
    J.s[7] = (const float4*)wff2;    J.d[7] = (__nv_bfloat162*)cwff2; J.n[7] = FFI * C_DIM / 4;
    J.s[8] = (const float4*)w_out;   J.d[8] = (__nv_bfloat162*)cwout; J.n[8] = CC4;
    prep_kernel<<<512, 256>>>(J,
        (const float4*)wk1, (const float4*)wv1, (__nv_bfloat162*)cwkv1,
        (const float4*)wk2, (const float4*)wv2, (__nv_bfloat162*)cwkv2,
        x);

    dim3 g320(C_DIM / 64, L_TOK / 128);
    dim3 gKV(2 * C_DIM / 64, L_TOK / 128);
    dim3 gKVc(2 * C_DIM / 64, 1);
    dim3 gFF1(FFI / 64, L_TOK / 128);
    dim3 gFF2(C_DIM / 64, L_TOK / 128);
    dim3 attnGrid(L_TOK / 128, HEADS);

    gn_apply_kernel<<<dim3(L_TOK / 64, C_DIM / 32), 256>>>(x, gn_w, gn_b, xn);
    gemm_bf16_kernel<false><<<g320, 256, GEMM_SMEM_S>>>(xn, cw_in, b_in, nullptr, t, nullptr,
                                    nullptr, nullptr, 0.f, 0, nullptr,
                                    L_TOK, C_DIM, C_DIM, 0);

    // ---- self-attention ----
    ln_kernel<<<L_TOK / 8, 256>>>(t, ln1_w, ln1_b, hn);
    gemm_bf16_kernel<false><<<g320, 256, GEMM_SMEM_S>>>(hn, cwq1, nullptr, nullptr, nullptr, q,
                                    qh, nullptr, scaleQ, L_TOK, nullptr,
                                    L_TOK, C_DIM, C_DIM, 0);
    gemm_bf16_kernel<false><<<gKV, 256, GEMM_SMEM_S>>>(q, cwkv1, nullptr, nullptr, nullptr, nullptr,
                                   kh, vh, 1.f, L_TOK, nullptr,
                                   L_TOK, 2 * C_DIM, C_DIM, 0);
    attn_reg_kernel<<<attnGrid, 256, ATTN_SMEM>>>(qh, kh, vh, a, L_TOK, L_TOK);
    gemm_bf16_kernel<false><<<g320, 256, GEMM_SMEM_S>>>(a, cwo1, bo1, t, t, nullptr,
                                    nullptr, nullptr, 0.f, 0, nullptr,
                                    L_TOK, C_DIM, C_DIM, 0);

    // ---- cross-attention ----
    ln_kernel<<<L_TOK / 8, 256>>>(t, ln2_w, ln2_b, hn);
    gemm_bf16_kernel<false><<<g320, 256, GEMM_SMEM_S>>>(hn, cwq2, nullptr, nullptr, nullptr, nullptr,
                                    qh, nullptr, scaleQ, L_TOK, nullptr,
                                    L_TOK, C_DIM, C_DIM, 0);
    gemm_bf16_kernel<false><<<gKVc, 256, GEMM_SMEM_S>>>(ctx, cwkv2, nullptr, nullptr, nullptr, nullptr,
                                    k2h, v2h, 1.f, LCTXP, nullptr,
                                    LCTX, 2 * C_DIM, CTX_DIM, 0);
    attn_reg_kernel<<<attnGrid, 256, ATTN_SMEM>>>(qh, k2h, v2h, a, LCTX, LCTXP);
    gemm_bf16_kernel<false><<<g320, 256, GEMM_SMEM_S>>>(a, cwo2, bo2, t, t, nullptr,
                                    nullptr, nullptr, 0.f, 0, nullptr,
                                    L_TOK, C_DIM, C_DIM, 0);

    // ---- feed-forward: fused FF1 + GEGLU, then FF2 ----
    ln_kernel<<<L_TOK / 8, 256>>>(t, ln3_w, ln3_b, hn);
    gemm_bf16_kernel<true><<<gFF1, 256, GEMM_SMEM_D>>>(hn, cwff1, bff1, nullptr, nullptr, nullptr,
                                    nullptr, nullptr, 0.f, 0, gg,
                                    L_TOK, 2 * FFI, C_DIM, 0);
    gemm_bf16_kernel<false><<<gFF2, 256, GEMM_SMEM_S>>>(gg, cwff2, bff2, t, t, tb,
                                    nullptr, nullptr, 0.f, 0, nullptr,
                                    L_TOK, C_DIM, FFI, 0);

    // ---- proj_out (+ x residual), channel-major store ----
    gemm_bf16_kernel<false><<<g320, 256, GEMM_SMEM_S>>>(tb, cwout, b_out, x, out, nullptr,
                                    nullptr, nullptr, 0.f, 0, nullptr,
                                    L_TOK, C_DIM, C_DIM, 1);
}